// round 1
// baseline (speedup 1.0000x reference)
#include <cuda_runtime.h>
#include <math.h>

#define B 64
#define S 197
#define D 768
#define H 12
#define HD 64
#define M_TOT (B * S)          // 12608
#define NUM_REL 732

// -------- device scratch (allowed: static __device__ globals) --------
__device__ float g_q[(size_t)B * H * S * HD];       // 38.7 MB
__device__ float g_k[(size_t)B * H * S * HD];
__device__ float g_v[(size_t)B * H * S * HD];
__device__ float g_p[(size_t)B * H * S * S];        // 119.2 MB scores/probs

// ============================================================================
// Kernel 1: fused QKV projection.
// C[m, n] = sum_k X[m,k] * W[n,k]  (GEMM_NT), N = 2304 (q|k|v concatenated).
// 128x128x16 tiles, 256 threads, 8x8 register tile per thread.
// Q gets +bq then *0.125 (folds the 1/sqrt(64) score scale); K no bias; V +bv.
// Outputs written in [B,H,S,HD] layout.
// ============================================================================
__global__ __launch_bounds__(256) void qkv_kernel(
    const float* __restrict__ X,
    const float* __restrict__ wq, const float* __restrict__ bq,
    const float* __restrict__ wk,
    const float* __restrict__ wv, const float* __restrict__ bv)
{
    __shared__ float As[16][128];
    __shared__ float Bs[16][128];

    const int tid = threadIdx.x;
    const int m0 = blockIdx.x * 128;
    const int n0g = blockIdx.y * 128;
    const int proj = n0g / 768;                 // 0=q, 1=k, 2=v
    const int n0 = n0g - proj * 768;

    const float* W    = (proj == 0) ? wq : ((proj == 1) ? wk : wv);
    const float* bias = (proj == 0) ? bq : ((proj == 2) ? bv : nullptr);
    float* dst        = (proj == 0) ? g_q : ((proj == 1) ? g_k : g_v);

    const int lrow = tid >> 2;                  // 0..63
    const int lcol = (tid & 3) * 4;             // 0,4,8,12

    const int ty = tid >> 4;                    // 0..15
    const int tx = tid & 15;                    // 0..15

    float acc[8][8];
#pragma unroll
    for (int i = 0; i < 8; ++i)
#pragma unroll
        for (int j = 0; j < 8; ++j) acc[i][j] = 0.f;

    for (int k0 = 0; k0 < 768; k0 += 16) {
#pragma unroll
        for (int half = 0; half < 2; ++half) {
            const int r = lrow + half * 64;     // 0..127
            // A tile
            const int m = m0 + r;
            float4 a = make_float4(0.f, 0.f, 0.f, 0.f);
            if (m < M_TOT)
                a = *(const float4*)(X + (size_t)m * 768 + k0 + lcol);
            As[lcol + 0][r] = a.x; As[lcol + 1][r] = a.y;
            As[lcol + 2][r] = a.z; As[lcol + 3][r] = a.w;
            // B tile (n always < 768)
            const int n = n0 + r;
            const float4 bb = *(const float4*)(W + (size_t)n * 768 + k0 + lcol);
            Bs[lcol + 0][r] = bb.x; Bs[lcol + 1][r] = bb.y;
            Bs[lcol + 2][r] = bb.z; Bs[lcol + 3][r] = bb.w;
        }
        __syncthreads();

#pragma unroll
        for (int kk = 0; kk < 16; ++kk) {
            float a[8], b[8];
            *(float4*)(a)     = *(const float4*)&As[kk][ty * 8];
            *(float4*)(a + 4) = *(const float4*)&As[kk][ty * 8 + 4];
            *(float4*)(b)     = *(const float4*)&Bs[kk][tx * 8];
            *(float4*)(b + 4) = *(const float4*)&Bs[kk][tx * 8 + 4];
#pragma unroll
            for (int i = 0; i < 8; ++i)
#pragma unroll
                for (int j = 0; j < 8; ++j)
                    acc[i][j] = fmaf(a[i], b[j], acc[i][j]);
        }
        __syncthreads();
    }

#pragma unroll
    for (int i = 0; i < 8; ++i) {
        const int m = m0 + ty * 8 + i;
        if (m >= M_TOT) continue;
        const int bb = m / S;
        const int ss = m - bb * S;
#pragma unroll
        for (int j = 0; j < 8; ++j) {
            const int n = n0 + tx * 8 + j;
            float c = acc[i][j];
            if (bias) c += bias[n];
            if (proj == 0) c *= 0.125f;
            const int hh = n >> 6;
            const int hd = n & 63;
            dst[(((size_t)bb * H + hh) * S + ss) * HD + hd] = c;
        }
    }
}

// ============================================================================
// Kernel 2: scores[bh, q, k] = Q[bh,q,:] . K[bh,k,:]  + bias_table[rel_index[q,k], h]
// (Q pre-scaled). 64x64 tile per block, 256 threads, 4x4 per thread, K-dim = 64.
// ============================================================================
__global__ __launch_bounds__(256) void scores_kernel(
    const float* __restrict__ bias_table, const int* __restrict__ rel_index)
{
    const int bh = blockIdx.z;                  // 0..767
    const int q0 = blockIdx.y * 64;
    const int k0 = blockIdx.x * 64;
    const int h = bh % H;

    const float* Q = g_q + (size_t)bh * S * HD;
    const float* K = g_k + (size_t)bh * S * HD;

    __shared__ float Qs[16][64];
    __shared__ float Ks[16][64];

    const int tid = threadIdx.x;
    const int lrow = tid >> 2;                  // 0..63
    const int lcol = (tid & 3) * 4;
    const int ty = tid >> 4;
    const int tx = tid & 15;

    float acc[4][4];
#pragma unroll
    for (int i = 0; i < 4; ++i)
#pragma unroll
        for (int j = 0; j < 4; ++j) acc[i][j] = 0.f;

    for (int d0 = 0; d0 < HD; d0 += 16) {
        const int qrow = q0 + lrow;
        float4 a = make_float4(0.f, 0.f, 0.f, 0.f);
        if (qrow < S) a = *(const float4*)(Q + (size_t)qrow * HD + d0 + lcol);
        Qs[lcol + 0][lrow] = a.x; Qs[lcol + 1][lrow] = a.y;
        Qs[lcol + 2][lrow] = a.z; Qs[lcol + 3][lrow] = a.w;

        const int krow = k0 + lrow;
        float4 bb = make_float4(0.f, 0.f, 0.f, 0.f);
        if (krow < S) bb = *(const float4*)(K + (size_t)krow * HD + d0 + lcol);
        Ks[lcol + 0][lrow] = bb.x; Ks[lcol + 1][lrow] = bb.y;
        Ks[lcol + 2][lrow] = bb.z; Ks[lcol + 3][lrow] = bb.w;
        __syncthreads();

#pragma unroll
        for (int kk = 0; kk < 16; ++kk) {
            float a4[4], b4[4];
            *(float4*)a4 = *(const float4*)&Qs[kk][ty * 4];
            *(float4*)b4 = *(const float4*)&Ks[kk][tx * 4];
#pragma unroll
            for (int i = 0; i < 4; ++i)
#pragma unroll
                for (int j = 0; j < 4; ++j)
                    acc[i][j] = fmaf(a4[i], b4[j], acc[i][j]);
        }
        __syncthreads();
    }

#pragma unroll
    for (int i = 0; i < 4; ++i) {
        const int qq = q0 + ty * 4 + i;
        if (qq >= S) continue;
#pragma unroll
        for (int j = 0; j < 4; ++j) {
            const int kk = k0 + tx * 4 + j;
            if (kk >= S) continue;
            const int ridx = rel_index[qq * S + kk];
            const float bias = bias_table[ridx * H + h];
            g_p[((size_t)bh * S + qq) * S + kk] = acc[i][j] + bias;
        }
    }
}

// ============================================================================
// Kernel 3: row softmax over g_p rows of length S=197. One block (128 thr) / row.
// ============================================================================
__global__ __launch_bounds__(128) void softmax_kernel()
{
    const size_t row = blockIdx.x;
    float* p = g_p + row * (size_t)S;
    const int t = threadIdx.x;

    const float v0 = (t < S) ? p[t] : -3.0e38f;
    const float v1 = (t + 128 < S) ? p[t + 128] : -3.0e38f;

    float m = fmaxf(v0, v1);
#pragma unroll
    for (int o = 16; o > 0; o >>= 1) m = fmaxf(m, __shfl_xor_sync(0xffffffffu, m, o));
    __shared__ float redm[4];
    if ((t & 31) == 0) redm[t >> 5] = m;
    __syncthreads();
    m = fmaxf(fmaxf(redm[0], redm[1]), fmaxf(redm[2], redm[3]));

    const float e0 = (t < S) ? __expf(v0 - m) : 0.f;
    const float e1 = (t + 128 < S) ? __expf(v1 - m) : 0.f;
    float sum = e0 + e1;
#pragma unroll
    for (int o = 16; o > 0; o >>= 1) sum += __shfl_xor_sync(0xffffffffu, sum, o);
    __shared__ float reds[4];
    if ((t & 31) == 0) reds[t >> 5] = sum;
    __syncthreads();
    sum = reds[0] + reds[1] + reds[2] + reds[3];
    const float inv = 1.f / sum;

    if (t < S) p[t] = e0 * inv;
    if (t + 128 < S) p[t + 128] = e1 * inv;
}

// ============================================================================
// Kernel 4: ctx[bh, q, :] = P[bh, q, :] @ V[bh, :, :]   (M=197, N=64, K=197)
// 64(q) x 64(d) tile per block, BK=32, 256 threads, 4x4 per thread.
// Writes output directly in [B, S, D] layout.
// ============================================================================
__global__ __launch_bounds__(256) void ctx_kernel(float* __restrict__ out)
{
    const int bh = blockIdx.y;                  // 0..767
    const int q0 = blockIdx.x * 64;             // 0,64,128,192
    const int bb = bh / H;
    const int h = bh % H;

    const float* P = g_p + (size_t)bh * S * S;
    const float* V = g_v + (size_t)bh * S * HD;

    __shared__ float Ps[32][64];                // [k][q]
    __shared__ float Vs[32][64];                // [k][d]

    const int tid = threadIdx.x;
    const int ty = tid >> 4;
    const int tx = tid & 15;

    float acc[4][4];
#pragma unroll
    for (int i = 0; i < 4; ++i)
#pragma unroll
        for (int j = 0; j < 4; ++j) acc[i][j] = 0.f;

    const int prow = tid >> 2;                  // 0..63  (q within tile)
    const int pcol = (tid & 3) * 8;             // 0,8,16,24

    for (int c0 = 0; c0 < S; c0 += 32) {        // 7 iterations (224 >= 197)
        // P tile [64 q][32 k] -> Ps[k][q], scalar guarded loads
        const int qq = q0 + prow;
#pragma unroll
        for (int e = 0; e < 8; ++e) {
            const int kk = c0 + pcol + e;
            float v = 0.f;
            if (qq < S && kk < S) v = P[(size_t)qq * S + kk];
            Ps[pcol + e][prow] = v;
        }
        // V tile [32 k][64 d] -> Vs[k][d], float4 loads
#pragma unroll
        for (int half = 0; half < 2; ++half) {
            const int f = tid + half * 256;
            const int vrow = f >> 4;            // 0..31
            const int vcol = (f & 15) * 4;
            const int kk = c0 + vrow;
            float4 vv = make_float4(0.f, 0.f, 0.f, 0.f);
            if (kk < S) vv = *(const float4*)(V + (size_t)kk * HD + vcol);
            *(float4*)&Vs[vrow][vcol] = vv;
        }
        __syncthreads();

#pragma unroll
        for (int kk = 0; kk < 32; ++kk) {
            float a4[4], b4[4];
            *(float4*)a4 = *(const float4*)&Ps[kk][ty * 4];
            *(float4*)b4 = *(const float4*)&Vs[kk][tx * 4];
#pragma unroll
            for (int i = 0; i < 4; ++i)
#pragma unroll
                for (int j = 0; j < 4; ++j)
                    acc[i][j] = fmaf(a4[i], b4[j], acc[i][j]);
        }
        __syncthreads();
    }

#pragma unroll
    for (int i = 0; i < 4; ++i) {
        const int qq = q0 + ty * 4 + i;
        if (qq >= S) continue;
        float4 r = make_float4(acc[i][0], acc[i][1], acc[i][2], acc[i][3]);
        *(float4*)(out + ((size_t)bb * S + qq) * D + h * HD + tx * 4) = r;
    }
}

// ============================================================================
// Launch
// Inputs (metadata order): hidden_states, wq, bq, wk, wv, bv, bias_table, rel_index
// ============================================================================
extern "C" void kernel_launch(void* const* d_in, const int* in_sizes, int n_in,
                              void* d_out, int out_size)
{
    const float* X  = (const float*)d_in[0];
    const float* wq = (const float*)d_in[1];
    const float* bq = (const float*)d_in[2];
    const float* wk = (const float*)d_in[3];
    const float* wv = (const float*)d_in[4];
    const float* bv = (const float*)d_in[5];
    const float* bt = (const float*)d_in[6];
    const int*   ri = (const int*)d_in[7];
    float* out = (float*)d_out;

    (void)in_sizes; (void)n_in; (void)out_size;

    qkv_kernel<<<dim3((M_TOT + 127) / 128, 2304 / 128), 256>>>(X, wq, bq, wk, wv, bv);
    scores_kernel<<<dim3(4, 4, B * H), 256>>>(bt, ri);
    softmax_kernel<<<B * H * S, 128>>>();
    ctx_kernel<<<dim3(4, B * H), 256>>>(out);
}

// round 3
// speedup vs baseline: 1.9394x; 1.9394x over previous
#include <cuda_runtime.h>
#include <math.h>
#include <cstdint>

#define B 64
#define S 197
#define D 768
#define H 12
#define HD 64
#define M_TOT (B * S)          // 12608
#define NUM_REL 732

// -------- device scratch --------
__device__ float g_q[(size_t)B * H * S * HD];
__device__ float g_k[(size_t)B * H * S * HD];
__device__ float g_v[(size_t)B * H * S * HD];
__device__ float g_p[(size_t)B * H * S * S];

__device__ __forceinline__ uint32_t f2tf32(float x) {
    uint32_t u;
    asm("cvt.rna.tf32.f32 %0, %1;" : "=r"(u) : "f"(x));
    return u;
}

__device__ __forceinline__ void mma_tf32(float* d, const uint32_t* a, const uint32_t* b) {
    asm volatile(
        "mma.sync.aligned.m16n8k8.row.col.f32.tf32.tf32.f32 "
        "{%0,%1,%2,%3}, {%4,%5,%6,%7}, {%8,%9}, {%0,%1,%2,%3};"
        : "+f"(d[0]), "+f"(d[1]), "+f"(d[2]), "+f"(d[3])
        : "r"(a[0]), "r"(a[1]), "r"(a[2]), "r"(a[3]), "r"(b[0]), "r"(b[1]));
}

// ============================================================================
// QKV projection with mma.sync TF32.
// C[m,n] = sum_k X[m,k] * W[n,k] (GEMM_NT), N = 2304 (q|k|v).
// CTA tile 128x128x32, 256 thr, 8 warps (2m x 4n), warp tile 64x32.
// Smem pitch 36 floats -> conflict-free fragment LDS.
// ============================================================================
#define BKQ 32
#define NCHUNK 24
#define APITCH 36
#define STG_FLOATS (128 * APITCH)               // 4608 per stage
#define SMEM_QKV_BYTES (4 * STG_FLOATS * 4)     // A0 A1 B0 B1 = 73728

__global__ __launch_bounds__(256, 1) void qkv_mma_kernel(
    const float* __restrict__ X,
    const float* __restrict__ wq, const float* __restrict__ bq,
    const float* __restrict__ wk,
    const float* __restrict__ wv, const float* __restrict__ bv)
{
    extern __shared__ float sm[];               // [A0 | A1 | B0 | B1]
    const int tid  = threadIdx.x;
    const int wid  = tid >> 5;
    const int lane = tid & 31;
    const int g    = lane >> 2;                 // 0..7
    const int t    = lane & 3;                  // 0..3
    const int wm   = wid & 1;                   // 0..1
    const int wn   = wid >> 1;                  // 0..3

    const int m0  = blockIdx.x * 128;
    const int n0g = blockIdx.y * 128;
    const int proj = n0g / 768;                 // 0=q 1=k 2=v
    const int n0   = n0g - proj * 768;

    const float* W    = (proj == 0) ? wq : ((proj == 1) ? wk : wv);
    const float* bias = (proj == 0) ? bq : ((proj == 2) ? bv : nullptr);
    float* dst        = (proj == 0) ? g_q : ((proj == 1) ? g_k : g_v);

    const int lrow = tid >> 3;                  // 0..31 (row base per i-pass)
    const int lcg  = tid & 7;                   // col group (4 floats)

    float4 ra[4], rb[4];

    // ---- prologue: chunk 0 ----
#pragma unroll
    for (int i = 0; i < 4; ++i) {
        const int row = lrow + i * 32;
        const int m = m0 + row;
        ra[i] = make_float4(0.f, 0.f, 0.f, 0.f);
        if (m < M_TOT) ra[i] = *(const float4*)(X + (size_t)m * 768 + lcg * 4);
        rb[i] = *(const float4*)(W + (size_t)(n0 + row) * 768 + lcg * 4);
    }
#pragma unroll
    for (int i = 0; i < 4; ++i) {
        const int row = lrow + i * 32;
        uint4 ua = make_uint4(f2tf32(ra[i].x), f2tf32(ra[i].y), f2tf32(ra[i].z), f2tf32(ra[i].w));
        uint4 ub = make_uint4(f2tf32(rb[i].x), f2tf32(rb[i].y), f2tf32(rb[i].z), f2tf32(rb[i].w));
        *(uint4*)(sm + row * APITCH + lcg * 4) = ua;
        *(uint4*)(sm + 2 * STG_FLOATS + row * APITCH + lcg * 4) = ub;
    }
    __syncthreads();

    float acc[4][4][4];
#pragma unroll
    for (int mt = 0; mt < 4; ++mt)
#pragma unroll
        for (int nt = 0; nt < 4; ++nt)
#pragma unroll
            for (int e = 0; e < 4; ++e) acc[mt][nt][e] = 0.f;

    // ---- main loop ----
    for (int c = 0; c < NCHUNK; ++c) {
        const int cur = c & 1;
        if (c + 1 < NCHUNK) {
            const int k0 = (c + 1) * BKQ;
#pragma unroll
            for (int i = 0; i < 4; ++i) {
                const int row = lrow + i * 32;
                const int m = m0 + row;
                ra[i] = make_float4(0.f, 0.f, 0.f, 0.f);
                if (m < M_TOT) ra[i] = *(const float4*)(X + (size_t)m * 768 + k0 + lcg * 4);
                rb[i] = *(const float4*)(W + (size_t)(n0 + row) * 768 + k0 + lcg * 4);
            }
        }

        const uint32_t* Au = (const uint32_t*)(sm + cur * STG_FLOATS);
        const uint32_t* Bu = (const uint32_t*)(sm + (2 + cur) * STG_FLOATS);
#pragma unroll
        for (int ks = 0; ks < 4; ++ks) {
            uint32_t af[4][4], bf[4][2];
#pragma unroll
            for (int mt = 0; mt < 4; ++mt) {
                const int r0 = wm * 64 + mt * 16 + g;
                af[mt][0] = Au[r0 * APITCH + ks * 8 + t];
                af[mt][1] = Au[(r0 + 8) * APITCH + ks * 8 + t];
                af[mt][2] = Au[r0 * APITCH + ks * 8 + t + 4];
                af[mt][3] = Au[(r0 + 8) * APITCH + ks * 8 + t + 4];
            }
#pragma unroll
            for (int nt = 0; nt < 4; ++nt) {
                const int c0 = wn * 32 + nt * 8 + g;
                bf[nt][0] = Bu[c0 * APITCH + ks * 8 + t];
                bf[nt][1] = Bu[c0 * APITCH + ks * 8 + t + 4];
            }
#pragma unroll
            for (int mt = 0; mt < 4; ++mt)
#pragma unroll
                for (int nt = 0; nt < 4; ++nt)
                    mma_tf32(acc[mt][nt], af[mt], bf[nt]);
        }

        if (c + 1 < NCHUNK) {
            __syncthreads();
            const int nxt = cur ^ 1;
#pragma unroll
            for (int i = 0; i < 4; ++i) {
                const int row = lrow + i * 32;
                uint4 ua = make_uint4(f2tf32(ra[i].x), f2tf32(ra[i].y), f2tf32(ra[i].z), f2tf32(ra[i].w));
                uint4 ub = make_uint4(f2tf32(rb[i].x), f2tf32(rb[i].y), f2tf32(rb[i].z), f2tf32(rb[i].w));
                *(uint4*)(sm + nxt * STG_FLOATS + row * APITCH + lcg * 4) = ua;
                *(uint4*)(sm + (2 + nxt) * STG_FLOATS + row * APITCH + lcg * 4) = ub;
            }
            __syncthreads();
        }
    }

    // ---- epilogue: direct float2 stores into [B,H,S,HD] ----
    const float scale = (proj == 0) ? 0.125f : 1.0f;
#pragma unroll
    for (int mt = 0; mt < 4; ++mt) {
        const int r0 = m0 + wm * 64 + mt * 16 + g;
#pragma unroll
        for (int nt = 0; nt < 4; ++nt) {
            const int n = n0 + wn * 32 + nt * 8 + t * 2;
            const int hh = n >> 6;
            const int hd = n & 63;
            float bx = 0.f, by = 0.f;
            if (bias) { bx = bias[n]; by = bias[n + 1]; }
#pragma unroll
            for (int half = 0; half < 2; ++half) {
                const int m = r0 + half * 8;
                if (m >= M_TOT) continue;
                const int bb = m / S;
                const int ss = m - bb * S;
                float2 v;
                v.x = (acc[mt][nt][half * 2 + 0] + bx) * scale;
                v.y = (acc[mt][nt][half * 2 + 1] + by) * scale;
                *(float2*)(dst + (((size_t)bb * H + hh) * S + ss) * HD + hd) = v;
            }
        }
    }
}

// ============================================================================
// Kernel 2: scores + rel bias (known-good from R1)
// ============================================================================
__global__ __launch_bounds__(256) void scores_kernel(
    const float* __restrict__ bias_table, const int* __restrict__ rel_index)
{
    const int bh = blockIdx.z;
    const int q0 = blockIdx.y * 64;
    const int k0 = blockIdx.x * 64;
    const int h = bh % H;

    const float* Q = g_q + (size_t)bh * S * HD;
    const float* K = g_k + (size_t)bh * S * HD;

    __shared__ float Qs[16][64];
    __shared__ float Ks[16][64];

    const int tid = threadIdx.x;
    const int lrow = tid >> 2;
    const int lcol = (tid & 3) * 4;
    const int ty = tid >> 4;
    const int tx = tid & 15;

    float acc[4][4];
#pragma unroll
    for (int i = 0; i < 4; ++i)
#pragma unroll
        for (int j = 0; j < 4; ++j) acc[i][j] = 0.f;

    for (int d0 = 0; d0 < HD; d0 += 16) {
        const int qrow = q0 + lrow;
        float4 a = make_float4(0.f, 0.f, 0.f, 0.f);
        if (qrow < S) a = *(const float4*)(Q + (size_t)qrow * HD + d0 + lcol);
        Qs[lcol + 0][lrow] = a.x; Qs[lcol + 1][lrow] = a.y;
        Qs[lcol + 2][lrow] = a.z; Qs[lcol + 3][lrow] = a.w;

        const int krow = k0 + lrow;
        float4 bb = make_float4(0.f, 0.f, 0.f, 0.f);
        if (krow < S) bb = *(const float4*)(K + (size_t)krow * HD + d0 + lcol);
        Ks[lcol + 0][lrow] = bb.x; Ks[lcol + 1][lrow] = bb.y;
        Ks[lcol + 2][lrow] = bb.z; Ks[lcol + 3][lrow] = bb.w;
        __syncthreads();

#pragma unroll
        for (int kk = 0; kk < 16; ++kk) {
            float a4[4], b4[4];
            *(float4*)a4 = *(const float4*)&Qs[kk][ty * 4];
            *(float4*)b4 = *(const float4*)&Ks[kk][tx * 4];
#pragma unroll
            for (int i = 0; i < 4; ++i)
#pragma unroll
                for (int j = 0; j < 4; ++j)
                    acc[i][j] = fmaf(a4[i], b4[j], acc[i][j]);
        }
        __syncthreads();
    }

#pragma unroll
    for (int i = 0; i < 4; ++i) {
        const int qq = q0 + ty * 4 + i;
        if (qq >= S) continue;
#pragma unroll
        for (int j = 0; j < 4; ++j) {
            const int kk = k0 + tx * 4 + j;
            if (kk >= S) continue;
            const int ridx = rel_index[qq * S + kk];
            g_p[((size_t)bh * S + qq) * S + kk] = acc[i][j] + bias_table[ridx * H + h];
        }
    }
}

// ============================================================================
// Kernel 3: row softmax (known-good)
// ============================================================================
__global__ __launch_bounds__(128) void softmax_kernel()
{
    const size_t row = blockIdx.x;
    float* p = g_p + row * (size_t)S;
    const int t = threadIdx.x;

    const float v0 = (t < S) ? p[t] : -3.0e38f;
    const float v1 = (t + 128 < S) ? p[t + 128] : -3.0e38f;

    float m = fmaxf(v0, v1);
#pragma unroll
    for (int o = 16; o > 0; o >>= 1) m = fmaxf(m, __shfl_xor_sync(0xffffffffu, m, o));
    __shared__ float redm[4];
    if ((t & 31) == 0) redm[t >> 5] = m;
    __syncthreads();
    m = fmaxf(fmaxf(redm[0], redm[1]), fmaxf(redm[2], redm[3]));

    const float e0 = (t < S) ? __expf(v0 - m) : 0.f;
    const float e1 = (t + 128 < S) ? __expf(v1 - m) : 0.f;
    float sum = e0 + e1;
#pragma unroll
    for (int o = 16; o > 0; o >>= 1) sum += __shfl_xor_sync(0xffffffffu, sum, o);
    __shared__ float reds[4];
    if ((t & 31) == 0) reds[t >> 5] = sum;
    __syncthreads();
    sum = reds[0] + reds[1] + reds[2] + reds[3];
    const float inv = 1.f / sum;

    if (t < S) p[t] = e0 * inv;
    if (t + 128 < S) p[t + 128] = e1 * inv;
}

// ============================================================================
// Kernel 4: ctx = P @ V (known-good)
// ============================================================================
__global__ __launch_bounds__(256) void ctx_kernel(float* __restrict__ out)
{
    const int bh = blockIdx.y;
    const int q0 = blockIdx.x * 64;
    const int bb = bh / H;
    const int h = bh % H;

    const float* P = g_p + (size_t)bh * S * S;
    const float* V = g_v + (size_t)bh * S * HD;

    __shared__ float Ps[32][64];
    __shared__ float Vs[32][64];

    const int tid = threadIdx.x;
    const int ty = tid >> 4;
    const int tx = tid & 15;

    float acc[4][4];
#pragma unroll
    for (int i = 0; i < 4; ++i)
#pragma unroll
        for (int j = 0; j < 4; ++j) acc[i][j] = 0.f;

    const int prow = tid >> 2;
    const int pcol = (tid & 3) * 8;

    for (int c0 = 0; c0 < S; c0 += 32) {
        const int qq = q0 + prow;
#pragma unroll
        for (int e = 0; e < 8; ++e) {
            const int kk = c0 + pcol + e;
            float v = 0.f;
            if (qq < S && kk < S) v = P[(size_t)qq * S + kk];
            Ps[pcol + e][prow] = v;
        }
#pragma unroll
        for (int half = 0; half < 2; ++half) {
            const int f = tid + half * 256;
            const int vrow = f >> 4;
            const int vcol = (f & 15) * 4;
            const int kk = c0 + vrow;
            float4 vv = make_float4(0.f, 0.f, 0.f, 0.f);
            if (kk < S) vv = *(const float4*)(V + (size_t)kk * HD + vcol);
            *(float4*)&Vs[vrow][vcol] = vv;
        }
        __syncthreads();

#pragma unroll
        for (int kk = 0; kk < 32; ++kk) {
            float a4[4], b4[4];
            *(float4*)a4 = *(const float4*)&Ps[kk][ty * 4];
            *(float4*)b4 = *(const float4*)&Vs[kk][tx * 4];
#pragma unroll
            for (int i = 0; i < 4; ++i)
#pragma unroll
                for (int j = 0; j < 4; ++j)
                    acc[i][j] = fmaf(a4[i], b4[j], acc[i][j]);
        }
        __syncthreads();
    }

#pragma unroll
    for (int i = 0; i < 4; ++i) {
        const int qq = q0 + ty * 4 + i;
        if (qq >= S) continue;
        float4 r = make_float4(acc[i][0], acc[i][1], acc[i][2], acc[i][3]);
        *(float4*)(out + ((size_t)bb * S + qq) * D + h * HD + tx * 4) = r;
    }
}

// ============================================================================
// Launch. Inputs: hidden_states, wq, bq, wk, wv, bv, bias_table, rel_index
// ============================================================================
extern "C" void kernel_launch(void* const* d_in, const int* in_sizes, int n_in,
                              void* d_out, int out_size)
{
    const float* X  = (const float*)d_in[0];
    const float* wq = (const float*)d_in[1];
    const float* bq = (const float*)d_in[2];
    const float* wk = (const float*)d_in[3];
    const float* wv = (const float*)d_in[4];
    const float* bv = (const float*)d_in[5];
    const float* bt = (const float*)d_in[6];
    const int*   ri = (const int*)d_in[7];
    float* out = (float*)d_out;

    (void)in_sizes; (void)n_in; (void)out_size;

    cudaFuncSetAttribute(qkv_mma_kernel, cudaFuncAttributeMaxDynamicSharedMemorySize, SMEM_QKV_BYTES);

    qkv_mma_kernel<<<dim3((M_TOT + 127) / 128, 2304 / 128), 256, SMEM_QKV_BYTES>>>(X, wq, bq, wk, wv, bv);
    scores_kernel<<<dim3(4, 4, B * H), 256>>>(bt, ri);
    softmax_kernel<<<B * H * S, 128>>>();
    ctx_kernel<<<dim3(4, B * H), 256>>>(out);
}

// round 4
// speedup vs baseline: 3.0481x; 1.5717x over previous
#include <cuda_runtime.h>
#include <math.h>
#include <cstdint>

#define B 64
#define S 197
#define D 768
#define H 12
#define HD 64
#define M_TOT (B * S)          // 12608
#define NUM_REL 732

// -------- device scratch --------
__device__ float g_q[(size_t)B * H * S * HD];
__device__ float g_k[(size_t)B * H * S * HD];
__device__ float g_v[(size_t)B * H * S * HD];
__device__ float g_bias[(size_t)H * S * S];     // 1.86 MB, L2-resident

__device__ __forceinline__ uint32_t f2tf32(float x) {
    uint32_t u;
    asm("cvt.rna.tf32.f32 %0, %1;" : "=r"(u) : "f"(x));
    return u;
}

__device__ __forceinline__ void mma_tf32(float* d, const uint32_t* a, const uint32_t* b) {
    asm volatile(
        "mma.sync.aligned.m16n8k8.row.col.f32.tf32.tf32.f32 "
        "{%0,%1,%2,%3}, {%4,%5,%6,%7}, {%8,%9}, {%0,%1,%2,%3};"
        : "+f"(d[0]), "+f"(d[1]), "+f"(d[2]), "+f"(d[3])
        : "r"(a[0]), "r"(a[1]), "r"(a[2]), "r"(a[3]), "r"(b[0]), "r"(b[1]));
}

// ============================================================================
// Kernel 1: QKV projection with mma.sync TF32 (unchanged from R3, passing).
// ============================================================================
#define BKQ 32
#define NCHUNK 24
#define APITCH 36
#define STG_FLOATS (128 * APITCH)
#define SMEM_QKV_BYTES (4 * STG_FLOATS * 4)

__global__ __launch_bounds__(256, 1) void qkv_mma_kernel(
    const float* __restrict__ X,
    const float* __restrict__ wq, const float* __restrict__ bq,
    const float* __restrict__ wk,
    const float* __restrict__ wv, const float* __restrict__ bv)
{
    extern __shared__ float sm[];
    const int tid  = threadIdx.x;
    const int wid  = tid >> 5;
    const int lane = tid & 31;
    const int g    = lane >> 2;
    const int t    = lane & 3;
    const int wm   = wid & 1;
    const int wn   = wid >> 1;

    const int m0  = blockIdx.x * 128;
    const int n0g = blockIdx.y * 128;
    const int proj = n0g / 768;
    const int n0   = n0g - proj * 768;

    const float* W    = (proj == 0) ? wq : ((proj == 1) ? wk : wv);
    const float* bias = (proj == 0) ? bq : ((proj == 2) ? bv : nullptr);
    float* dst        = (proj == 0) ? g_q : ((proj == 1) ? g_k : g_v);

    const int lrow = tid >> 3;
    const int lcg  = tid & 7;

    float4 ra[4], rb[4];

#pragma unroll
    for (int i = 0; i < 4; ++i) {
        const int row = lrow + i * 32;
        const int m = m0 + row;
        ra[i] = make_float4(0.f, 0.f, 0.f, 0.f);
        if (m < M_TOT) ra[i] = *(const float4*)(X + (size_t)m * 768 + lcg * 4);
        rb[i] = *(const float4*)(W + (size_t)(n0 + row) * 768 + lcg * 4);
    }
#pragma unroll
    for (int i = 0; i < 4; ++i) {
        const int row = lrow + i * 32;
        uint4 ua = make_uint4(f2tf32(ra[i].x), f2tf32(ra[i].y), f2tf32(ra[i].z), f2tf32(ra[i].w));
        uint4 ub = make_uint4(f2tf32(rb[i].x), f2tf32(rb[i].y), f2tf32(rb[i].z), f2tf32(rb[i].w));
        *(uint4*)(sm + row * APITCH + lcg * 4) = ua;
        *(uint4*)(sm + 2 * STG_FLOATS + row * APITCH + lcg * 4) = ub;
    }
    __syncthreads();

    float acc[4][4][4];
#pragma unroll
    for (int mt = 0; mt < 4; ++mt)
#pragma unroll
        for (int nt = 0; nt < 4; ++nt)
#pragma unroll
            for (int e = 0; e < 4; ++e) acc[mt][nt][e] = 0.f;

    for (int c = 0; c < NCHUNK; ++c) {
        const int cur = c & 1;
        if (c + 1 < NCHUNK) {
            const int k0 = (c + 1) * BKQ;
#pragma unroll
            for (int i = 0; i < 4; ++i) {
                const int row = lrow + i * 32;
                const int m = m0 + row;
                ra[i] = make_float4(0.f, 0.f, 0.f, 0.f);
                if (m < M_TOT) ra[i] = *(const float4*)(X + (size_t)m * 768 + k0 + lcg * 4);
                rb[i] = *(const float4*)(W + (size_t)(n0 + row) * 768 + k0 + lcg * 4);
            }
        }

        const uint32_t* Au = (const uint32_t*)(sm + cur * STG_FLOATS);
        const uint32_t* Bu = (const uint32_t*)(sm + (2 + cur) * STG_FLOATS);
#pragma unroll
        for (int ks = 0; ks < 4; ++ks) {
            uint32_t af[4][4], bf[4][2];
#pragma unroll
            for (int mt = 0; mt < 4; ++mt) {
                const int r0 = wm * 64 + mt * 16 + g;
                af[mt][0] = Au[r0 * APITCH + ks * 8 + t];
                af[mt][1] = Au[(r0 + 8) * APITCH + ks * 8 + t];
                af[mt][2] = Au[r0 * APITCH + ks * 8 + t + 4];
                af[mt][3] = Au[(r0 + 8) * APITCH + ks * 8 + t + 4];
            }
#pragma unroll
            for (int nt = 0; nt < 4; ++nt) {
                const int c0 = wn * 32 + nt * 8 + g;
                bf[nt][0] = Bu[c0 * APITCH + ks * 8 + t];
                bf[nt][1] = Bu[c0 * APITCH + ks * 8 + t + 4];
            }
#pragma unroll
            for (int mt = 0; mt < 4; ++mt)
#pragma unroll
                for (int nt = 0; nt < 4; ++nt)
                    mma_tf32(acc[mt][nt], af[mt], bf[nt]);
        }

        if (c + 1 < NCHUNK) {
            __syncthreads();
            const int nxt = cur ^ 1;
#pragma unroll
            for (int i = 0; i < 4; ++i) {
                const int row = lrow + i * 32;
                uint4 ua = make_uint4(f2tf32(ra[i].x), f2tf32(ra[i].y), f2tf32(ra[i].z), f2tf32(ra[i].w));
                uint4 ub = make_uint4(f2tf32(rb[i].x), f2tf32(rb[i].y), f2tf32(rb[i].z), f2tf32(rb[i].w));
                *(uint4*)(sm + nxt * STG_FLOATS + row * APITCH + lcg * 4) = ua;
                *(uint4*)(sm + (2 + nxt) * STG_FLOATS + row * APITCH + lcg * 4) = ub;
            }
            __syncthreads();
        }
    }

    const float scale = (proj == 0) ? 0.125f : 1.0f;
#pragma unroll
    for (int mt = 0; mt < 4; ++mt) {
        const int r0 = m0 + wm * 64 + mt * 16 + g;
#pragma unroll
        for (int nt = 0; nt < 4; ++nt) {
            const int n = n0 + wn * 32 + nt * 8 + t * 2;
            const int hh = n >> 6;
            const int hd = n & 63;
            float bx = 0.f, by = 0.f;
            if (bias) { bx = bias[n]; by = bias[n + 1]; }
#pragma unroll
            for (int half = 0; half < 2; ++half) {
                const int m = r0 + half * 8;
                if (m >= M_TOT) continue;
                const int bb = m / S;
                const int ss = m - bb * S;
                float2 v;
                v.x = (acc[mt][nt][half * 2 + 0] + bx) * scale;
                v.y = (acc[mt][nt][half * 2 + 1] + by) * scale;
                *(float2*)(dst + (((size_t)bb * H + hh) * S + ss) * HD + hd) = v;
            }
        }
    }
}

// ============================================================================
// Kernel 2: expand relative-position bias to g_bias[h][q][k] (1.86 MB).
// ============================================================================
__global__ __launch_bounds__(256) void bias_expand_kernel(
    const float* __restrict__ bias_table, const int* __restrict__ rel_index)
{
    const int i = blockIdx.x * 256 + threadIdx.x;   // over S*S
    if (i >= S * S) return;
    const int r = rel_index[i];
#pragma unroll
    for (int h = 0; h < H; ++h)
        g_bias[(size_t)h * S * S + i] = bias_table[r * H + h];
}

// ============================================================================
// Kernel 3: fused flash attention (scores + bias + softmax + ctx).
// CTA: (qtile in {0,1}, bh). 256 thr = 8 warps, each warp owns 16 q-rows.
// K-tiles of 128 (2 iterations), online softmax, O in registers.
// smem: sK[128][72] | sV[128][72] | sP[128][136] (sQ staged in sP region).
// ============================================================================
#define PKV 72
#define PPP 136
#define SK_OFF 0
#define SV_OFF (128 * PKV)
#define SP_OFF (2 * 128 * PKV)
#define SMEM_FLASH_FLOATS (2 * 128 * PKV + 128 * PPP)
#define SMEM_FLASH_BYTES (SMEM_FLASH_FLOATS * 4)    // 143360

__global__ __launch_bounds__(256, 1) void flash_kernel(float* __restrict__ out)
{
    extern __shared__ float sm[];
    uint32_t* smu = (uint32_t*)sm;

    const int tid  = threadIdx.x;
    const int wid  = tid >> 5;
    const int lane = tid & 31;
    const int g    = lane >> 2;
    const int t    = lane & 3;

    const int qt = blockIdx.x;                  // 0,1
    const int bh = blockIdx.y;                  // 0..767
    const int b  = bh / H;
    const int h  = bh - b * H;
    const int qbase = qt * 128;
    const int wrow  = wid * 16;

    const float* Qg = g_q + (size_t)bh * S * HD;
    const float* Kg = g_k + (size_t)bh * S * HD;
    const float* Vg = g_v + (size_t)bh * S * HD;

    // ---- stage Q tile into sP region (pitch PKV), tf32 ----
    {
        uint32_t* sQ = smu + SP_OFF;
#pragma unroll
        for (int it = 0; it < 8; ++it) {
            const int f = tid + it * 256;       // 2048 = 128*16
            const int row = f >> 4, cg = f & 15;
            const int m = qbase + row;
            float4 v = make_float4(0.f, 0.f, 0.f, 0.f);
            if (m < S) v = *(const float4*)(Qg + (size_t)m * HD + cg * 4);
            uint4 u = make_uint4(f2tf32(v.x), f2tf32(v.y), f2tf32(v.z), f2tf32(v.w));
            *(uint4*)(sQ + row * PKV + cg * 4) = u;
        }
    }
    __syncthreads();

    // ---- extract Q fragments (warp-private, 32 regs) ----
    uint32_t qf[8][4];
    {
        const uint32_t* sQ = smu + SP_OFF;
#pragma unroll
        for (int ks = 0; ks < 8; ++ks) {
            qf[ks][0] = sQ[(wrow + g) * PKV + ks * 8 + t];
            qf[ks][1] = sQ[(wrow + g + 8) * PKV + ks * 8 + t];
            qf[ks][2] = sQ[(wrow + g) * PKV + ks * 8 + t + 4];
            qf[ks][3] = sQ[(wrow + g + 8) * PKV + ks * 8 + t + 4];
        }
    }
    __syncthreads();    // sP region now free for P

    // bias row pointers (clamped to stay in bounds; OOB rows masked at store)
    const int qr0 = qbase + wrow + g;
    const int qr1 = qr0 + 8;
    const float* brow0 = g_bias + ((size_t)h * S + min(qr0, S - 1)) * S;
    const float* brow1 = g_bias + ((size_t)h * S + min(qr1, S - 1)) * S;

    float m0r = -1e30f, m1r = -1e30f, l0 = 0.f, l1 = 0.f;
    float o[8][4];
#pragma unroll
    for (int j = 0; j < 8; ++j)
#pragma unroll
        for (int e = 0; e < 4; ++e) o[j][e] = 0.f;

    for (int kt = 0; kt < 2; ++kt) {
        const int kb = kt * 128;

        // ---- load K,V tiles (tf32, zero-padded) ----
#pragma unroll
        for (int it = 0; it < 8; ++it) {
            const int f = tid + it * 256;
            const int row = f >> 4, cg = f & 15;
            const int kk = kb + row;
            float4 vk = make_float4(0.f, 0.f, 0.f, 0.f);
            float4 vv = make_float4(0.f, 0.f, 0.f, 0.f);
            if (kk < S) {
                vk = *(const float4*)(Kg + (size_t)kk * HD + cg * 4);
                vv = *(const float4*)(Vg + (size_t)kk * HD + cg * 4);
            }
            uint4 uk = make_uint4(f2tf32(vk.x), f2tf32(vk.y), f2tf32(vk.z), f2tf32(vk.w));
            uint4 uv = make_uint4(f2tf32(vv.x), f2tf32(vv.y), f2tf32(vv.z), f2tf32(vv.w));
            *(uint4*)(smu + SK_OFF + row * PKV + cg * 4) = uk;
            *(uint4*)(smu + SV_OFF + row * PKV + cg * 4) = uv;
        }
        __syncthreads();

        // ---- S = Q K^T : 16 n-tiles x 8 k-steps ----
        float sacc[16][4];
#pragma unroll
        for (int j = 0; j < 16; ++j)
#pragma unroll
            for (int e = 0; e < 4; ++e) sacc[j][e] = 0.f;

#pragma unroll
        for (int ks = 0; ks < 8; ++ks) {
#pragma unroll
            for (int j = 0; j < 16; ++j) {
                uint32_t bf[2];
                bf[0] = smu[SK_OFF + (j * 8 + g) * PKV + ks * 8 + t];
                bf[1] = smu[SK_OFF + (j * 8 + g) * PKV + ks * 8 + t + 4];
                mma_tf32(sacc[j], qf[ks], bf);
            }
        }

        // ---- bias add + mask ----
#pragma unroll
        for (int j = 0; j < 16; ++j) {
            const int kc = kb + j * 8 + 2 * t;
            if (kc < S)     sacc[j][0] += brow0[kc];     else sacc[j][0] = -1e30f;
            if (kc + 1 < S) sacc[j][1] += brow0[kc + 1]; else sacc[j][1] = -1e30f;
            if (kc < S)     sacc[j][2] += brow1[kc];     else sacc[j][2] = -1e30f;
            if (kc + 1 < S) sacc[j][3] += brow1[kc + 1]; else sacc[j][3] = -1e30f;
        }

        // ---- online softmax (quad-local rows) ----
        float mx0 = -1e30f, mx1 = -1e30f;
#pragma unroll
        for (int j = 0; j < 16; ++j) {
            mx0 = fmaxf(mx0, fmaxf(sacc[j][0], sacc[j][1]));
            mx1 = fmaxf(mx1, fmaxf(sacc[j][2], sacc[j][3]));
        }
        mx0 = fmaxf(mx0, __shfl_xor_sync(0xffffffffu, mx0, 1));
        mx0 = fmaxf(mx0, __shfl_xor_sync(0xffffffffu, mx0, 2));
        mx1 = fmaxf(mx1, __shfl_xor_sync(0xffffffffu, mx1, 1));
        mx1 = fmaxf(mx1, __shfl_xor_sync(0xffffffffu, mx1, 2));

        const float nm0 = fmaxf(m0r, mx0);
        const float nm1 = fmaxf(m1r, mx1);
        const float sc0 = __expf(m0r - nm0);
        const float sc1 = __expf(m1r - nm1);
        m0r = nm0; m1r = nm1;

        float sum0 = 0.f, sum1 = 0.f;
        uint32_t* sP = smu + SP_OFF;
#pragma unroll
        for (int j = 0; j < 16; ++j) {
            const float p0 = __expf(sacc[j][0] - nm0);
            const float p1 = __expf(sacc[j][1] - nm0);
            const float p2 = __expf(sacc[j][2] - nm1);
            const float p3 = __expf(sacc[j][3] - nm1);
            sum0 += p0 + p1; sum1 += p2 + p3;
            const int col = j * 8 + 2 * t;
            sP[(wrow + g) * PPP + col]     = f2tf32(p0);
            sP[(wrow + g) * PPP + col + 1] = f2tf32(p1);
            sP[(wrow + g + 8) * PPP + col]     = f2tf32(p2);
            sP[(wrow + g + 8) * PPP + col + 1] = f2tf32(p3);
        }
        sum0 += __shfl_xor_sync(0xffffffffu, sum0, 1);
        sum0 += __shfl_xor_sync(0xffffffffu, sum0, 2);
        sum1 += __shfl_xor_sync(0xffffffffu, sum1, 1);
        sum1 += __shfl_xor_sync(0xffffffffu, sum1, 2);
        l0 = l0 * sc0 + sum0;
        l1 = l1 * sc1 + sum1;

#pragma unroll
        for (int j = 0; j < 8; ++j) {
            o[j][0] *= sc0; o[j][1] *= sc0;
            o[j][2] *= sc1; o[j][3] *= sc1;
        }
        __syncwarp();

        // ---- O += P V : 16 k-steps x 8 n-tiles ----
#pragma unroll
        for (int ks = 0; ks < 16; ++ks) {
            uint32_t af[4];
            af[0] = sP[(wrow + g) * PPP + ks * 8 + t];
            af[1] = sP[(wrow + g + 8) * PPP + ks * 8 + t];
            af[2] = sP[(wrow + g) * PPP + ks * 8 + t + 4];
            af[3] = sP[(wrow + g + 8) * PPP + ks * 8 + t + 4];
#pragma unroll
            for (int j = 0; j < 8; ++j) {
                uint32_t bf[2];
                bf[0] = smu[SV_OFF + (ks * 8 + t) * PKV + j * 8 + g];
                bf[1] = smu[SV_OFF + (ks * 8 + t + 4) * PKV + j * 8 + g];
                mma_tf32(o[j], af, bf);
            }
        }
        __syncthreads();   // all warps done with sK/sV before next tile
    }

    // ---- epilogue ----
    const float inv0 = 1.f / l0;
    const float inv1 = 1.f / l1;
#pragma unroll
    for (int j = 0; j < 8; ++j) {
        const int col = h * HD + j * 8 + 2 * t;
        if (qr0 < S) {
            float2 v; v.x = o[j][0] * inv0; v.y = o[j][1] * inv0;
            *(float2*)(out + ((size_t)b * S + qr0) * D + col) = v;
        }
        if (qr1 < S) {
            float2 v; v.x = o[j][2] * inv1; v.y = o[j][3] * inv1;
            *(float2*)(out + ((size_t)b * S + qr1) * D + col) = v;
        }
    }
}

// ============================================================================
// Launch. Inputs: hidden_states, wq, bq, wk, wv, bv, bias_table, rel_index
// ============================================================================
extern "C" void kernel_launch(void* const* d_in, const int* in_sizes, int n_in,
                              void* d_out, int out_size)
{
    const float* X  = (const float*)d_in[0];
    const float* wq = (const float*)d_in[1];
    const float* bq = (const float*)d_in[2];
    const float* wk = (const float*)d_in[3];
    const float* wv = (const float*)d_in[4];
    const float* bv = (const float*)d_in[5];
    const float* bt = (const float*)d_in[6];
    const int*   ri = (const int*)d_in[7];
    float* out = (float*)d_out;

    (void)in_sizes; (void)n_in; (void)out_size;

    cudaFuncSetAttribute(qkv_mma_kernel, cudaFuncAttributeMaxDynamicSharedMemorySize, SMEM_QKV_BYTES);
    cudaFuncSetAttribute(flash_kernel, cudaFuncAttributeMaxDynamicSharedMemorySize, SMEM_FLASH_BYTES);

    qkv_mma_kernel<<<dim3((M_TOT + 127) / 128, 2304 / 128), 256, SMEM_QKV_BYTES>>>(X, wq, bq, wk, wv, bv);
    bias_expand_kernel<<<(S * S + 255) / 256, 256>>>(bt, ri);
    flash_kernel<<<dim3(2, B * H), 256, SMEM_FLASH_BYTES>>>(out);
}

// round 5
// speedup vs baseline: 3.2965x; 1.0815x over previous
#include <cuda_runtime.h>
#include <math.h>
#include <cstdint>

#define B 64
#define S 197
#define D 768
#define H 12
#define HD 64
#define M_TOT (B * S)          // 12608
#define NUM_REL 732

// -------- device scratch --------
__device__ uint32_t g_xt[(size_t)M_TOT * D];        // X in tf32 (38.7 MB)
__device__ uint32_t g_wt[(size_t)3 * D * D];        // wq|wk|wv in tf32 (7.1 MB)
__device__ uint32_t g_q[(size_t)B * H * S * HD];    // tf32
__device__ uint32_t g_k[(size_t)B * H * S * HD];    // tf32
__device__ uint32_t g_v[(size_t)B * H * S * HD];    // tf32
__device__ float g_bias[(size_t)H * S * S];         // 1.86 MB, L2-resident

__device__ __forceinline__ uint32_t f2tf32(float x) {
    uint32_t u;
    asm("cvt.rna.tf32.f32 %0, %1;" : "=r"(u) : "f"(x));
    return u;
}

__device__ __forceinline__ void mma_tf32(float* d, const uint32_t* a, const uint32_t* b) {
    asm volatile(
        "mma.sync.aligned.m16n8k8.row.col.f32.tf32.tf32.f32 "
        "{%0,%1,%2,%3}, {%4,%5,%6,%7}, {%8,%9}, {%0,%1,%2,%3};"
        : "+f"(d[0]), "+f"(d[1]), "+f"(d[2]), "+f"(d[3])
        : "r"(a[0]), "r"(a[1]), "r"(a[2]), "r"(a[3]), "r"(b[0]), "r"(b[1]));
}

__device__ __forceinline__ uint32_t smem_u32(const void* p) {
    uint32_t a;
    asm("{ .reg .u64 t; cvta.to.shared.u64 t, %1; cvt.u32.u64 %0, t; }" : "=r"(a) : "l"(p));
    return a;
}

__device__ __forceinline__ void cp16(uint32_t dst, const void* src, bool pred) {
    const int sz = pred ? 16 : 0;
    asm volatile("cp.async.cg.shared.global [%0], [%1], 16, %2;"
                 :: "r"(dst), "l"(src), "r"(sz) : "memory");
}
#define CP_COMMIT() asm volatile("cp.async.commit_group;" ::: "memory")
#define CP_WAIT1()  asm volatile("cp.async.wait_group 1;" ::: "memory")

// ============================================================================
// Kernel 0: fp32 -> tf32 bulk convert (float4 granularity).
// ============================================================================
__global__ __launch_bounds__(256) void cvt_kernel(
    const float* __restrict__ src, uint32_t* __restrict__ dst, int n4)
{
    const int i = blockIdx.x * 256 + threadIdx.x;
    if (i >= n4) return;
    const float4 v = ((const float4*)src)[i];
    ((uint4*)dst)[i] = make_uint4(f2tf32(v.x), f2tf32(v.y), f2tf32(v.z), f2tf32(v.w));
}

// ============================================================================
// Kernel 1: QKV projection, TF32 mma.sync, cp.async 3-stage pipeline.
// CTA 128x128x32, 256 thr, 2 CTAs/SM. Zero CVT in mainloop.
// Stage: A[128][36] + B[128][36] uint32 -> 36864 B; 3 stages = 110592 B.
// ============================================================================
#define APITCH 36
#define TILE_U32 (128 * APITCH)                 // 4608
#define STAGE_BYTES (2 * TILE_U32 * 4)          // 36864
#define SMEM_QKV_BYTES (3 * STAGE_BYTES)        // 110592
#define NCHUNK 24

__global__ __launch_bounds__(256, 2) void qkv_mma_kernel(
    const float* __restrict__ bq, const float* __restrict__ bv)
{
    extern __shared__ uint32_t smq[];
    const uint32_t sbase = smem_u32(smq);

    const int tid  = threadIdx.x;
    const int wid  = tid >> 5;
    const int lane = tid & 31;
    const int g    = lane >> 2;
    const int t    = lane & 3;
    const int wm   = wid & 1;
    const int wn   = wid >> 1;

    const int m0  = blockIdx.x * 128;
    const int n0g = blockIdx.y * 128;
    const int proj = n0g / 768;                 // 0=q 1=k 2=v
    const int n0   = n0g - proj * 768;

    const float* bias = (proj == 0) ? bq : ((proj == 2) ? bv : nullptr);
    uint32_t* dst     = (proj == 0) ? g_q : ((proj == 1) ? g_k : g_v);

    const int lrow = tid >> 3;                  // 0..31
    const int lcg  = tid & 7;                   // 0..7

    // issue loads for K-chunk c into stage slot s
    auto issue = [&](int c, int s) {
        const int k0 = c * 32;
        const uint32_t smA = sbase + s * STAGE_BYTES;
        const uint32_t smB = smA + TILE_U32 * 4;
#pragma unroll
        for (int i = 0; i < 4; ++i) {
            const int row = lrow + i * 32;
            const int m = m0 + row;
            const bool pa = m < M_TOT;
            const uint32_t* srcA = g_xt + (size_t)(pa ? m : 0) * 768 + k0 + lcg * 4;
            cp16(smA + (row * APITCH + lcg * 4) * 4, srcA, pa);
            const uint32_t* srcB = g_wt + (size_t)(n0g + row) * 768 + k0 + lcg * 4;
            cp16(smB + (row * APITCH + lcg * 4) * 4, srcB, true);
        }
        CP_COMMIT();
    };

    issue(0, 0);
    issue(1, 1);

    float acc[4][4][4];
#pragma unroll
    for (int mt = 0; mt < 4; ++mt)
#pragma unroll
        for (int nt = 0; nt < 4; ++nt)
#pragma unroll
            for (int e = 0; e < 4; ++e) acc[mt][nt][e] = 0.f;

    for (int c = 0; c < NCHUNK; ++c) {
        CP_WAIT1();
        __syncthreads();

        const uint32_t* Au = smq + (c % 3) * (STAGE_BYTES / 4);
        const uint32_t* Bu = Au + TILE_U32;
#pragma unroll
        for (int ks = 0; ks < 4; ++ks) {
            uint32_t af[4][4], bf[4][2];
#pragma unroll
            for (int mt = 0; mt < 4; ++mt) {
                const int r0 = wm * 64 + mt * 16 + g;
                af[mt][0] = Au[r0 * APITCH + ks * 8 + t];
                af[mt][1] = Au[(r0 + 8) * APITCH + ks * 8 + t];
                af[mt][2] = Au[r0 * APITCH + ks * 8 + t + 4];
                af[mt][3] = Au[(r0 + 8) * APITCH + ks * 8 + t + 4];
            }
#pragma unroll
            for (int nt = 0; nt < 4; ++nt) {
                const int c0 = wn * 32 + nt * 8 + g;
                bf[nt][0] = Bu[c0 * APITCH + ks * 8 + t];
                bf[nt][1] = Bu[c0 * APITCH + ks * 8 + t + 4];
            }
#pragma unroll
            for (int mt = 0; mt < 4; ++mt)
#pragma unroll
                for (int nt = 0; nt < 4; ++nt)
                    mma_tf32(acc[mt][nt], af[mt], bf[nt]);
        }
        __syncthreads();

        if (c + 2 < NCHUNK) issue(c + 2, (c + 2) % 3);
    }

    // ---- epilogue: bias + scale, convert to tf32, store [B,H,S,HD] ----
    const float scale = (proj == 0) ? 0.125f : 1.0f;
#pragma unroll
    for (int mt = 0; mt < 4; ++mt) {
        const int r0 = m0 + wm * 64 + mt * 16 + g;
#pragma unroll
        for (int nt = 0; nt < 4; ++nt) {
            const int n = n0 + wn * 32 + nt * 8 + t * 2;
            const int hh = n >> 6;
            const int hd = n & 63;
            float bx = 0.f, by = 0.f;
            if (bias) { bx = bias[n]; by = bias[n + 1]; }
#pragma unroll
            for (int half = 0; half < 2; ++half) {
                const int m = r0 + half * 8;
                if (m >= M_TOT) continue;
                const int bb = m / S;
                const int ss = m - bb * S;
                uint2 v;
                v.x = f2tf32((acc[mt][nt][half * 2 + 0] + bx) * scale);
                v.y = f2tf32((acc[mt][nt][half * 2 + 1] + by) * scale);
                *(uint2*)(dst + (((size_t)bb * H + hh) * S + ss) * HD + hd) = v;
            }
        }
    }
}

// ============================================================================
// Kernel 2: expand relative-position bias to g_bias[h][q][k].
// ============================================================================
__global__ __launch_bounds__(256) void bias_expand_kernel(
    const float* __restrict__ bias_table, const int* __restrict__ rel_index)
{
    const int i = blockIdx.x * 256 + threadIdx.x;
    if (i >= S * S) return;
    const int r = rel_index[i];
#pragma unroll
    for (int h = 0; h < H; ++h)
        g_bias[(size_t)h * S * S + i] = bias_table[r * H + h];
}

// ============================================================================
// Kernel 3: fused flash attention. Q/K/V already tf32 -> zero CVT on loads.
// ============================================================================
#define PKV 72
#define PPP 136
#define SK_OFF 0
#define SV_OFF (128 * PKV)
#define SP_OFF (2 * 128 * PKV)
#define SMEM_FLASH_BYTES ((2 * 128 * PKV + 128 * PPP) * 4)   // 143360

__global__ __launch_bounds__(256, 1) void flash_kernel(float* __restrict__ out)
{
    extern __shared__ uint32_t smu[];

    const int tid  = threadIdx.x;
    const int wid  = tid >> 5;
    const int lane = tid & 31;
    const int g    = lane >> 2;
    const int t    = lane & 3;

    const int qt = blockIdx.x;
    const int bh = blockIdx.y;
    const int b  = bh / H;
    const int h  = bh - b * H;
    const int qbase = qt * 128;
    const int wrow  = wid * 16;

    const uint32_t* Qg = g_q + (size_t)bh * S * HD;
    const uint32_t* Kg = g_k + (size_t)bh * S * HD;
    const uint32_t* Vg = g_v + (size_t)bh * S * HD;

    // ---- stage Q tile into sP region ----
    {
        uint32_t* sQ = smu + SP_OFF;
#pragma unroll
        for (int it = 0; it < 8; ++it) {
            const int f = tid + it * 256;
            const int row = f >> 4, cg = f & 15;
            const int m = qbase + row;
            uint4 u = make_uint4(0u, 0u, 0u, 0u);
            if (m < S) u = *(const uint4*)(Qg + (size_t)m * HD + cg * 4);
            *(uint4*)(sQ + row * PKV + cg * 4) = u;
        }
    }
    __syncthreads();

    uint32_t qf[8][4];
    {
        const uint32_t* sQ = smu + SP_OFF;
#pragma unroll
        for (int ks = 0; ks < 8; ++ks) {
            qf[ks][0] = sQ[(wrow + g) * PKV + ks * 8 + t];
            qf[ks][1] = sQ[(wrow + g + 8) * PKV + ks * 8 + t];
            qf[ks][2] = sQ[(wrow + g) * PKV + ks * 8 + t + 4];
            qf[ks][3] = sQ[(wrow + g + 8) * PKV + ks * 8 + t + 4];
        }
    }
    __syncthreads();

    const int qr0 = qbase + wrow + g;
    const int qr1 = qr0 + 8;
    const float* brow0 = g_bias + ((size_t)h * S + min(qr0, S - 1)) * S;
    const float* brow1 = g_bias + ((size_t)h * S + min(qr1, S - 1)) * S;

    float m0r = -1e30f, m1r = -1e30f, l0 = 0.f, l1 = 0.f;
    float o[8][4];
#pragma unroll
    for (int j = 0; j < 8; ++j)
#pragma unroll
        for (int e = 0; e < 4; ++e) o[j][e] = 0.f;

    for (int kt = 0; kt < 2; ++kt) {
        const int kb = kt * 128;

#pragma unroll
        for (int it = 0; it < 8; ++it) {
            const int f = tid + it * 256;
            const int row = f >> 4, cg = f & 15;
            const int kk = kb + row;
            uint4 uk = make_uint4(0u, 0u, 0u, 0u);
            uint4 uv = make_uint4(0u, 0u, 0u, 0u);
            if (kk < S) {
                uk = *(const uint4*)(Kg + (size_t)kk * HD + cg * 4);
                uv = *(const uint4*)(Vg + (size_t)kk * HD + cg * 4);
            }
            *(uint4*)(smu + SK_OFF + row * PKV + cg * 4) = uk;
            *(uint4*)(smu + SV_OFF + row * PKV + cg * 4) = uv;
        }
        __syncthreads();

        float sacc[16][4];
#pragma unroll
        for (int j = 0; j < 16; ++j)
#pragma unroll
            for (int e = 0; e < 4; ++e) sacc[j][e] = 0.f;

#pragma unroll
        for (int ks = 0; ks < 8; ++ks) {
#pragma unroll
            for (int j = 0; j < 16; ++j) {
                uint32_t bf[2];
                bf[0] = smu[SK_OFF + (j * 8 + g) * PKV + ks * 8 + t];
                bf[1] = smu[SK_OFF + (j * 8 + g) * PKV + ks * 8 + t + 4];
                mma_tf32(sacc[j], qf[ks], bf);
            }
        }

#pragma unroll
        for (int j = 0; j < 16; ++j) {
            const int kc = kb + j * 8 + 2 * t;
            if (kc < S)     sacc[j][0] += brow0[kc];     else sacc[j][0] = -1e30f;
            if (kc + 1 < S) sacc[j][1] += brow0[kc + 1]; else sacc[j][1] = -1e30f;
            if (kc < S)     sacc[j][2] += brow1[kc];     else sacc[j][2] = -1e30f;
            if (kc + 1 < S) sacc[j][3] += brow1[kc + 1]; else sacc[j][3] = -1e30f;
        }

        float mx0 = -1e30f, mx1 = -1e30f;
#pragma unroll
        for (int j = 0; j < 16; ++j) {
            mx0 = fmaxf(mx0, fmaxf(sacc[j][0], sacc[j][1]));
            mx1 = fmaxf(mx1, fmaxf(sacc[j][2], sacc[j][3]));
        }
        mx0 = fmaxf(mx0, __shfl_xor_sync(0xffffffffu, mx0, 1));
        mx0 = fmaxf(mx0, __shfl_xor_sync(0xffffffffu, mx0, 2));
        mx1 = fmaxf(mx1, __shfl_xor_sync(0xffffffffu, mx1, 1));
        mx1 = fmaxf(mx1, __shfl_xor_sync(0xffffffffu, mx1, 2));

        const float nm0 = fmaxf(m0r, mx0);
        const float nm1 = fmaxf(m1r, mx1);
        const float sc0 = __expf(m0r - nm0);
        const float sc1 = __expf(m1r - nm1);
        m0r = nm0; m1r = nm1;

        float sum0 = 0.f, sum1 = 0.f;
        uint32_t* sP = smu + SP_OFF;
#pragma unroll
        for (int j = 0; j < 16; ++j) {
            const float p0 = __expf(sacc[j][0] - nm0);
            const float p1 = __expf(sacc[j][1] - nm0);
            const float p2 = __expf(sacc[j][2] - nm1);
            const float p3 = __expf(sacc[j][3] - nm1);
            sum0 += p0 + p1; sum1 += p2 + p3;
            const int col = j * 8 + 2 * t;
            sP[(wrow + g) * PPP + col]     = f2tf32(p0);
            sP[(wrow + g) * PPP + col + 1] = f2tf32(p1);
            sP[(wrow + g + 8) * PPP + col]     = f2tf32(p2);
            sP[(wrow + g + 8) * PPP + col + 1] = f2tf32(p3);
        }
        sum0 += __shfl_xor_sync(0xffffffffu, sum0, 1);
        sum0 += __shfl_xor_sync(0xffffffffu, sum0, 2);
        sum1 += __shfl_xor_sync(0xffffffffu, sum1, 1);
        sum1 += __shfl_xor_sync(0xffffffffu, sum1, 2);
        l0 = l0 * sc0 + sum0;
        l1 = l1 * sc1 + sum1;

#pragma unroll
        for (int j = 0; j < 8; ++j) {
            o[j][0] *= sc0; o[j][1] *= sc0;
            o[j][2] *= sc1; o[j][3] *= sc1;
        }
        __syncwarp();

#pragma unroll
        for (int ks = 0; ks < 16; ++ks) {
            uint32_t af[4];
            af[0] = sP[(wrow + g) * PPP + ks * 8 + t];
            af[1] = sP[(wrow + g + 8) * PPP + ks * 8 + t];
            af[2] = sP[(wrow + g) * PPP + ks * 8 + t + 4];
            af[3] = sP[(wrow + g + 8) * PPP + ks * 8 + t + 4];
#pragma unroll
            for (int j = 0; j < 8; ++j) {
                uint32_t bf[2];
                bf[0] = smu[SV_OFF + (ks * 8 + t) * PKV + j * 8 + g];
                bf[1] = smu[SV_OFF + (ks * 8 + t + 4) * PKV + j * 8 + g];
                mma_tf32(o[j], af, bf);
            }
        }
        __syncthreads();
    }

    const float inv0 = 1.f / l0;
    const float inv1 = 1.f / l1;
#pragma unroll
    for (int j = 0; j < 8; ++j) {
        const int col = h * HD + j * 8 + 2 * t;
        if (qr0 < S) {
            float2 v; v.x = o[j][0] * inv0; v.y = o[j][1] * inv0;
            *(float2*)(out + ((size_t)b * S + qr0) * D + col) = v;
        }
        if (qr1 < S) {
            float2 v; v.x = o[j][2] * inv1; v.y = o[j][3] * inv1;
            *(float2*)(out + ((size_t)b * S + qr1) * D + col) = v;
        }
    }
}

// ============================================================================
// Launch. Inputs: hidden_states, wq, bq, wk, wv, bv, bias_table, rel_index
// ============================================================================
extern "C" void kernel_launch(void* const* d_in, const int* in_sizes, int n_in,
                              void* d_out, int out_size)
{
    const float* X  = (const float*)d_in[0];
    const float* wq = (const float*)d_in[1];
    const float* bq = (const float*)d_in[2];
    const float* wk = (const float*)d_in[3];
    const float* wv = (const float*)d_in[4];
    const float* bv = (const float*)d_in[5];
    const float* bt = (const float*)d_in[6];
    const int*   ri = (const int*)d_in[7];
    float* out = (float*)d_out;

    (void)in_sizes; (void)n_in; (void)out_size;

    static uint32_t* xt_ptr = nullptr;
    static uint32_t* wt_ptr = nullptr;
    if (!xt_ptr) {
        cudaGetSymbolAddress((void**)&xt_ptr, g_xt);
        cudaGetSymbolAddress((void**)&wt_ptr, g_wt);
        cudaFuncSetAttribute(qkv_mma_kernel, cudaFuncAttributeMaxDynamicSharedMemorySize, SMEM_QKV_BYTES);
        cudaFuncSetAttribute(flash_kernel, cudaFuncAttributeMaxDynamicSharedMemorySize, SMEM_FLASH_BYTES);
    }

    const int nx4 = M_TOT * D / 4;              // 2420736
    const int nw4 = D * D / 4;                  // 147456
    cvt_kernel<<<(nx4 + 255) / 256, 256>>>(X, xt_ptr, nx4);
    cvt_kernel<<<(nw4 + 255) / 256, 256>>>(wq, wt_ptr, nw4);
    cvt_kernel<<<(nw4 + 255) / 256, 256>>>(wk, wt_ptr + (size_t)D * D, nw4);
    cvt_kernel<<<(nw4 + 255) / 256, 256>>>(wv, wt_ptr + (size_t)2 * D * D, nw4);
    bias_expand_kernel<<<(S * S + 255) / 256, 256>>>(bt, ri);

    qkv_mma_kernel<<<dim3((M_TOT + 127) / 128, 2304 / 128), 256, SMEM_QKV_BYTES>>>(bq, bv);
    flash_kernel<<<dim3(2, B * H), 256, SMEM_FLASH_BYTES>>>(out);
}

// round 6
// speedup vs baseline: 3.3132x; 1.0051x over previous
#include <cuda_runtime.h>
#include <math.h>
#include <cstdint>

#define B 64
#define S 197
#define D 768
#define H 12
#define HD 64
#define M_TOT (B * S)          // 12608
#define NUM_REL 732

// -------- device scratch --------
__device__ uint32_t g_xt[(size_t)M_TOT * D];        // X in tf32
__device__ uint32_t g_wt[(size_t)3 * D * D];        // wq|wk|wv in tf32
__device__ uint32_t g_q[(size_t)B * H * S * HD];    // tf32
__device__ uint32_t g_k[(size_t)B * H * S * HD];    // tf32
__device__ uint32_t g_v[(size_t)B * H * S * HD];    // tf32
__device__ float g_bias[(size_t)H * S * S];         // 1.86 MB, L2-resident

__device__ __forceinline__ uint32_t f2tf32(float x) {
    uint32_t u;
    asm("cvt.rna.tf32.f32 %0, %1;" : "=r"(u) : "f"(x));
    return u;
}

__device__ __forceinline__ void mma_tf32(float* d, const uint32_t* a, const uint32_t* b) {
    asm volatile(
        "mma.sync.aligned.m16n8k8.row.col.f32.tf32.tf32.f32 "
        "{%0,%1,%2,%3}, {%4,%5,%6,%7}, {%8,%9}, {%0,%1,%2,%3};"
        : "+f"(d[0]), "+f"(d[1]), "+f"(d[2]), "+f"(d[3])
        : "r"(a[0]), "r"(a[1]), "r"(a[2]), "r"(a[3]), "r"(b[0]), "r"(b[1]));
}

__device__ __forceinline__ uint32_t smem_u32(const void* p) {
    uint32_t a;
    asm("{ .reg .u64 t; cvta.to.shared.u64 t, %1; cvt.u32.u64 %0, t; }" : "=r"(a) : "l"(p));
    return a;
}

__device__ __forceinline__ void cp16(uint32_t dst, const void* src, bool pred) {
    const int sz = pred ? 16 : 0;
    asm volatile("cp.async.cg.shared.global [%0], [%1], 16, %2;"
                 :: "r"(dst), "l"(src), "r"(sz) : "memory");
}
#define CP_COMMIT() asm volatile("cp.async.commit_group;" ::: "memory")
#define CP_WAIT1()  asm volatile("cp.async.wait_group 1;" ::: "memory")
#define CP_WAIT0()  asm volatile("cp.async.wait_group 0;" ::: "memory")

// ============================================================================
// Kernel 0a: fp32 -> tf32 bulk convert (X).
// ============================================================================
__global__ __launch_bounds__(256) void cvt_kernel(
    const float* __restrict__ src, uint32_t* __restrict__ dst, int n4)
{
    const int i = blockIdx.x * 256 + threadIdx.x;
    if (i >= n4) return;
    const float4 v = ((const float4*)src)[i];
    ((uint4*)dst)[i] = make_uint4(f2tf32(v.x), f2tf32(v.y), f2tf32(v.z), f2tf32(v.w));
}

// ============================================================================
// Kernel 0b: fused weight convert (wq|wk|wv -> g_wt).
// ============================================================================
__global__ __launch_bounds__(256) void cvt_w_kernel(
    const float* __restrict__ wq, const float* __restrict__ wk,
    const float* __restrict__ wv, uint32_t* __restrict__ dst)
{
    const int nw4 = D * D / 4;
    const int i = blockIdx.x * 256 + threadIdx.x;
    if (i >= 3 * nw4) return;
    const float* src;
    int j;
    if (i < nw4)           { src = wq; j = i; }
    else if (i < 2 * nw4)  { src = wk; j = i - nw4; }
    else                   { src = wv; j = i - 2 * nw4; }
    const float4 v = ((const float4*)src)[j];
    ((uint4*)dst)[i] = make_uint4(f2tf32(v.x), f2tf32(v.y), f2tf32(v.z), f2tf32(v.w));
}

// ============================================================================
// Kernel 1: QKV projection. TF32 mma.sync, 512 threads, tile 128x256x32,
// 16 warps (2m x 8n), warp tile 64x32, 3-stage cp.async. Zero CVT in loop.
// ============================================================================
#define APITCH 36
#define A_U32 (128 * APITCH)                    // 4608
#define B_U32 (256 * APITCH)                    // 9216
#define STAGE_U32 (A_U32 + B_U32)               // 13824
#define STAGE_BYTES (STAGE_U32 * 4)             // 55296
#define SMEM_QKV_BYTES (3 * STAGE_BYTES)        // 165888
#define NCHUNK 24

__global__ __launch_bounds__(512, 1) void qkv_mma_kernel(
    const float* __restrict__ bq, const float* __restrict__ bv)
{
    extern __shared__ uint32_t smq[];
    const uint32_t sbase = smem_u32(smq);

    const int tid  = threadIdx.x;
    const int wid  = tid >> 5;
    const int lane = tid & 31;
    const int g    = lane >> 2;
    const int t    = lane & 3;
    const int wm   = wid & 1;                   // 0..1
    const int wn   = wid >> 1;                  // 0..7

    const int m0  = blockIdx.x * 128;
    const int n0g = blockIdx.y * 256;
    const int proj = n0g / 768;                 // 0=q 1=k 2=v
    const int n0   = n0g - proj * 768;

    const float* bias = (proj == 0) ? bq : ((proj == 2) ? bv : nullptr);
    uint32_t* dst     = (proj == 0) ? g_q : ((proj == 1) ? g_k : g_v);

    const int lrow = tid >> 3;                  // 0..63
    const int lcg  = tid & 7;                   // 0..7

    auto issue = [&](int c, int s) {
        const int k0 = c * 32;
        const uint32_t smA = sbase + s * STAGE_BYTES;
        const uint32_t smB = smA + A_U32 * 4;
#pragma unroll
        for (int i = 0; i < 2; ++i) {           // A: 128 rows
            const int row = lrow + i * 64;
            const int m = m0 + row;
            const bool pa = m < M_TOT;
            const uint32_t* srcA = g_xt + (size_t)(pa ? m : 0) * 768 + k0 + lcg * 4;
            cp16(smA + (row * APITCH + lcg * 4) * 4, srcA, pa);
        }
#pragma unroll
        for (int i = 0; i < 4; ++i) {           // B: 256 rows
            const int row = lrow + i * 64;
            const uint32_t* srcB = g_wt + (size_t)(n0g + row) * 768 + k0 + lcg * 4;
            cp16(smB + (row * APITCH + lcg * 4) * 4, srcB, true);
        }
        CP_COMMIT();
    };

    issue(0, 0);
    issue(1, 1);

    float acc[4][4][4];
#pragma unroll
    for (int mt = 0; mt < 4; ++mt)
#pragma unroll
        for (int nt = 0; nt < 4; ++nt)
#pragma unroll
            for (int e = 0; e < 4; ++e) acc[mt][nt][e] = 0.f;

    for (int c = 0; c < NCHUNK; ++c) {
        CP_WAIT1();
        __syncthreads();

        const uint32_t* Au = smq + (c % 3) * STAGE_U32;
        const uint32_t* Bu = Au + A_U32;
#pragma unroll
        for (int ks = 0; ks < 4; ++ks) {
            uint32_t af[4][4], bf[4][2];
#pragma unroll
            for (int mt = 0; mt < 4; ++mt) {
                const int r0 = wm * 64 + mt * 16 + g;
                af[mt][0] = Au[r0 * APITCH + ks * 8 + t];
                af[mt][1] = Au[(r0 + 8) * APITCH + ks * 8 + t];
                af[mt][2] = Au[r0 * APITCH + ks * 8 + t + 4];
                af[mt][3] = Au[(r0 + 8) * APITCH + ks * 8 + t + 4];
            }
#pragma unroll
            for (int nt = 0; nt < 4; ++nt) {
                const int c0 = wn * 32 + nt * 8 + g;
                bf[nt][0] = Bu[c0 * APITCH + ks * 8 + t];
                bf[nt][1] = Bu[c0 * APITCH + ks * 8 + t + 4];
            }
#pragma unroll
            for (int mt = 0; mt < 4; ++mt)
#pragma unroll
                for (int nt = 0; nt < 4; ++nt)
                    mma_tf32(acc[mt][nt], af[mt], bf[nt]);
        }
        __syncthreads();

        if (c + 2 < NCHUNK) issue(c + 2, (c + 2) % 3);
    }

    // ---- epilogue: bias + scale, tf32 store into [B,H,S,HD] ----
    const float scale = (proj == 0) ? 0.125f : 1.0f;
#pragma unroll
    for (int mt = 0; mt < 4; ++mt) {
        const int r0 = m0 + wm * 64 + mt * 16 + g;
#pragma unroll
        for (int nt = 0; nt < 4; ++nt) {
            const int n = n0 + wn * 32 + nt * 8 + t * 2;
            const int hh = n >> 6;
            const int hd = n & 63;
            float bx = 0.f, by = 0.f;
            if (bias) { bx = bias[n]; by = bias[n + 1]; }
#pragma unroll
            for (int half = 0; half < 2; ++half) {
                const int m = r0 + half * 8;
                if (m >= M_TOT) continue;
                const int bb = m / S;
                const int ss = m - bb * S;
                uint2 v;
                v.x = f2tf32((acc[mt][nt][half * 2 + 0] + bx) * scale);
                v.y = f2tf32((acc[mt][nt][half * 2 + 1] + by) * scale);
                *(uint2*)(dst + (((size_t)bb * H + hh) * S + ss) * HD + hd) = v;
            }
        }
    }
}

// ============================================================================
// Kernel 2: expand relative-position bias to g_bias[h][q][k].
// ============================================================================
__global__ __launch_bounds__(256) void bias_expand_kernel(
    const float* __restrict__ bias_table, const int* __restrict__ rel_index)
{
    const int i = blockIdx.x * 256 + threadIdx.x;
    if (i >= S * S) return;
    const int r = rel_index[i];
#pragma unroll
    for (int h = 0; h < H; ++h)
        g_bias[(size_t)h * S * S + i] = bias_table[r * H + h];
}

// ============================================================================
// Kernel 3: fused flash attention with double-buffered cp.async K/V.
// smem: K0|V0|K1|V1 (each 128x72 u32) then P (128x136 u32). 217 KB.
// ============================================================================
#define PKV 72
#define PPP 136
#define KVBUF (128 * PKV)                       // 9216 u32 per tensor
#define SP_OFF (4 * KVBUF)
#define SMEM_FLASH_BYTES ((4 * KVBUF + 128 * PPP) * 4)   // 217088

__global__ __launch_bounds__(256, 1) void flash_kernel(float* __restrict__ out)
{
    extern __shared__ uint32_t smu[];
    const uint32_t sbase = smem_u32(smu);

    const int tid  = threadIdx.x;
    const int wid  = tid >> 5;
    const int lane = tid & 31;
    const int g    = lane >> 2;
    const int t    = lane & 3;

    const int qt = blockIdx.x;
    const int bh = blockIdx.y;
    const int b  = bh / H;
    const int h  = bh - b * H;
    const int qbase = qt * 128;
    const int wrow  = wid * 16;

    const uint32_t* Qg = g_q + (size_t)bh * S * HD;
    const uint32_t* Kg = g_k + (size_t)bh * S * HD;
    const uint32_t* Vg = g_v + (size_t)bh * S * HD;

    // ---- issue both K/V tiles up front (one group per tile) ----
#pragma unroll
    for (int kt = 0; kt < 2; ++kt) {
        const int kb = kt * 128;
        const uint32_t smK = sbase + (2 * kt) * KVBUF * 4;
        const uint32_t smV = sbase + (2 * kt + 1) * KVBUF * 4;
#pragma unroll
        for (int it = 0; it < 2; ++it) {
            const int f = tid + it * 256;       // 512 uint4 per tensor
            const int row = f >> 2, cg = f & 3; // 128 rows x 4 uint4
            const int kk = kb + row;
            const bool p = kk < S;
            const uint32_t* sK = Kg + (size_t)(p ? kk : 0) * HD + cg * 16;
            const uint32_t* sV = Vg + (size_t)(p ? kk : 0) * HD + cg * 16;
#pragma unroll
            for (int q4 = 0; q4 < 4; ++q4) {
                cp16(smK + (row * PKV + cg * 16 + q4 * 4) * 4, sK + q4 * 4, p);
                cp16(smV + (row * PKV + cg * 16 + q4 * 4) * 4, sV + q4 * 4, p);
            }
        }
        CP_COMMIT();
    }

    // ---- stage Q tile into sP region (overlaps with cp.async) ----
    {
        uint32_t* sQ = smu + SP_OFF;
#pragma unroll
        for (int it = 0; it < 8; ++it) {
            const int f = tid + it * 256;
            const int row = f >> 4, cg = f & 15;
            const int m = qbase + row;
            uint4 u = make_uint4(0u, 0u, 0u, 0u);
            if (m < S) u = *(const uint4*)(Qg + (size_t)m * HD + cg * 4);
            *(uint4*)(sQ + row * PKV + cg * 4) = u;
        }
    }
    __syncthreads();

    uint32_t qf[8][4];
    {
        const uint32_t* sQ = smu + SP_OFF;
#pragma unroll
        for (int ks = 0; ks < 8; ++ks) {
            qf[ks][0] = sQ[(wrow + g) * PKV + ks * 8 + t];
            qf[ks][1] = sQ[(wrow + g + 8) * PKV + ks * 8 + t];
            qf[ks][2] = sQ[(wrow + g) * PKV + ks * 8 + t + 4];
            qf[ks][3] = sQ[(wrow + g + 8) * PKV + ks * 8 + t + 4];
        }
    }
    __syncthreads();    // sP region now free for P

    const int qr0 = qbase + wrow + g;
    const int qr1 = qr0 + 8;
    const float* brow0 = g_bias + ((size_t)h * S + min(qr0, S - 1)) * S;
    const float* brow1 = g_bias + ((size_t)h * S + min(qr1, S - 1)) * S;

    float m0r = -1e30f, m1r = -1e30f, l0 = 0.f, l1 = 0.f;
    float o[8][4];
#pragma unroll
    for (int j = 0; j < 8; ++j)
#pragma unroll
        for (int e = 0; e < 4; ++e) o[j][e] = 0.f;

#pragma unroll
    for (int kt = 0; kt < 2; ++kt) {
        const int kb = kt * 128;
        if (kt == 0) { CP_WAIT1(); } else { CP_WAIT0(); }
        __syncthreads();

        const uint32_t* sK = smu + (2 * kt) * KVBUF;
        const uint32_t* sV = smu + (2 * kt + 1) * KVBUF;

        float sacc[16][4];
#pragma unroll
        for (int j = 0; j < 16; ++j)
#pragma unroll
            for (int e = 0; e < 4; ++e) sacc[j][e] = 0.f;

#pragma unroll
        for (int ks = 0; ks < 8; ++ks) {
#pragma unroll
            for (int j = 0; j < 16; ++j) {
                uint32_t bf[2];
                bf[0] = sK[(j * 8 + g) * PKV + ks * 8 + t];
                bf[1] = sK[(j * 8 + g) * PKV + ks * 8 + t + 4];
                mma_tf32(sacc[j], qf[ks], bf);
            }
        }

#pragma unroll
        for (int j = 0; j < 16; ++j) {
            const int kc = kb + j * 8 + 2 * t;
            if (kc < S)     sacc[j][0] += brow0[kc];     else sacc[j][0] = -1e30f;
            if (kc + 1 < S) sacc[j][1] += brow0[kc + 1]; else sacc[j][1] = -1e30f;
            if (kc < S)     sacc[j][2] += brow1[kc];     else sacc[j][2] = -1e30f;
            if (kc + 1 < S) sacc[j][3] += brow1[kc + 1]; else sacc[j][3] = -1e30f;
        }

        float mx0 = -1e30f, mx1 = -1e30f;
#pragma unroll
        for (int j = 0; j < 16; ++j) {
            mx0 = fmaxf(mx0, fmaxf(sacc[j][0], sacc[j][1]));
            mx1 = fmaxf(mx1, fmaxf(sacc[j][2], sacc[j][3]));
        }
        mx0 = fmaxf(mx0, __shfl_xor_sync(0xffffffffu, mx0, 1));
        mx0 = fmaxf(mx0, __shfl_xor_sync(0xffffffffu, mx0, 2));
        mx1 = fmaxf(mx1, __shfl_xor_sync(0xffffffffu, mx1, 1));
        mx1 = fmaxf(mx1, __shfl_xor_sync(0xffffffffu, mx1, 2));

        const float nm0 = fmaxf(m0r, mx0);
        const float nm1 = fmaxf(m1r, mx1);
        const float sc0 = __expf(m0r - nm0);
        const float sc1 = __expf(m1r - nm1);
        m0r = nm0; m1r = nm1;

        float sum0 = 0.f, sum1 = 0.f;
        uint32_t* sP = smu + SP_OFF;
#pragma unroll
        for (int j = 0; j < 16; ++j) {
            const float p0 = __expf(sacc[j][0] - nm0);
            const float p1 = __expf(sacc[j][1] - nm0);
            const float p2 = __expf(sacc[j][2] - nm1);
            const float p3 = __expf(sacc[j][3] - nm1);
            sum0 += p0 + p1; sum1 += p2 + p3;
            const int col = j * 8 + 2 * t;
            sP[(wrow + g) * PPP + col]     = f2tf32(p0);
            sP[(wrow + g) * PPP + col + 1] = f2tf32(p1);
            sP[(wrow + g + 8) * PPP + col]     = f2tf32(p2);
            sP[(wrow + g + 8) * PPP + col + 1] = f2tf32(p3);
        }
        sum0 += __shfl_xor_sync(0xffffffffu, sum0, 1);
        sum0 += __shfl_xor_sync(0xffffffffu, sum0, 2);
        sum1 += __shfl_xor_sync(0xffffffffu, sum1, 1);
        sum1 += __shfl_xor_sync(0xffffffffu, sum1, 2);
        l0 = l0 * sc0 + sum0;
        l1 = l1 * sc1 + sum1;

#pragma unroll
        for (int j = 0; j < 8; ++j) {
            o[j][0] *= sc0; o[j][1] *= sc0;
            o[j][2] *= sc1; o[j][3] *= sc1;
        }
        __syncwarp();

#pragma unroll
        for (int ks = 0; ks < 16; ++ks) {
            uint32_t af[4];
            af[0] = sP[(wrow + g) * PPP + ks * 8 + t];
            af[1] = sP[(wrow + g + 8) * PPP + ks * 8 + t];
            af[2] = sP[(wrow + g) * PPP + ks * 8 + t + 4];
            af[3] = sP[(wrow + g + 8) * PPP + ks * 8 + t + 4];
#pragma unroll
            for (int j = 0; j < 8; ++j) {
                uint32_t bf[2];
                bf[0] = sV[(ks * 8 + t) * PKV + j * 8 + g];
                bf[1] = sV[(ks * 8 + t + 4) * PKV + j * 8 + g];
                mma_tf32(o[j], af, bf);
            }
        }
        __syncwarp();   // protect sP WAR before next tile's stores
    }

    const float inv0 = 1.f / l0;
    const float inv1 = 1.f / l1;
#pragma unroll
    for (int j = 0; j < 8; ++j) {
        const int col = h * HD + j * 8 + 2 * t;
        if (qr0 < S) {
            float2 v; v.x = o[j][0] * inv0; v.y = o[j][1] * inv0;
            *(float2*)(out + ((size_t)b * S + qr0) * D + col) = v;
        }
        if (qr1 < S) {
            float2 v; v.x = o[j][2] * inv1; v.y = o[j][3] * inv1;
            *(float2*)(out + ((size_t)b * S + qr1) * D + col) = v;
        }
    }
}

// ============================================================================
// Launch. Inputs: hidden_states, wq, bq, wk, wv, bv, bias_table, rel_index
// ============================================================================
extern "C" void kernel_launch(void* const* d_in, const int* in_sizes, int n_in,
                              void* d_out, int out_size)
{
    const float* X  = (const float*)d_in[0];
    const float* wq = (const float*)d_in[1];
    const float* bq = (const float*)d_in[2];
    const float* wk = (const float*)d_in[3];
    const float* wv = (const float*)d_in[4];
    const float* bv = (const float*)d_in[5];
    const float* bt = (const float*)d_in[6];
    const int*   ri = (const int*)d_in[7];
    float* out = (float*)d_out;

    (void)in_sizes; (void)n_in; (void)out_size;

    static uint32_t* xt_ptr = nullptr;
    static uint32_t* wt_ptr = nullptr;
    if (!xt_ptr) {
        cudaGetSymbolAddress((void**)&xt_ptr, g_xt);
        cudaGetSymbolAddress((void**)&wt_ptr, g_wt);
        cudaFuncSetAttribute(qkv_mma_kernel, cudaFuncAttributeMaxDynamicSharedMemorySize, SMEM_QKV_BYTES);
        cudaFuncSetAttribute(flash_kernel, cudaFuncAttributeMaxDynamicSharedMemorySize, SMEM_FLASH_BYTES);
    }

    const int nx4 = M_TOT * D / 4;
    const int nw4 = 3 * D * D / 4;
    cvt_kernel<<<(nx4 + 255) / 256, 256>>>(X, xt_ptr, nx4);
    cvt_w_kernel<<<(nw4 + 255) / 256, 256>>>(wq, wk, wv, wt_ptr);
    bias_expand_kernel<<<(S * S + 255) / 256, 256>>>(bt, ri);

    qkv_mma_kernel<<<dim3((M_TOT + 127) / 128, 2304 / 256), 512, SMEM_QKV_BYTES>>>(bq, bv);
    flash_kernel<<<dim3(2, B * H), 256, SMEM_FLASH_BYTES>>>(out);
}

// round 7
// speedup vs baseline: 6.3886x; 1.9283x over previous
#include <cuda_runtime.h>
#include <cuda_fp16.h>
#include <math.h>
#include <cstdint>

#define B 64
#define S 197
#define D 768
#define H 12
#define HD 64
#define M_TOT (B * S)          // 12608
#define NUM_REL 732
#define VT_PITCH 256

// -------- device scratch --------
__device__ __half g_xh[(size_t)M_TOT * D];          // X fp16
__device__ __half g_wh[(size_t)3 * D * D];          // wq|wk|wv fp16
__device__ __half g_qh[(size_t)B * H * S * HD];     // Q fp16 (pre-scaled)
__device__ __half g_kh[(size_t)B * H * S * HD];     // K fp16
__device__ __half g_vt[(size_t)B * H * HD * VT_PITCH]; // V transposed [bh][d][256]
__device__ float g_bias[(size_t)H * S * S];         // fp32, L2-resident

__device__ __forceinline__ void mma_f16(float* d, const uint32_t* a, const uint32_t* b) {
    asm volatile(
        "mma.sync.aligned.m16n8k16.row.col.f32.f16.f16.f32 "
        "{%0,%1,%2,%3}, {%4,%5,%6,%7}, {%8,%9}, {%0,%1,%2,%3};"
        : "+f"(d[0]), "+f"(d[1]), "+f"(d[2]), "+f"(d[3])
        : "r"(a[0]), "r"(a[1]), "r"(a[2]), "r"(a[3]), "r"(b[0]), "r"(b[1]));
}

__device__ __forceinline__ void ldsm_x4(uint32_t& r0, uint32_t& r1, uint32_t& r2, uint32_t& r3,
                                        uint32_t addr) {
    asm volatile("ldmatrix.sync.aligned.m8n8.x4.shared.b16 {%0,%1,%2,%3}, [%4];"
                 : "=r"(r0), "=r"(r1), "=r"(r2), "=r"(r3) : "r"(addr));
}

__device__ __forceinline__ uint32_t smem_u32(const void* p) {
    uint32_t a;
    asm("{ .reg .u64 t; cvta.to.shared.u64 t, %1; cvt.u32.u64 %0, t; }" : "=r"(a) : "l"(p));
    return a;
}

__device__ __forceinline__ void cp16(uint32_t dst, const void* src, bool pred) {
    const int sz = pred ? 16 : 0;
    asm volatile("cp.async.cg.shared.global [%0], [%1], 16, %2;"
                 :: "r"(dst), "l"(src), "r"(sz) : "memory");
}
#define CP_COMMIT() asm volatile("cp.async.commit_group;" ::: "memory")
#define CP_WAIT1()  asm volatile("cp.async.wait_group 1;" ::: "memory")
#define CP_WAIT0()  asm volatile("cp.async.wait_group 0;" ::: "memory")

// ============================================================================
// Kernel 0a: fp32 -> fp16 convert (X), 8 elems/thread.
// ============================================================================
__global__ __launch_bounds__(256) void cvt_x_kernel(
    const float* __restrict__ src, __half* __restrict__ dst, int n8)
{
    const int i = blockIdx.x * 256 + threadIdx.x;
    if (i >= n8) return;
    const float4 a = ((const float4*)src)[2 * i];
    const float4 b = ((const float4*)src)[2 * i + 1];
    __half2 h0 = __floats2half2_rn(a.x, a.y);
    __half2 h1 = __floats2half2_rn(a.z, a.w);
    __half2 h2 = __floats2half2_rn(b.x, b.y);
    __half2 h3 = __floats2half2_rn(b.z, b.w);
    uint4 u;
    u.x = *(uint32_t*)&h0; u.y = *(uint32_t*)&h1;
    u.z = *(uint32_t*)&h2; u.w = *(uint32_t*)&h3;
    ((uint4*)dst)[i] = u;
}

// ============================================================================
// Kernel 0b: fused weight convert (wq|wk|wv -> g_wh).
// ============================================================================
__global__ __launch_bounds__(256) void cvt_w_kernel(
    const float* __restrict__ wq, const float* __restrict__ wk,
    const float* __restrict__ wv, __half* __restrict__ dst)
{
    const int nw8 = D * D / 8;
    const int i = blockIdx.x * 256 + threadIdx.x;
    if (i >= 3 * nw8) return;
    const float* src;
    int j;
    if (i < nw8)          { src = wq; j = i; }
    else if (i < 2 * nw8) { src = wk; j = i - nw8; }
    else                  { src = wv; j = i - 2 * nw8; }
    const float4 a = ((const float4*)src)[2 * j];
    const float4 b = ((const float4*)src)[2 * j + 1];
    __half2 h0 = __floats2half2_rn(a.x, a.y);
    __half2 h1 = __floats2half2_rn(a.z, a.w);
    __half2 h2 = __floats2half2_rn(b.x, b.y);
    __half2 h3 = __floats2half2_rn(b.z, b.w);
    uint4 u;
    u.x = *(uint32_t*)&h0; u.y = *(uint32_t*)&h1;
    u.z = *(uint32_t*)&h2; u.w = *(uint32_t*)&h3;
    ((uint4*)dst)[i] = u;
}

// ============================================================================
// Kernel 0c: zero g_vt tail (k in [192,256)) so flash OOB reads are finite.
// Valid V (k<197) is written afterwards by qkv epilogue.
// ============================================================================
__global__ __launch_bounds__(256) void vt_pad_kernel()
{
    const int i = blockIdx.x * 256 + threadIdx.x;   // over 768*64*16
    if (i >= B * H * HD * 16) return;
    const int row = i >> 4, j = i & 15;
    ((uint2*)(g_vt + (size_t)row * VT_PITCH + 192))[j] = make_uint2(0u, 0u);
}

// ============================================================================
// Kernel 1: QKV projection. FP16 mma m16n8k16, 512 thr, tile 128x256x64,
// 16 warps (2m x 8n), ldmatrix fragment loads, 3-stage cp.async.
// ============================================================================
#define HPITCH 72
#define A_HALVES (128 * HPITCH)                 // 9216
#define B_HALVES (256 * HPITCH)                 // 18432
#define STAGE_HALVES (A_HALVES + B_HALVES)      // 27648
#define STAGE_BYTES (STAGE_HALVES * 2)          // 55296
#define SMEM_QKV_BYTES (3 * STAGE_BYTES)        // 165888
#define NCHUNK 12

__global__ __launch_bounds__(512, 1) void qkv_mma_kernel(
    const float* __restrict__ bq, const float* __restrict__ bv)
{
    extern __shared__ __half smh[];
    const uint32_t sbase = smem_u32(smh);

    const int tid  = threadIdx.x;
    const int lane = tid & 31;
    const int wid  = tid >> 5;
    const int g    = lane >> 2;
    const int t    = lane & 3;
    const int wm   = wid & 1;
    const int wn   = wid >> 1;

    const int m0  = blockIdx.x * 128;
    const int n0g = blockIdx.y * 256;
    const int proj = n0g / 768;                 // 0=q 1=k 2=v
    const int n0   = n0g - proj * 768;

    const float* bias = (proj == 0) ? bq : ((proj == 2) ? bv : nullptr);

    const int lrow = tid >> 3;                  // 0..63
    const int lcg  = tid & 7;                   // 0..7 (16B units of 8 halves)

    auto issue = [&](int c, int s) {
        const int k0 = c * 64;
        const uint32_t smA = sbase + s * STAGE_BYTES;
        const uint32_t smB = smA + A_HALVES * 2;
#pragma unroll
        for (int i = 0; i < 2; ++i) {           // A: 128 rows
            const int row = lrow + i * 64;
            const int m = m0 + row;
            const bool pa = m < M_TOT;
            const __half* srcA = g_xh + (size_t)(pa ? m : 0) * 768 + k0 + lcg * 8;
            cp16(smA + (row * HPITCH + lcg * 8) * 2, srcA, pa);
        }
#pragma unroll
        for (int i = 0; i < 4; ++i) {           // B: 256 rows
            const int row = lrow + i * 64;
            const __half* srcB = g_wh + (size_t)(n0g + row) * 768 + k0 + lcg * 8;
            cp16(smB + (row * HPITCH + lcg * 8) * 2, srcB, true);
        }
        CP_COMMIT();
    };

    issue(0, 0);
    issue(1, 1);

    // ldmatrix lane decode
    const int a_row_l = (lane & 7) + ((lane >> 3) & 1) * 8;
    const int a_col_l = ((lane >> 4) & 1) * 8;
    const int b_row_l = (lane & 7) + ((lane >> 4) & 1) * 8;
    const int b_col_l = ((lane >> 3) & 1) * 8;

    float acc[4][4][4];
#pragma unroll
    for (int mt = 0; mt < 4; ++mt)
#pragma unroll
        for (int nt = 0; nt < 4; ++nt)
#pragma unroll
            for (int e = 0; e < 4; ++e) acc[mt][nt][e] = 0.f;

    for (int c = 0; c < NCHUNK; ++c) {
        CP_WAIT1();
        __syncthreads();

        const uint32_t stA = sbase + (c % 3) * STAGE_BYTES;
        const uint32_t stB = stA + A_HALVES * 2;
#pragma unroll
        for (int ks = 0; ks < 4; ++ks) {
            uint32_t af[4][4], bf[4][2];
#pragma unroll
            for (int mt = 0; mt < 4; ++mt) {
                const uint32_t addr = stA +
                    ((wm * 64 + mt * 16 + a_row_l) * HPITCH + ks * 16 + a_col_l) * 2;
                ldsm_x4(af[mt][0], af[mt][1], af[mt][2], af[mt][3], addr);
            }
#pragma unroll
            for (int ntp = 0; ntp < 2; ++ntp) {
                const uint32_t addr = stB +
                    ((wn * 32 + ntp * 16 + b_row_l) * HPITCH + ks * 16 + b_col_l) * 2;
                ldsm_x4(bf[2 * ntp][0], bf[2 * ntp][1],
                        bf[2 * ntp + 1][0], bf[2 * ntp + 1][1], addr);
            }
#pragma unroll
            for (int mt = 0; mt < 4; ++mt)
#pragma unroll
                for (int nt = 0; nt < 4; ++nt)
                    mma_f16(acc[mt][nt], af[mt], bf[nt]);
        }
        __syncthreads();

        if (c + 2 < NCHUNK) issue(c + 2, (c + 2) % 3);
    }

    // ---- epilogue: bias + scale, fp16 stores ----
    const float scale = (proj == 0) ? 0.125f : 1.0f;
#pragma unroll
    for (int mt = 0; mt < 4; ++mt) {
        const int r0 = m0 + wm * 64 + mt * 16 + g;
#pragma unroll
        for (int nt = 0; nt < 4; ++nt) {
            const int n = n0 + wn * 32 + nt * 8 + t * 2;
            const int hh = n >> 6;
            const int hd = n & 63;
            float bx = 0.f, by = 0.f;
            if (bias) { bx = bias[n]; by = bias[n + 1]; }
#pragma unroll
            for (int half_i = 0; half_i < 2; ++half_i) {
                const int m = r0 + half_i * 8;
                if (m >= M_TOT) continue;
                const int bb = m / S;
                const int ss = m - bb * S;
                const int bh = bb * H + hh;
                const float vx = (acc[mt][nt][half_i * 2 + 0] + bx) * scale;
                const float vy = (acc[mt][nt][half_i * 2 + 1] + by) * scale;
                if (proj == 2) {
                    g_vt[((size_t)bh * HD + hd) * VT_PITCH + ss]     = __float2half_rn(vx);
                    g_vt[((size_t)bh * HD + hd + 1) * VT_PITCH + ss] = __float2half_rn(vy);
                } else {
                    __half2 hv = __floats2half2_rn(vx, vy);
                    __half* dst = (proj == 0) ? g_qh : g_kh;
                    *(__half2*)(dst + ((size_t)bh * S + ss) * HD + hd) = hv;
                }
            }
        }
    }
}

// ============================================================================
// Kernel 2: expand relative-position bias to g_bias[h][q][k].
// ============================================================================
__global__ __launch_bounds__(256) void bias_expand_kernel(
    const float* __restrict__ bias_table, const int* __restrict__ rel_index)
{
    const int i = blockIdx.x * 256 + threadIdx.x;
    if (i >= S * S) return;
    const int r = rel_index[i];
#pragma unroll
    for (int h = 0; h < H; ++h)
        g_bias[(size_t)h * S * S + i] = bias_table[r * H + h];
}

// ============================================================================
// Kernel 3: fused flash attention, FP16 mma. K double-buffered cp.async,
// V pre-transposed. smem 106.5 KB -> 2 CTAs/SM.
// layout (halves): K0 K1 | V0 V1 | P(=Q staging)
// ============================================================================
#define FK_PITCH 72
#define FP_PITCH 136
#define K_HALVES (128 * FK_PITCH)               // 9216
#define V_HALVES (64 * FP_PITCH)                // 8704
#define FV_BASE (2 * K_HALVES)
#define FP_BASE (2 * K_HALVES + 2 * V_HALVES)   // 35840
#define SMEM_FLASH_BYTES ((FP_BASE + 128 * FP_PITCH) * 2)   // 106496

__global__ __launch_bounds__(256, 2) void flash_kernel(float* __restrict__ out)
{
    extern __shared__ __half smh[];
    const uint32_t sbase = smem_u32(smh);

    const int tid  = threadIdx.x;
    const int lane = tid & 31;
    const int wid  = tid >> 5;
    const int g    = lane >> 2;
    const int t    = lane & 3;

    const int qt = blockIdx.x;
    const int bh = blockIdx.y;
    const int b  = bh / H;
    const int h  = bh - b * H;
    const int qbase = qt * 128;
    const int wrow  = wid * 16;

    const __half* Qg = g_qh + (size_t)bh * S * HD;
    const __half* Kg = g_kh + (size_t)bh * S * HD;
    const __half* Vt = g_vt + (size_t)bh * HD * VT_PITCH;

    // ---- issue both K and V tiles (one cp.async group per kt) ----
#pragma unroll
    for (int kt = 0; kt < 2; ++kt) {
        const int kb = kt * 128;
        const uint32_t smK = sbase + kt * K_HALVES * 2;
        const uint32_t smV = sbase + (FV_BASE + kt * V_HALVES) * 2;
#pragma unroll
        for (int it = 0; it < 4; ++it) {        // K: 128 rows x 8 cg
            const int f = tid + it * 256;
            const int row = f >> 3, cg = f & 7;
            const int kk = kb + row;
            const bool p = kk < S;
            cp16(smK + (row * FK_PITCH + cg * 8) * 2,
                 Kg + (size_t)(p ? kk : 0) * HD + cg * 8, p);
        }
#pragma unroll
        for (int it = 0; it < 4; ++it) {        // Vt: 64 rows x 16 cg
            const int f = tid + it * 256;
            const int row = f >> 4, cg = f & 15;
            cp16(smV + (row * FP_PITCH + cg * 8) * 2,
                 Vt + (size_t)row * VT_PITCH + kb + cg * 8, true);
        }
        CP_COMMIT();
    }

    // ---- stage Q into P region ----
    {
        __half* sQ = smh + FP_BASE;
#pragma unroll
        for (int it = 0; it < 4; ++it) {
            const int f = tid + it * 256;       // 128 rows x 8 cg
            const int row = f >> 3, cg = f & 7;
            const int m = qbase + row;
            uint4 u = make_uint4(0u, 0u, 0u, 0u);
            if (m < S) u = *(const uint4*)(Qg + (size_t)m * HD + cg * 8);
            *(uint4*)(sQ + row * FK_PITCH + cg * 8) = u;
        }
    }
    __syncthreads();

    // ---- Q fragments: 4 ks of k16 ----
    uint32_t qf[4][4];
    {
        const __half* sQ = smh + FP_BASE;
#pragma unroll
        for (int ks = 0; ks < 4; ++ks) {
            qf[ks][0] = *(const uint32_t*)(sQ + (wrow + g) * FK_PITCH + ks * 16 + 2 * t);
            qf[ks][1] = *(const uint32_t*)(sQ + (wrow + g + 8) * FK_PITCH + ks * 16 + 2 * t);
            qf[ks][2] = *(const uint32_t*)(sQ + (wrow + g) * FK_PITCH + ks * 16 + 8 + 2 * t);
            qf[ks][3] = *(const uint32_t*)(sQ + (wrow + g + 8) * FK_PITCH + ks * 16 + 8 + 2 * t);
        }
    }
    __syncthreads();    // P region free

    const int qr0 = qbase + wrow + g;
    const int qr1 = qr0 + 8;
    const float* brow0 = g_bias + ((size_t)h * S + min(qr0, S - 1)) * S;
    const float* brow1 = g_bias + ((size_t)h * S + min(qr1, S - 1)) * S;

    float m0r = -1e30f, m1r = -1e30f, l0 = 0.f, l1 = 0.f;
    float o[8][4];
#pragma unroll
    for (int j = 0; j < 8; ++j)
#pragma unroll
        for (int e = 0; e < 4; ++e) o[j][e] = 0.f;

#pragma unroll
    for (int kt = 0; kt < 2; ++kt) {
        const int kb = kt * 128;
        if (kt == 0) { CP_WAIT1(); } else { CP_WAIT0(); }
        __syncthreads();

        const __half* sK = smh + kt * K_HALVES;
        const __half* sV = smh + FV_BASE + kt * V_HALVES;

        float sacc[16][4];
#pragma unroll
        for (int j = 0; j < 16; ++j)
#pragma unroll
            for (int e = 0; e < 4; ++e) sacc[j][e] = 0.f;

#pragma unroll
        for (int ks = 0; ks < 4; ++ks) {
#pragma unroll
            for (int j = 0; j < 16; ++j) {
                uint32_t bf[2];
                bf[0] = *(const uint32_t*)(sK + (j * 8 + g) * FK_PITCH + ks * 16 + 2 * t);
                bf[1] = *(const uint32_t*)(sK + (j * 8 + g) * FK_PITCH + ks * 16 + 8 + 2 * t);
                mma_f16(sacc[j], qf[ks], bf);
            }
        }

#pragma unroll
        for (int j = 0; j < 16; ++j) {
            const int kc = kb + j * 8 + 2 * t;
            if (kc < S)     sacc[j][0] += brow0[kc];     else sacc[j][0] = -1e30f;
            if (kc + 1 < S) sacc[j][1] += brow0[kc + 1]; else sacc[j][1] = -1e30f;
            if (kc < S)     sacc[j][2] += brow1[kc];     else sacc[j][2] = -1e30f;
            if (kc + 1 < S) sacc[j][3] += brow1[kc + 1]; else sacc[j][3] = -1e30f;
        }

        float mx0 = -1e30f, mx1 = -1e30f;
#pragma unroll
        for (int j = 0; j < 16; ++j) {
            mx0 = fmaxf(mx0, fmaxf(sacc[j][0], sacc[j][1]));
            mx1 = fmaxf(mx1, fmaxf(sacc[j][2], sacc[j][3]));
        }
        mx0 = fmaxf(mx0, __shfl_xor_sync(0xffffffffu, mx0, 1));
        mx0 = fmaxf(mx0, __shfl_xor_sync(0xffffffffu, mx0, 2));
        mx1 = fmaxf(mx1, __shfl_xor_sync(0xffffffffu, mx1, 1));
        mx1 = fmaxf(mx1, __shfl_xor_sync(0xffffffffu, mx1, 2));

        const float nm0 = fmaxf(m0r, mx0);
        const float nm1 = fmaxf(m1r, mx1);
        const float sc0 = __expf(m0r - nm0);
        const float sc1 = __expf(m1r - nm1);
        m0r = nm0; m1r = nm1;

        float sum0 = 0.f, sum1 = 0.f;
        __half* sP = smh + FP_BASE;
#pragma unroll
        for (int j = 0; j < 16; ++j) {
            const float p0 = __expf(sacc[j][0] - nm0);
            const float p1 = __expf(sacc[j][1] - nm0);
            const float p2 = __expf(sacc[j][2] - nm1);
            const float p3 = __expf(sacc[j][3] - nm1);
            sum0 += p0 + p1; sum1 += p2 + p3;
            const int col = j * 8 + 2 * t;
            *(__half2*)(sP + (wrow + g) * FP_PITCH + col)     = __floats2half2_rn(p0, p1);
            *(__half2*)(sP + (wrow + g + 8) * FP_PITCH + col) = __floats2half2_rn(p2, p3);
        }
        sum0 += __shfl_xor_sync(0xffffffffu, sum0, 1);
        sum0 += __shfl_xor_sync(0xffffffffu, sum0, 2);
        sum1 += __shfl_xor_sync(0xffffffffu, sum1, 1);
        sum1 += __shfl_xor_sync(0xffffffffu, sum1, 2);
        l0 = l0 * sc0 + sum0;
        l1 = l1 * sc1 + sum1;

#pragma unroll
        for (int j = 0; j < 8; ++j) {
            o[j][0] *= sc0; o[j][1] *= sc0;
            o[j][2] *= sc1; o[j][3] *= sc1;
        }
        __syncwarp();

        // ---- O += P V : 8 ks of k16 ----
#pragma unroll
        for (int ks = 0; ks < 8; ++ks) {
            uint32_t af[4];
            af[0] = *(const uint32_t*)(sP + (wrow + g) * FP_PITCH + ks * 16 + 2 * t);
            af[1] = *(const uint32_t*)(sP + (wrow + g + 8) * FP_PITCH + ks * 16 + 2 * t);
            af[2] = *(const uint32_t*)(sP + (wrow + g) * FP_PITCH + ks * 16 + 8 + 2 * t);
            af[3] = *(const uint32_t*)(sP + (wrow + g + 8) * FP_PITCH + ks * 16 + 8 + 2 * t);
#pragma unroll
            for (int j = 0; j < 8; ++j) {
                uint32_t bf[2];
                bf[0] = *(const uint32_t*)(sV + (j * 8 + g) * FP_PITCH + ks * 16 + 2 * t);
                bf[1] = *(const uint32_t*)(sV + (j * 8 + g) * FP_PITCH + ks * 16 + 8 + 2 * t);
                mma_f16(o[j], af, bf);
            }
        }
        __syncwarp();   // warp-private sP rows: WAR guard before next tile
    }

    const float inv0 = 1.f / l0;
    const float inv1 = 1.f / l1;
#pragma unroll
    for (int j = 0; j < 8; ++j) {
        const int col = h * HD + j * 8 + 2 * t;
        if (qr0 < S) {
            float2 v; v.x = o[j][0] * inv0; v.y = o[j][1] * inv0;
            *(float2*)(out + ((size_t)b * S + qr0) * D + col) = v;
        }
        if (qr1 < S) {
            float2 v; v.x = o[j][2] * inv1; v.y = o[j][3] * inv1;
            *(float2*)(out + ((size_t)b * S + qr1) * D + col) = v;
        }
    }
}

// ============================================================================
// Launch. Inputs: hidden_states, wq, bq, wk, wv, bv, bias_table, rel_index
// ============================================================================
extern "C" void kernel_launch(void* const* d_in, const int* in_sizes, int n_in,
                              void* d_out, int out_size)
{
    const float* X  = (const float*)d_in[0];
    const float* wq = (const float*)d_in[1];
    const float* bq = (const float*)d_in[2];
    const float* wk = (const float*)d_in[3];
    const float* wv = (const float*)d_in[4];
    const float* bv = (const float*)d_in[5];
    const float* bt = (const float*)d_in[6];
    const int*   ri = (const int*)d_in[7];
    float* out = (float*)d_out;

    (void)in_sizes; (void)n_in; (void)out_size;

    static __half* xh_ptr = nullptr;
    static __half* wh_ptr = nullptr;
    if (!xh_ptr) {
        cudaGetSymbolAddress((void**)&xh_ptr, g_xh);
        cudaGetSymbolAddress((void**)&wh_ptr, g_wh);
        cudaFuncSetAttribute(qkv_mma_kernel, cudaFuncAttributeMaxDynamicSharedMemorySize, SMEM_QKV_BYTES);
        cudaFuncSetAttribute(flash_kernel, cudaFuncAttributeMaxDynamicSharedMemorySize, SMEM_FLASH_BYTES);
    }

    const int nx8 = M_TOT * D / 8;              // 1210368
    const int nw8 = 3 * D * D / 8;              // 221184
    cvt_x_kernel<<<(nx8 + 255) / 256, 256>>>(X, xh_ptr, nx8);
    cvt_w_kernel<<<(nw8 + 255) / 256, 256>>>(wq, wk, wv, wh_ptr);
    vt_pad_kernel<<<(B * H * HD * 16 + 255) / 256, 256>>>();
    bias_expand_kernel<<<(S * S + 255) / 256, 256>>>(bt, ri);

    qkv_mma_kernel<<<dim3((M_TOT + 127) / 128, 2304 / 256), 512, SMEM_QKV_BYTES>>>(bq, bv);
    flash_kernel<<<dim3(2, B * H), 256, SMEM_FLASH_BYTES>>>(out);
}

// round 8
// speedup vs baseline: 6.4798x; 1.0143x over previous
#include <cuda_runtime.h>
#include <cuda_fp16.h>
#include <math.h>
#include <cstdint>

#define B 64
#define S 197
#define D 768
#define H 12
#define HD 64
#define M_TOT (B * S)          // 12608
#define NUM_REL 732
#define VT_PITCH 256

// -------- device scratch --------
__device__ __half g_xh[(size_t)M_TOT * D];          // X fp16
__device__ __half g_wh[(size_t)3 * D * D];          // wq|wk|wv fp16
__device__ __half g_qh[(size_t)B * H * S * HD];     // Q fp16 (pre-scaled)
__device__ __half g_kh[(size_t)B * H * S * HD];     // K fp16
__device__ __half g_vt[(size_t)B * H * HD * VT_PITCH]; // V transposed [bh][d][256]
__device__ float g_bias[(size_t)H * S * S];         // fp32, L2-resident

__device__ __forceinline__ void mma_f16(float* d, const uint32_t* a, const uint32_t* b) {
    asm volatile(
        "mma.sync.aligned.m16n8k16.row.col.f32.f16.f16.f32 "
        "{%0,%1,%2,%3}, {%4,%5,%6,%7}, {%8,%9}, {%0,%1,%2,%3};"
        : "+f"(d[0]), "+f"(d[1]), "+f"(d[2]), "+f"(d[3])
        : "r"(a[0]), "r"(a[1]), "r"(a[2]), "r"(a[3]), "r"(b[0]), "r"(b[1]));
}

__device__ __forceinline__ void ldsm_x4(uint32_t& r0, uint32_t& r1, uint32_t& r2, uint32_t& r3,
                                        uint32_t addr) {
    asm volatile("ldmatrix.sync.aligned.m8n8.x4.shared.b16 {%0,%1,%2,%3}, [%4];"
                 : "=r"(r0), "=r"(r1), "=r"(r2), "=r"(r3) : "r"(addr));
}

__device__ __forceinline__ uint32_t smem_u32(const void* p) {
    uint32_t a;
    asm("{ .reg .u64 t; cvta.to.shared.u64 t, %1; cvt.u32.u64 %0, t; }" : "=r"(a) : "l"(p));
    return a;
}

__device__ __forceinline__ void cp16(uint32_t dst, const void* src, bool pred) {
    const int sz = pred ? 16 : 0;
    asm volatile("cp.async.cg.shared.global [%0], [%1], 16, %2;"
                 :: "r"(dst), "l"(src), "r"(sz) : "memory");
}
#define CP_COMMIT() asm volatile("cp.async.commit_group;" ::: "memory")
#define CP_WAIT1()  asm volatile("cp.async.wait_group 1;" ::: "memory")
#define CP_WAIT0()  asm volatile("cp.async.wait_group 0;" ::: "memory")

// ============================================================================
// Kernel 0a: fp32 -> fp16 convert (X), 8 elems/thread.
// ============================================================================
__global__ __launch_bounds__(256) void cvt_x_kernel(
    const float* __restrict__ src, __half* __restrict__ dst, int n8)
{
    const int i = blockIdx.x * 256 + threadIdx.x;
    if (i >= n8) return;
    const float4 a = ((const float4*)src)[2 * i];
    const float4 b = ((const float4*)src)[2 * i + 1];
    __half2 h0 = __floats2half2_rn(a.x, a.y);
    __half2 h1 = __floats2half2_rn(a.z, a.w);
    __half2 h2 = __floats2half2_rn(b.x, b.y);
    __half2 h3 = __floats2half2_rn(b.z, b.w);
    uint4 u;
    u.x = *(uint32_t*)&h0; u.y = *(uint32_t*)&h1;
    u.z = *(uint32_t*)&h2; u.w = *(uint32_t*)&h3;
    ((uint4*)dst)[i] = u;
}

// ============================================================================
// Kernel 0b: fused weight convert (wq|wk|wv -> g_wh).
// ============================================================================
__global__ __launch_bounds__(256) void cvt_w_kernel(
    const float* __restrict__ wq, const float* __restrict__ wk,
    const float* __restrict__ wv, __half* __restrict__ dst)
{
    const int nw8 = D * D / 8;
    const int i = blockIdx.x * 256 + threadIdx.x;
    if (i >= 3 * nw8) return;
    const float* src;
    int j;
    if (i < nw8)          { src = wq; j = i; }
    else if (i < 2 * nw8) { src = wk; j = i - nw8; }
    else                  { src = wv; j = i - 2 * nw8; }
    const float4 a = ((const float4*)src)[2 * j];
    const float4 b = ((const float4*)src)[2 * j + 1];
    __half2 h0 = __floats2half2_rn(a.x, a.y);
    __half2 h1 = __floats2half2_rn(a.z, a.w);
    __half2 h2 = __floats2half2_rn(b.x, b.y);
    __half2 h3 = __floats2half2_rn(b.z, b.w);
    uint4 u;
    u.x = *(uint32_t*)&h0; u.y = *(uint32_t*)&h1;
    u.z = *(uint32_t*)&h2; u.w = *(uint32_t*)&h3;
    ((uint4*)dst)[i] = u;
}

// ============================================================================
// Kernel 0c: zero g_vt tail (k in [192,256)). Must run BEFORE qkv (valid
// rows 192..196 are rewritten by the qkv epilogue afterwards).
// ============================================================================
__global__ __launch_bounds__(256) void vt_pad_kernel()
{
    const int i = blockIdx.x * 256 + threadIdx.x;
    if (i >= B * H * HD * 16) return;
    const int row = i >> 4, j = i & 15;
    ((uint2*)(g_vt + (size_t)row * VT_PITCH + 192))[j] = make_uint2(0u, 0u);
}

// ============================================================================
// Kernel 1: QKV projection. FP16 mma m16n8k16, 512 thr, tile 128x256x64,
// 16 warps (2m x 8n), ldmatrix, 3-stage cp.async, ONE barrier per chunk.
// ============================================================================
#define HPITCH 72
#define A_HALVES (128 * HPITCH)
#define B_HALVES (256 * HPITCH)
#define STAGE_HALVES (A_HALVES + B_HALVES)
#define STAGE_BYTES (STAGE_HALVES * 2)          // 55296
#define SMEM_QKV_BYTES (3 * STAGE_BYTES)        // 165888
#define NCHUNK 12

__global__ __launch_bounds__(512, 1) void qkv_mma_kernel(
    const float* __restrict__ bq, const float* __restrict__ bv)
{
    extern __shared__ __half smh[];
    const uint32_t sbase = smem_u32(smh);

    const int tid  = threadIdx.x;
    const int lane = tid & 31;
    const int wid  = tid >> 5;
    const int g    = lane >> 2;
    const int t    = lane & 3;
    const int wm   = wid & 1;
    const int wn   = wid >> 1;

    const int m0  = blockIdx.x * 128;
    const int n0g = blockIdx.y * 256;
    const int proj = n0g / 768;
    const int n0   = n0g - proj * 768;

    const float* bias = (proj == 0) ? bq : ((proj == 2) ? bv : nullptr);

    const int lrow = tid >> 3;
    const int lcg  = tid & 7;

    auto issue = [&](int c, int s) {
        const int k0 = c * 64;
        const uint32_t smA = sbase + s * STAGE_BYTES;
        const uint32_t smB = smA + A_HALVES * 2;
#pragma unroll
        for (int i = 0; i < 2; ++i) {
            const int row = lrow + i * 64;
            const int m = m0 + row;
            const bool pa = m < M_TOT;
            const __half* srcA = g_xh + (size_t)(pa ? m : 0) * 768 + k0 + lcg * 8;
            cp16(smA + (row * HPITCH + lcg * 8) * 2, srcA, pa);
        }
#pragma unroll
        for (int i = 0; i < 4; ++i) {
            const int row = lrow + i * 64;
            const __half* srcB = g_wh + (size_t)(n0g + row) * 768 + k0 + lcg * 8;
            cp16(smB + (row * HPITCH + lcg * 8) * 2, srcB, true);
        }
        CP_COMMIT();
    };

    issue(0, 0);
    issue(1, 1);

    const int a_row_l = (lane & 7) + ((lane >> 3) & 1) * 8;
    const int a_col_l = ((lane >> 4) & 1) * 8;
    const int b_row_l = (lane & 7) + ((lane >> 4) & 1) * 8;
    const int b_col_l = ((lane >> 3) & 1) * 8;

    float acc[4][4][4];
#pragma unroll
    for (int mt = 0; mt < 4; ++mt)
#pragma unroll
        for (int nt = 0; nt < 4; ++nt)
#pragma unroll
            for (int e = 0; e < 4; ++e) acc[mt][nt][e] = 0.f;

    for (int c = 0; c < NCHUNK; ++c) {
        CP_WAIT1();
        __syncthreads();
        // issue next-next chunk NOW: top barrier proved all warps finished
        // reading slot (c+2)%3 (their iteration c-1 reads). Loads overlap
        // this chunk's compute; no trailing barrier needed.
        if (c + 2 < NCHUNK) issue(c + 2, (c + 2) % 3);

        const uint32_t stA = sbase + (c % 3) * STAGE_BYTES;
        const uint32_t stB = stA + A_HALVES * 2;
#pragma unroll
        for (int ks = 0; ks < 4; ++ks) {
            uint32_t af[4][4], bf[4][2];
#pragma unroll
            for (int mt = 0; mt < 4; ++mt) {
                const uint32_t addr = stA +
                    ((wm * 64 + mt * 16 + a_row_l) * HPITCH + ks * 16 + a_col_l) * 2;
                ldsm_x4(af[mt][0], af[mt][1], af[mt][2], af[mt][3], addr);
            }
#pragma unroll
            for (int ntp = 0; ntp < 2; ++ntp) {
                const uint32_t addr = stB +
                    ((wn * 32 + ntp * 16 + b_row_l) * HPITCH + ks * 16 + b_col_l) * 2;
                ldsm_x4(bf[2 * ntp][0], bf[2 * ntp][1],
                        bf[2 * ntp + 1][0], bf[2 * ntp + 1][1], addr);
            }
#pragma unroll
            for (int mt = 0; mt < 4; ++mt)
#pragma unroll
                for (int nt = 0; nt < 4; ++nt)
                    mma_f16(acc[mt][nt], af[mt], bf[nt]);
        }
    }

    const float scale = (proj == 0) ? 0.125f : 1.0f;
#pragma unroll
    for (int mt = 0; mt < 4; ++mt) {
        const int r0 = m0 + wm * 64 + mt * 16 + g;
#pragma unroll
        for (int nt = 0; nt < 4; ++nt) {
            const int n = n0 + wn * 32 + nt * 8 + t * 2;
            const int hh = n >> 6;
            const int hd = n & 63;
            float bx = 0.f, by = 0.f;
            if (bias) { bx = bias[n]; by = bias[n + 1]; }
#pragma unroll
            for (int half_i = 0; half_i < 2; ++half_i) {
                const int m = r0 + half_i * 8;
                if (m >= M_TOT) continue;
                const int bb = m / S;
                const int ss = m - bb * S;
                const int bh = bb * H + hh;
                const float vx = (acc[mt][nt][half_i * 2 + 0] + bx) * scale;
                const float vy = (acc[mt][nt][half_i * 2 + 1] + by) * scale;
                if (proj == 2) {
                    g_vt[((size_t)bh * HD + hd) * VT_PITCH + ss]     = __float2half_rn(vx);
                    g_vt[((size_t)bh * HD + hd + 1) * VT_PITCH + ss] = __float2half_rn(vy);
                } else {
                    __half2 hv = __floats2half2_rn(vx, vy);
                    __half* dst = (proj == 0) ? g_qh : g_kh;
                    *(__half2*)(dst + ((size_t)bh * S + ss) * HD + hd) = hv;
                }
            }
        }
    }
}

// ============================================================================
// Kernel 2: expand relative-position bias to g_bias[h][q][k].
// ============================================================================
__global__ __launch_bounds__(256) void bias_expand_kernel(
    const float* __restrict__ bias_table, const int* __restrict__ rel_index)
{
    const int i = blockIdx.x * 256 + threadIdx.x;
    if (i >= S * S) return;
    const int r = rel_index[i];
#pragma unroll
    for (int h = 0; h < H; ++h)
        g_bias[(size_t)h * S * S + i] = bias_table[r * H + h];
}

// ============================================================================
// Kernel 3: fused flash attention, FP16 mma (unchanged from R7, passing).
// ============================================================================
#define FK_PITCH 72
#define FP_PITCH 136
#define K_HALVES (128 * FK_PITCH)
#define V_HALVES (64 * FP_PITCH)
#define FV_BASE (2 * K_HALVES)
#define FP_BASE (2 * K_HALVES + 2 * V_HALVES)
#define SMEM_FLASH_BYTES ((FP_BASE + 128 * FP_PITCH) * 2)   // 106496

__global__ __launch_bounds__(256, 2) void flash_kernel(float* __restrict__ out)
{
    extern __shared__ __half smh[];
    const uint32_t sbase = smem_u32(smh);

    const int tid  = threadIdx.x;
    const int lane = tid & 31;
    const int wid  = tid >> 5;
    const int g    = lane >> 2;
    const int t    = lane & 3;

    const int qt = blockIdx.x;
    const int bh = blockIdx.y;
    const int b  = bh / H;
    const int h  = bh - b * H;
    const int qbase = qt * 128;
    const int wrow  = wid * 16;

    const __half* Qg = g_qh + (size_t)bh * S * HD;
    const __half* Kg = g_kh + (size_t)bh * S * HD;
    const __half* Vt = g_vt + (size_t)bh * HD * VT_PITCH;

#pragma unroll
    for (int kt = 0; kt < 2; ++kt) {
        const int kb = kt * 128;
        const uint32_t smK = sbase + kt * K_HALVES * 2;
        const uint32_t smV = sbase + (FV_BASE + kt * V_HALVES) * 2;
#pragma unroll
        for (int it = 0; it < 4; ++it) {
            const int f = tid + it * 256;
            const int row = f >> 3, cg = f & 7;
            const int kk = kb + row;
            const bool p = kk < S;
            cp16(smK + (row * FK_PITCH + cg * 8) * 2,
                 Kg + (size_t)(p ? kk : 0) * HD + cg * 8, p);
        }
#pragma unroll
        for (int it = 0; it < 4; ++it) {
            const int f = tid + it * 256;
            const int row = f >> 4, cg = f & 15;
            cp16(smV + (row * FP_PITCH + cg * 8) * 2,
                 Vt + (size_t)row * VT_PITCH + kb + cg * 8, true);
        }
        CP_COMMIT();
    }

    {
        __half* sQ = smh + FP_BASE;
#pragma unroll
        for (int it = 0; it < 4; ++it) {
            const int f = tid + it * 256;
            const int row = f >> 3, cg = f & 7;
            const int m = qbase + row;
            uint4 u = make_uint4(0u, 0u, 0u, 0u);
            if (m < S) u = *(const uint4*)(Qg + (size_t)m * HD + cg * 8);
            *(uint4*)(sQ + row * FK_PITCH + cg * 8) = u;
        }
    }
    __syncthreads();

    uint32_t qf[4][4];
    {
        const __half* sQ = smh + FP_BASE;
#pragma unroll
        for (int ks = 0; ks < 4; ++ks) {
            qf[ks][0] = *(const uint32_t*)(sQ + (wrow + g) * FK_PITCH + ks * 16 + 2 * t);
            qf[ks][1] = *(const uint32_t*)(sQ + (wrow + g + 8) * FK_PITCH + ks * 16 + 2 * t);
            qf[ks][2] = *(const uint32_t*)(sQ + (wrow + g) * FK_PITCH + ks * 16 + 8 + 2 * t);
            qf[ks][3] = *(const uint32_t*)(sQ + (wrow + g + 8) * FK_PITCH + ks * 16 + 8 + 2 * t);
        }
    }
    __syncthreads();

    const int qr0 = qbase + wrow + g;
    const int qr1 = qr0 + 8;
    const float* brow0 = g_bias + ((size_t)h * S + min(qr0, S - 1)) * S;
    const float* brow1 = g_bias + ((size_t)h * S + min(qr1, S - 1)) * S;

    float m0r = -1e30f, m1r = -1e30f, l0 = 0.f, l1 = 0.f;
    float o[8][4];
#pragma unroll
    for (int j = 0; j < 8; ++j)
#pragma unroll
        for (int e = 0; e < 4; ++e) o[j][e] = 0.f;

#pragma unroll
    for (int kt = 0; kt < 2; ++kt) {
        const int kb = kt * 128;
        if (kt == 0) { CP_WAIT1(); } else { CP_WAIT0(); }
        __syncthreads();

        const __half* sK = smh + kt * K_HALVES;
        const __half* sV = smh + FV_BASE + kt * V_HALVES;

        float sacc[16][4];
#pragma unroll
        for (int j = 0; j < 16; ++j)
#pragma unroll
            for (int e = 0; e < 4; ++e) sacc[j][e] = 0.f;

#pragma unroll
        for (int ks = 0; ks < 4; ++ks) {
#pragma unroll
            for (int j = 0; j < 16; ++j) {
                uint32_t bf[2];
                bf[0] = *(const uint32_t*)(sK + (j * 8 + g) * FK_PITCH + ks * 16 + 2 * t);
                bf[1] = *(const uint32_t*)(sK + (j * 8 + g) * FK_PITCH + ks * 16 + 8 + 2 * t);
                mma_f16(sacc[j], qf[ks], bf);
            }
        }

#pragma unroll
        for (int j = 0; j < 16; ++j) {
            const int kc = kb + j * 8 + 2 * t;
            if (kc < S)     sacc[j][0] += brow0[kc];     else sacc[j][0] = -1e30f;
            if (kc + 1 < S) sacc[j][1] += brow0[kc + 1]; else sacc[j][1] = -1e30f;
            if (kc < S)     sacc[j][2] += brow1[kc];     else sacc[j][2] = -1e30f;
            if (kc + 1 < S) sacc[j][3] += brow1[kc + 1]; else sacc[j][3] = -1e30f;
        }

        float mx0 = -1e30f, mx1 = -1e30f;
#pragma unroll
        for (int j = 0; j < 16; ++j) {
            mx0 = fmaxf(mx0, fmaxf(sacc[j][0], sacc[j][1]));
            mx1 = fmaxf(mx1, fmaxf(sacc[j][2], sacc[j][3]));
        }
        mx0 = fmaxf(mx0, __shfl_xor_sync(0xffffffffu, mx0, 1));
        mx0 = fmaxf(mx0, __shfl_xor_sync(0xffffffffu, mx0, 2));
        mx1 = fmaxf(mx1, __shfl_xor_sync(0xffffffffu, mx1, 1));
        mx1 = fmaxf(mx1, __shfl_xor_sync(0xffffffffu, mx1, 2));

        const float nm0 = fmaxf(m0r, mx0);
        const float nm1 = fmaxf(m1r, mx1);
        const float sc0 = __expf(m0r - nm0);
        const float sc1 = __expf(m1r - nm1);
        m0r = nm0; m1r = nm1;

        float sum0 = 0.f, sum1 = 0.f;
        __half* sP = smh + FP_BASE;
#pragma unroll
        for (int j = 0; j < 16; ++j) {
            const float p0 = __expf(sacc[j][0] - nm0);
            const float p1 = __expf(sacc[j][1] - nm0);
            const float p2 = __expf(sacc[j][2] - nm1);
            const float p3 = __expf(sacc[j][3] - nm1);
            sum0 += p0 + p1; sum1 += p2 + p3;
            const int col = j * 8 + 2 * t;
            *(__half2*)(sP + (wrow + g) * FP_PITCH + col)     = __floats2half2_rn(p0, p1);
            *(__half2*)(sP + (wrow + g + 8) * FP_PITCH + col) = __floats2half2_rn(p2, p3);
        }
        sum0 += __shfl_xor_sync(0xffffffffu, sum0, 1);
        sum0 += __shfl_xor_sync(0xffffffffu, sum0, 2);
        sum1 += __shfl_xor_sync(0xffffffffu, sum1, 1);
        sum1 += __shfl_xor_sync(0xffffffffu, sum1, 2);
        l0 = l0 * sc0 + sum0;
        l1 = l1 * sc1 + sum1;

#pragma unroll
        for (int j = 0; j < 8; ++j) {
            o[j][0] *= sc0; o[j][1] *= sc0;
            o[j][2] *= sc1; o[j][3] *= sc1;
        }
        __syncwarp();

#pragma unroll
        for (int ks = 0; ks < 8; ++ks) {
            uint32_t af[4];
            af[0] = *(const uint32_t*)(sP + (wrow + g) * FP_PITCH + ks * 16 + 2 * t);
            af[1] = *(const uint32_t*)(sP + (wrow + g + 8) * FP_PITCH + ks * 16 + 2 * t);
            af[2] = *(const uint32_t*)(sP + (wrow + g) * FP_PITCH + ks * 16 + 8 + 2 * t);
            af[3] = *(const uint32_t*)(sP + (wrow + g + 8) * FP_PITCH + ks * 16 + 8 + 2 * t);
#pragma unroll
            for (int j = 0; j < 8; ++j) {
                uint32_t bf[2];
                bf[0] = *(const uint32_t*)(sV + (j * 8 + g) * FP_PITCH + ks * 16 + 2 * t);
                bf[1] = *(const uint32_t*)(sV + (j * 8 + g) * FP_PITCH + ks * 16 + 8 + 2 * t);
                mma_f16(o[j], af, bf);
            }
        }
        __syncwarp();
    }

    const float inv0 = 1.f / l0;
    const float inv1 = 1.f / l1;
#pragma unroll
    for (int j = 0; j < 8; ++j) {
        const int col = h * HD + j * 8 + 2 * t;
        if (qr0 < S) {
            float2 v; v.x = o[j][0] * inv0; v.y = o[j][1] * inv0;
            *(float2*)(out + ((size_t)b * S + qr0) * D + col) = v;
        }
        if (qr1 < S) {
            float2 v; v.x = o[j][2] * inv1; v.y = o[j][3] * inv1;
            *(float2*)(out + ((size_t)b * S + qr1) * D + col) = v;
        }
    }
}

// ============================================================================
// Launch. Inputs: hidden_states, wq, bq, wk, wv, bv, bias_table, rel_index
// Prep kernels forked onto a side stream (created once, uncaptured first call).
// ============================================================================
extern "C" void kernel_launch(void* const* d_in, const int* in_sizes, int n_in,
                              void* d_out, int out_size)
{
    const float* X  = (const float*)d_in[0];
    const float* wq = (const float*)d_in[1];
    const float* bq = (const float*)d_in[2];
    const float* wk = (const float*)d_in[3];
    const float* wv = (const float*)d_in[4];
    const float* bv = (const float*)d_in[5];
    const float* bt = (const float*)d_in[6];
    const int*   ri = (const int*)d_in[7];
    float* out = (float*)d_out;

    (void)in_sizes; (void)n_in; (void)out_size;

    static __half* xh_ptr = nullptr;
    static __half* wh_ptr = nullptr;
    static cudaStream_t s1 = nullptr;
    static cudaEvent_t ev_fork = nullptr, ev_join = nullptr;
    if (!xh_ptr) {
        cudaGetSymbolAddress((void**)&xh_ptr, g_xh);
        cudaGetSymbolAddress((void**)&wh_ptr, g_wh);
        cudaFuncSetAttribute(qkv_mma_kernel, cudaFuncAttributeMaxDynamicSharedMemorySize, SMEM_QKV_BYTES);
        cudaFuncSetAttribute(flash_kernel, cudaFuncAttributeMaxDynamicSharedMemorySize, SMEM_FLASH_BYTES);
        cudaStreamCreateWithFlags(&s1, cudaStreamNonBlocking);
        cudaEventCreateWithFlags(&ev_fork, cudaEventDisableTiming);
        cudaEventCreateWithFlags(&ev_join, cudaEventDisableTiming);
    }

    const int nx8 = M_TOT * D / 8;
    const int nw8 = 3 * D * D / 8;

    // fork: side stream runs weight/bias/pad prep while main runs cvt_x
    cudaEventRecord(ev_fork, 0);
    cudaStreamWaitEvent(s1, ev_fork, 0);

    cvt_x_kernel<<<(nx8 + 255) / 256, 256>>>(X, xh_ptr, nx8);

    cvt_w_kernel<<<(nw8 + 255) / 256, 256, 0, s1>>>(wq, wk, wv, wh_ptr);
    vt_pad_kernel<<<(B * H * HD * 16 + 255) / 256, 256, 0, s1>>>();
    bias_expand_kernel<<<(S * S + 255) / 256, 256, 0, s1>>>(bt, ri);
    cudaEventRecord(ev_join, s1);

    // join before qkv (needs g_wh; vt_pad must precede qkv's V writes)
    cudaStreamWaitEvent(0, ev_join, 0);

    qkv_mma_kernel<<<dim3((M_TOT + 127) / 128, 2304 / 256), 512, SMEM_QKV_BYTES>>>(bq, bv);
    flash_kernel<<<dim3(2, B * H), 256, SMEM_FLASH_BYTES>>>(out);
}

// round 9
// speedup vs baseline: 6.7797x; 1.0463x over previous
#include <cuda_runtime.h>
#include <cuda_fp16.h>
#include <math.h>
#include <cstdint>

#define B 64
#define S 197
#define D 768
#define H 12
#define HD 64
#define M_TOT (B * S)          // 12608
#define NUM_REL 732
#define VT_PITCH 256
#define BP 198                 // bias pitch (even -> aligned float2)
#define LOG2E 1.44269504f

// -------- device scratch --------
__device__ __half g_xh[(size_t)M_TOT * D];
__device__ __half g_wh[(size_t)3 * D * D];
__device__ __half g_qh[(size_t)B * H * S * HD];
__device__ __half g_kh[(size_t)B * H * S * HD];
__device__ __half g_vt[(size_t)B * H * HD * VT_PITCH];
__device__ float g_bias[(size_t)H * S * BP];

__device__ __forceinline__ void mma_f16(float* d, const uint32_t* a, const uint32_t* b) {
    asm volatile(
        "mma.sync.aligned.m16n8k16.row.col.f32.f16.f16.f32 "
        "{%0,%1,%2,%3}, {%4,%5,%6,%7}, {%8,%9}, {%0,%1,%2,%3};"
        : "+f"(d[0]), "+f"(d[1]), "+f"(d[2]), "+f"(d[3])
        : "r"(a[0]), "r"(a[1]), "r"(a[2]), "r"(a[3]), "r"(b[0]), "r"(b[1]));
}

__device__ __forceinline__ void ldsm_x4(uint32_t& r0, uint32_t& r1, uint32_t& r2, uint32_t& r3,
                                        uint32_t addr) {
    asm volatile("ldmatrix.sync.aligned.m8n8.x4.shared.b16 {%0,%1,%2,%3}, [%4];"
                 : "=r"(r0), "=r"(r1), "=r"(r2), "=r"(r3) : "r"(addr));
}

__device__ __forceinline__ uint32_t smem_u32(const void* p) {
    uint32_t a;
    asm("{ .reg .u64 t; cvta.to.shared.u64 t, %1; cvt.u32.u64 %0, t; }" : "=r"(a) : "l"(p));
    return a;
}

__device__ __forceinline__ void cp16(uint32_t dst, const void* src, bool pred) {
    const int sz = pred ? 16 : 0;
    asm volatile("cp.async.cg.shared.global [%0], [%1], 16, %2;"
                 :: "r"(dst), "l"(src), "r"(sz) : "memory");
}
#define CP_COMMIT() asm volatile("cp.async.commit_group;" ::: "memory")
#define CP_WAIT1()  asm volatile("cp.async.wait_group 1;" ::: "memory")
#define CP_WAIT0()  asm volatile("cp.async.wait_group 0;" ::: "memory")

__device__ __forceinline__ uint32_t ex2_f16x2(__half2 x) {
    uint32_t r;
    asm("ex2.approx.f16x2 %0, %1;" : "=r"(r) : "r"(*(uint32_t*)&x));
    return r;
}

// ============================================================================
// Kernel 0a: fp32 -> fp16 convert (X), 8 elems/thread.
// ============================================================================
__global__ __launch_bounds__(256) void cvt_x_kernel(
    const float* __restrict__ src, __half* __restrict__ dst, int n8)
{
    const int i = blockIdx.x * 256 + threadIdx.x;
    if (i >= n8) return;
    const float4 a = ((const float4*)src)[2 * i];
    const float4 b = ((const float4*)src)[2 * i + 1];
    __half2 h0 = __floats2half2_rn(a.x, a.y);
    __half2 h1 = __floats2half2_rn(a.z, a.w);
    __half2 h2 = __floats2half2_rn(b.x, b.y);
    __half2 h3 = __floats2half2_rn(b.z, b.w);
    uint4 u;
    u.x = *(uint32_t*)&h0; u.y = *(uint32_t*)&h1;
    u.z = *(uint32_t*)&h2; u.w = *(uint32_t*)&h3;
    ((uint4*)dst)[i] = u;
}

// ============================================================================
// Kernel 0b: fused weight convert (wq|wk|wv -> g_wh).
// ============================================================================
__global__ __launch_bounds__(256) void cvt_w_kernel(
    const float* __restrict__ wq, const float* __restrict__ wk,
    const float* __restrict__ wv, __half* __restrict__ dst)
{
    const int nw8 = D * D / 8;
    const int i = blockIdx.x * 256 + threadIdx.x;
    if (i >= 3 * nw8) return;
    const float* src;
    int j;
    if (i < nw8)          { src = wq; j = i; }
    else if (i < 2 * nw8) { src = wk; j = i - nw8; }
    else                  { src = wv; j = i - 2 * nw8; }
    const float4 a = ((const float4*)src)[2 * j];
    const float4 b = ((const float4*)src)[2 * j + 1];
    __half2 h0 = __floats2half2_rn(a.x, a.y);
    __half2 h1 = __floats2half2_rn(a.z, a.w);
    __half2 h2 = __floats2half2_rn(b.x, b.y);
    __half2 h3 = __floats2half2_rn(b.z, b.w);
    uint4 u;
    u.x = *(uint32_t*)&h0; u.y = *(uint32_t*)&h1;
    u.z = *(uint32_t*)&h2; u.w = *(uint32_t*)&h3;
    ((uint4*)dst)[i] = u;
}

// ============================================================================
// Kernel 0c: zero g_vt tail (k in [192,256)). Runs BEFORE qkv.
// ============================================================================
__global__ __launch_bounds__(256) void vt_pad_kernel()
{
    const int i = blockIdx.x * 256 + threadIdx.x;
    if (i >= B * H * HD * 16) return;
    const int row = i >> 4, j = i & 15;
    ((uint2*)(g_vt + (size_t)row * VT_PITCH + 192))[j] = make_uint2(0u, 0u);
}

// ============================================================================
// Kernel 1: QKV projection (unchanged from R8, passing).
// ============================================================================
#define HPITCH 72
#define A_HALVES (128 * HPITCH)
#define B_HALVES (256 * HPITCH)
#define STAGE_HALVES (A_HALVES + B_HALVES)
#define STAGE_BYTES (STAGE_HALVES * 2)          // 55296
#define SMEM_QKV_BYTES (3 * STAGE_BYTES)        // 165888
#define NCHUNK 12

__global__ __launch_bounds__(512, 1) void qkv_mma_kernel(
    const float* __restrict__ bq, const float* __restrict__ bv)
{
    extern __shared__ __half smh[];
    const uint32_t sbase = smem_u32(smh);

    const int tid  = threadIdx.x;
    const int lane = tid & 31;
    const int wid  = tid >> 5;
    const int g    = lane >> 2;
    const int t    = lane & 3;
    const int wm   = wid & 1;
    const int wn   = wid >> 1;

    const int m0  = blockIdx.x * 128;
    const int n0g = blockIdx.y * 256;
    const int proj = n0g / 768;
    const int n0   = n0g - proj * 768;

    const float* bias = (proj == 0) ? bq : ((proj == 2) ? bv : nullptr);

    const int lrow = tid >> 3;
    const int lcg  = tid & 7;

    auto issue = [&](int c, int s) {
        const int k0 = c * 64;
        const uint32_t smA = sbase + s * STAGE_BYTES;
        const uint32_t smB = smA + A_HALVES * 2;
#pragma unroll
        for (int i = 0; i < 2; ++i) {
            const int row = lrow + i * 64;
            const int m = m0 + row;
            const bool pa = m < M_TOT;
            const __half* srcA = g_xh + (size_t)(pa ? m : 0) * 768 + k0 + lcg * 8;
            cp16(smA + (row * HPITCH + lcg * 8) * 2, srcA, pa);
        }
#pragma unroll
        for (int i = 0; i < 4; ++i) {
            const int row = lrow + i * 64;
            const __half* srcB = g_wh + (size_t)(n0g + row) * 768 + k0 + lcg * 8;
            cp16(smB + (row * HPITCH + lcg * 8) * 2, srcB, true);
        }
        CP_COMMIT();
    };

    issue(0, 0);
    issue(1, 1);

    const int a_row_l = (lane & 7) + ((lane >> 3) & 1) * 8;
    const int a_col_l = ((lane >> 4) & 1) * 8;
    const int b_row_l = (lane & 7) + ((lane >> 4) & 1) * 8;
    const int b_col_l = ((lane >> 3) & 1) * 8;

    float acc[4][4][4];
#pragma unroll
    for (int mt = 0; mt < 4; ++mt)
#pragma unroll
        for (int nt = 0; nt < 4; ++nt)
#pragma unroll
            for (int e = 0; e < 4; ++e) acc[mt][nt][e] = 0.f;

    for (int c = 0; c < NCHUNK; ++c) {
        CP_WAIT1();
        __syncthreads();
        if (c + 2 < NCHUNK) issue(c + 2, (c + 2) % 3);

        const uint32_t stA = sbase + (c % 3) * STAGE_BYTES;
        const uint32_t stB = stA + A_HALVES * 2;
#pragma unroll
        for (int ks = 0; ks < 4; ++ks) {
            uint32_t af[4][4], bf[4][2];
#pragma unroll
            for (int mt = 0; mt < 4; ++mt) {
                const uint32_t addr = stA +
                    ((wm * 64 + mt * 16 + a_row_l) * HPITCH + ks * 16 + a_col_l) * 2;
                ldsm_x4(af[mt][0], af[mt][1], af[mt][2], af[mt][3], addr);
            }
#pragma unroll
            for (int ntp = 0; ntp < 2; ++ntp) {
                const uint32_t addr = stB +
                    ((wn * 32 + ntp * 16 + b_row_l) * HPITCH + ks * 16 + b_col_l) * 2;
                ldsm_x4(bf[2 * ntp][0], bf[2 * ntp][1],
                        bf[2 * ntp + 1][0], bf[2 * ntp + 1][1], addr);
            }
#pragma unroll
            for (int mt = 0; mt < 4; ++mt)
#pragma unroll
                for (int nt = 0; nt < 4; ++nt)
                    mma_f16(acc[mt][nt], af[mt], bf[nt]);
        }
    }

    const float scale = (proj == 0) ? 0.125f : 1.0f;
#pragma unroll
    for (int mt = 0; mt < 4; ++mt) {
        const int r0 = m0 + wm * 64 + mt * 16 + g;
#pragma unroll
        for (int nt = 0; nt < 4; ++nt) {
            const int n = n0 + wn * 32 + nt * 8 + t * 2;
            const int hh = n >> 6;
            const int hd = n & 63;
            float bx = 0.f, by = 0.f;
            if (bias) { bx = bias[n]; by = bias[n + 1]; }
#pragma unroll
            for (int half_i = 0; half_i < 2; ++half_i) {
                const int m = r0 + half_i * 8;
                if (m >= M_TOT) continue;
                const int bb = m / S;
                const int ss = m - bb * S;
                const int bh = bb * H + hh;
                const float vx = (acc[mt][nt][half_i * 2 + 0] + bx) * scale;
                const float vy = (acc[mt][nt][half_i * 2 + 1] + by) * scale;
                if (proj == 2) {
                    g_vt[((size_t)bh * HD + hd) * VT_PITCH + ss]     = __float2half_rn(vx);
                    g_vt[((size_t)bh * HD + hd + 1) * VT_PITCH + ss] = __float2half_rn(vy);
                } else {
                    __half2 hv = __floats2half2_rn(vx, vy);
                    __half* dst = (proj == 0) ? g_qh : g_kh;
                    *(__half2*)(dst + ((size_t)bh * S + ss) * HD + hd) = hv;
                }
            }
        }
    }
}

// ============================================================================
// Kernel 2: expand relative-position bias to g_bias[h][q][BP] (pitch 198).
// ============================================================================
__global__ __launch_bounds__(256) void bias_expand_kernel(
    const float* __restrict__ bias_table, const int* __restrict__ rel_index)
{
    const int i = blockIdx.x * 256 + threadIdx.x;
    if (i >= S * S) return;
    const int q = i / S, k = i - q * S;
    const int r = rel_index[i];
#pragma unroll
    for (int h = 0; h < H; ++h)
        g_bias[((size_t)h * S + q) * BP + k] = bias_table[r * H + h];
}

// ============================================================================
// Kernel 3: flash attention. ex2.f16x2 softmax + ones-column row sums.
// sV has 72 rows: 0-63 = V^T, 64 = ones, 65-71 = zeros. P.V over 9 n-tiles;
// n-tile 8 (cols 64..71) accumulates l = sum(P) exactly (incl. rescale).
// ============================================================================
#define FK_PITCH 72
#define FP_PITCH 136
#define K_HALVES (128 * FK_PITCH)               // 9216
#define V_HALVES (72 * FP_PITCH)                // 9792
#define FV_BASE (2 * K_HALVES)
#define FP_BASE (2 * K_HALVES + 2 * V_HALVES)   // 38016
#define SMEM_FLASH_BYTES ((FP_BASE + 128 * FP_PITCH) * 2)   // 110848

__global__ __launch_bounds__(256, 2) void flash_kernel(float* __restrict__ out)
{
    extern __shared__ __half smh[];
    const uint32_t sbase = smem_u32(smh);

    const int tid  = threadIdx.x;
    const int lane = tid & 31;
    const int wid  = tid >> 5;
    const int g    = lane >> 2;
    const int t    = lane & 3;

    const int qt = blockIdx.x;
    const int bh = blockIdx.y;
    const int b  = bh / H;
    const int h  = bh - b * H;
    const int qbase = qt * 128;
    const int wrow  = wid * 16;

    const __half* Qg = g_qh + (size_t)bh * S * HD;
    const __half* Kg = g_kh + (size_t)bh * S * HD;
    const __half* Vt = g_vt + (size_t)bh * HD * VT_PITCH;

    // ---- issue both K and V tiles ----
#pragma unroll
    for (int kt = 0; kt < 2; ++kt) {
        const int kb = kt * 128;
        const uint32_t smK = sbase + kt * K_HALVES * 2;
        const uint32_t smV = sbase + (FV_BASE + kt * V_HALVES) * 2;
#pragma unroll
        for (int it = 0; it < 4; ++it) {
            const int f = tid + it * 256;
            const int row = f >> 3, cg = f & 7;
            const int kk = kb + row;
            const bool p = kk < S;
            cp16(smK + (row * FK_PITCH + cg * 8) * 2,
                 Kg + (size_t)(p ? kk : 0) * HD + cg * 8, p);
        }
#pragma unroll
        for (int it = 0; it < 4; ++it) {
            const int f = tid + it * 256;
            const int row = f >> 4, cg = f & 15;
            cp16(smV + (row * FP_PITCH + cg * 8) * 2,
                 Vt + (size_t)row * VT_PITCH + kb + cg * 8, true);
        }
        CP_COMMIT();
    }

    // ---- static sV rows 64-71 (ones / zeros), both buffers ----
    {
        const __half one  = __float2half(1.f);
        const __half zero = __float2half(0.f);
        for (int i = tid; i < 2 * 8 * FP_PITCH; i += 256) {
            const int buf = i / (8 * FP_PITCH);
            const int rem = i - buf * 8 * FP_PITCH;
            const int r   = rem / FP_PITCH;
            const int cc  = rem - r * FP_PITCH;
            smh[FV_BASE + buf * V_HALVES + (64 + r) * FP_PITCH + cc] = (r == 0) ? one : zero;
        }
    }

    // ---- stage Q into P region ----
    {
        __half* sQ = smh + FP_BASE;
#pragma unroll
        for (int it = 0; it < 4; ++it) {
            const int f = tid + it * 256;
            const int row = f >> 3, cg = f & 7;
            const int m = qbase + row;
            uint4 u = make_uint4(0u, 0u, 0u, 0u);
            if (m < S) u = *(const uint4*)(Qg + (size_t)m * HD + cg * 8);
            *(uint4*)(sQ + row * FK_PITCH + cg * 8) = u;
        }
    }
    __syncthreads();

    uint32_t qf[4][4];
    {
        const __half* sQ = smh + FP_BASE;
#pragma unroll
        for (int ks = 0; ks < 4; ++ks) {
            qf[ks][0] = *(const uint32_t*)(sQ + (wrow + g) * FK_PITCH + ks * 16 + 2 * t);
            qf[ks][1] = *(const uint32_t*)(sQ + (wrow + g + 8) * FK_PITCH + ks * 16 + 2 * t);
            qf[ks][2] = *(const uint32_t*)(sQ + (wrow + g) * FK_PITCH + ks * 16 + 8 + 2 * t);
            qf[ks][3] = *(const uint32_t*)(sQ + (wrow + g + 8) * FK_PITCH + ks * 16 + 8 + 2 * t);
        }
    }
    __syncthreads();

    const int qr0 = qbase + wrow + g;
    const int qr1 = qr0 + 8;
    const float* brow0 = g_bias + ((size_t)h * S + min(qr0, S - 1)) * BP;
    const float* brow1 = g_bias + ((size_t)h * S + min(qr1, S - 1)) * BP;

    float m0r = -1e30f, m1r = -1e30f;
    float o[9][4];                              // o[8] = row-sum accumulator
#pragma unroll
    for (int j = 0; j < 9; ++j)
#pragma unroll
        for (int e = 0; e < 4; ++e) o[j][e] = 0.f;

#pragma unroll
    for (int kt = 0; kt < 2; ++kt) {
        const int kb = kt * 128;
        if (kt == 0) { CP_WAIT1(); } else { CP_WAIT0(); }
        __syncthreads();

        const __half* sK = smh + kt * K_HALVES;
        const __half* sV = smh + FV_BASE + kt * V_HALVES;

        float sacc[16][4];
#pragma unroll
        for (int j = 0; j < 16; ++j)
#pragma unroll
            for (int e = 0; e < 4; ++e) sacc[j][e] = 0.f;

#pragma unroll
        for (int ks = 0; ks < 4; ++ks) {
#pragma unroll
            for (int j = 0; j < 16; ++j) {
                uint32_t bf[2];
                bf[0] = *(const uint32_t*)(sK + (j * 8 + g) * FK_PITCH + ks * 16 + 2 * t);
                bf[1] = *(const uint32_t*)(sK + (j * 8 + g) * FK_PITCH + ks * 16 + 8 + 2 * t);
                mma_f16(sacc[j], qf[ks], bf);
            }
        }

        // ---- bias add + mask (aligned float2 loads, pitch 198) ----
#pragma unroll
        for (int j = 0; j < 16; ++j) {
            const int kc = kb + j * 8 + 2 * t;
            if (kc < S) {
                const float2 b0 = *(const float2*)(brow0 + kc);
                const float2 b1 = *(const float2*)(brow1 + kc);
                sacc[j][0] += b0.x;
                sacc[j][1] = (kc + 1 < S) ? sacc[j][1] + b0.y : -1e30f;
                sacc[j][2] += b1.x;
                sacc[j][3] = (kc + 1 < S) ? sacc[j][3] + b1.y : -1e30f;
            } else {
                sacc[j][0] = -1e30f; sacc[j][1] = -1e30f;
                sacc[j][2] = -1e30f; sacc[j][3] = -1e30f;
            }
        }

        // ---- online max (quad-local rows) ----
        float mx0 = -1e30f, mx1 = -1e30f;
#pragma unroll
        for (int j = 0; j < 16; ++j) {
            mx0 = fmaxf(mx0, fmaxf(sacc[j][0], sacc[j][1]));
            mx1 = fmaxf(mx1, fmaxf(sacc[j][2], sacc[j][3]));
        }
        mx0 = fmaxf(mx0, __shfl_xor_sync(0xffffffffu, mx0, 1));
        mx0 = fmaxf(mx0, __shfl_xor_sync(0xffffffffu, mx0, 2));
        mx1 = fmaxf(mx1, __shfl_xor_sync(0xffffffffu, mx1, 1));
        mx1 = fmaxf(mx1, __shfl_xor_sync(0xffffffffu, mx1, 2));

        const float nm0 = fmaxf(m0r, mx0);
        const float nm1 = fmaxf(m1r, mx1);
        const float sc0 = __expf(m0r - nm0);
        const float sc1 = __expf(m1r - nm1);
        m0r = nm0; m1r = nm1;

        // ---- P = 2^((s-m)*log2e) in packed fp16 ----
        const float c0 = -nm0 * LOG2E;
        const float c1 = -nm1 * LOG2E;
        __half* sP = smh + FP_BASE;
#pragma unroll
        for (int j = 0; j < 16; ++j) {
            const int col = j * 8 + 2 * t;
            __half2 a0 = __floats2half2_rn(fmaf(sacc[j][0], LOG2E, c0),
                                           fmaf(sacc[j][1], LOG2E, c0));
            __half2 a1 = __floats2half2_rn(fmaf(sacc[j][2], LOG2E, c1),
                                           fmaf(sacc[j][3], LOG2E, c1));
            *(uint32_t*)(sP + (wrow + g) * FP_PITCH + col)     = ex2_f16x2(a0);
            *(uint32_t*)(sP + (wrow + g + 8) * FP_PITCH + col) = ex2_f16x2(a1);
        }

        // ---- rescale O and row-sum accumulator ----
#pragma unroll
        for (int j = 0; j < 9; ++j) {
            o[j][0] *= sc0; o[j][1] *= sc0;
            o[j][2] *= sc1; o[j][3] *= sc1;
        }
        __syncwarp();

        // ---- O += P V (9 n-tiles: 8 data + 1 ones-column sum) ----
#pragma unroll
        for (int ks = 0; ks < 8; ++ks) {
            uint32_t af[4];
            af[0] = *(const uint32_t*)(sP + (wrow + g) * FP_PITCH + ks * 16 + 2 * t);
            af[1] = *(const uint32_t*)(sP + (wrow + g + 8) * FP_PITCH + ks * 16 + 2 * t);
            af[2] = *(const uint32_t*)(sP + (wrow + g) * FP_PITCH + ks * 16 + 8 + 2 * t);
            af[3] = *(const uint32_t*)(sP + (wrow + g + 8) * FP_PITCH + ks * 16 + 8 + 2 * t);
#pragma unroll
            for (int j = 0; j < 9; ++j) {
                uint32_t bf[2];
                bf[0] = *(const uint32_t*)(sV + (j * 8 + g) * FP_PITCH + ks * 16 + 2 * t);
                bf[1] = *(const uint32_t*)(sV + (j * 8 + g) * FP_PITCH + ks * 16 + 8 + 2 * t);
                mma_f16(o[j], af, bf);
            }
        }
        __syncwarp();
    }

    // row sums live in column 64 -> t=0 lanes of o[8]
    const float l0 = __shfl_sync(0xffffffffu, o[8][0], lane & ~3);
    const float l1 = __shfl_sync(0xffffffffu, o[8][2], lane & ~3);
    const float inv0 = 1.f / l0;
    const float inv1 = 1.f / l1;
#pragma unroll
    for (int j = 0; j < 8; ++j) {
        const int col = h * HD + j * 8 + 2 * t;
        if (qr0 < S) {
            float2 v; v.x = o[j][0] * inv0; v.y = o[j][1] * inv0;
            *(float2*)(out + ((size_t)b * S + qr0) * D + col) = v;
        }
        if (qr1 < S) {
            float2 v; v.x = o[j][2] * inv1; v.y = o[j][3] * inv1;
            *(float2*)(out + ((size_t)b * S + qr1) * D + col) = v;
        }
    }
}

// ============================================================================
// Launch. Inputs: hidden_states, wq, bq, wk, wv, bv, bias_table, rel_index
// ============================================================================
extern "C" void kernel_launch(void* const* d_in, const int* in_sizes, int n_in,
                              void* d_out, int out_size)
{
    const float* X  = (const float*)d_in[0];
    const float* wq = (const float*)d_in[1];
    const float* bq = (const float*)d_in[2];
    const float* wk = (const float*)d_in[3];
    const float* wv = (const float*)d_in[4];
    const float* bv = (const float*)d_in[5];
    const float* bt = (const float*)d_in[6];
    const int*   ri = (const int*)d_in[7];
    float* out = (float*)d_out;

    (void)in_sizes; (void)n_in; (void)out_size;

    static __half* xh_ptr = nullptr;
    static __half* wh_ptr = nullptr;
    static cudaStream_t s1 = nullptr;
    static cudaEvent_t ev_fork = nullptr, ev_join = nullptr;
    if (!xh_ptr) {
        cudaGetSymbolAddress((void**)&xh_ptr, g_xh);
        cudaGetSymbolAddress((void**)&wh_ptr, g_wh);
        cudaFuncSetAttribute(qkv_mma_kernel, cudaFuncAttributeMaxDynamicSharedMemorySize, SMEM_QKV_BYTES);
        cudaFuncSetAttribute(flash_kernel, cudaFuncAttributeMaxDynamicSharedMemorySize, SMEM_FLASH_BYTES);
        cudaStreamCreateWithFlags(&s1, cudaStreamNonBlocking);
        cudaEventCreateWithFlags(&ev_fork, cudaEventDisableTiming);
        cudaEventCreateWithFlags(&ev_join, cudaEventDisableTiming);
    }

    const int nx8 = M_TOT * D / 8;
    const int nw8 = 3 * D * D / 8;

    cudaEventRecord(ev_fork, 0);
    cudaStreamWaitEvent(s1, ev_fork, 0);

    cvt_x_kernel<<<(nx8 + 255) / 256, 256>>>(X, xh_ptr, nx8);

    cvt_w_kernel<<<(nw8 + 255) / 256, 256, 0, s1>>>(wq, wk, wv, wh_ptr);
    vt_pad_kernel<<<(B * H * HD * 16 + 255) / 256, 256, 0, s1>>>();
    bias_expand_kernel<<<(S * S + 255) / 256, 256, 0, s1>>>(bt, ri);
    cudaEventRecord(ev_join, s1);

    cudaStreamWaitEvent(0, ev_join, 0);

    qkv_mma_kernel<<<dim3((M_TOT + 127) / 128, 2304 / 256), 512, SMEM_QKV_BYTES>>>(bq, bv);
    flash_kernel<<<dim3(2, B * H), 256, SMEM_FLASH_BYTES>>>(out);
}

// round 10
// speedup vs baseline: 6.9961x; 1.0319x over previous
#include <cuda_runtime.h>
#include <cuda_fp16.h>
#include <math.h>
#include <cstdint>

#define B 64
#define S 197
#define D 768
#define H 12
#define HD 64
#define M_TOT (B * S)          // 12608
#define NUM_REL 732
#define VT_PITCH 256
#define BP 198                 // bias pitch (even -> aligned half2)
#define LOG2E 1.44269504f

// batch split: blocks 0..49 cover rows 0..6399 (batches 0..31 end at 6304)
#define MBLK_A 50
#define MBLK_B 49
#define ROWS_A 6400

// -------- device scratch --------
__device__ __half g_xh[(size_t)M_TOT * D];
__device__ __half g_wh[(size_t)3 * D * D];
__device__ __half g_qh[(size_t)B * H * S * HD];
__device__ __half g_kh[(size_t)B * H * S * HD];
__device__ __half g_vt[(size_t)B * H * HD * VT_PITCH];
__device__ __half g_bias[(size_t)H * S * BP];       // fp16 bias, elem 197/row = 0

__device__ __forceinline__ void mma_f16(float* d, const uint32_t* a, const uint32_t* b) {
    asm volatile(
        "mma.sync.aligned.m16n8k16.row.col.f32.f16.f16.f32 "
        "{%0,%1,%2,%3}, {%4,%5,%6,%7}, {%8,%9}, {%0,%1,%2,%3};"
        : "+f"(d[0]), "+f"(d[1]), "+f"(d[2]), "+f"(d[3])
        : "r"(a[0]), "r"(a[1]), "r"(a[2]), "r"(a[3]), "r"(b[0]), "r"(b[1]));
}

__device__ __forceinline__ void ldsm_x4(uint32_t& r0, uint32_t& r1, uint32_t& r2, uint32_t& r3,
                                        uint32_t addr) {
    asm volatile("ldmatrix.sync.aligned.m8n8.x4.shared.b16 {%0,%1,%2,%3}, [%4];"
                 : "=r"(r0), "=r"(r1), "=r"(r2), "=r"(r3) : "r"(addr));
}

__device__ __forceinline__ uint32_t smem_u32(const void* p) {
    uint32_t a;
    asm("{ .reg .u64 t; cvta.to.shared.u64 t, %1; cvt.u32.u64 %0, t; }" : "=r"(a) : "l"(p));
    return a;
}

__device__ __forceinline__ void cp16(uint32_t dst, const void* src, bool pred) {
    const int sz = pred ? 16 : 0;
    asm volatile("cp.async.cg.shared.global [%0], [%1], 16, %2;"
                 :: "r"(dst), "l"(src), "r"(sz) : "memory");
}
#define CP_COMMIT() asm volatile("cp.async.commit_group;" ::: "memory")
#define CP_WAIT1()  asm volatile("cp.async.wait_group 1;" ::: "memory")
#define CP_WAIT0()  asm volatile("cp.async.wait_group 0;" ::: "memory")

__device__ __forceinline__ uint32_t ex2_f16x2(__half2 x) {
    uint32_t r;
    asm("ex2.approx.f16x2 %0, %1;" : "=r"(r) : "r"(*(uint32_t*)&x));
    return r;
}

// ============================================================================
// Kernel 0a: fp32 -> fp16 convert, 8 elems/thread (offset via pointers).
// ============================================================================
__global__ __launch_bounds__(256) void cvt_x_kernel(
    const float* __restrict__ src, __half* __restrict__ dst, int n8)
{
    const int i = blockIdx.x * 256 + threadIdx.x;
    if (i >= n8) return;
    const float4 a = ((const float4*)src)[2 * i];
    const float4 b = ((const float4*)src)[2 * i + 1];
    __half2 h0 = __floats2half2_rn(a.x, a.y);
    __half2 h1 = __floats2half2_rn(a.z, a.w);
    __half2 h2 = __floats2half2_rn(b.x, b.y);
    __half2 h3 = __floats2half2_rn(b.z, b.w);
    uint4 u;
    u.x = *(uint32_t*)&h0; u.y = *(uint32_t*)&h1;
    u.z = *(uint32_t*)&h2; u.w = *(uint32_t*)&h3;
    ((uint4*)dst)[i] = u;
}

// ============================================================================
// Kernel 0b: fused weight convert (wq|wk|wv -> g_wh).
// ============================================================================
__global__ __launch_bounds__(256) void cvt_w_kernel(
    const float* __restrict__ wq, const float* __restrict__ wk,
    const float* __restrict__ wv, __half* __restrict__ dst)
{
    const int nw8 = D * D / 8;
    const int i = blockIdx.x * 256 + threadIdx.x;
    if (i >= 3 * nw8) return;
    const float* src;
    int j;
    if (i < nw8)          { src = wq; j = i; }
    else if (i < 2 * nw8) { src = wk; j = i - nw8; }
    else                  { src = wv; j = i - 2 * nw8; }
    const float4 a = ((const float4*)src)[2 * j];
    const float4 b = ((const float4*)src)[2 * j + 1];
    __half2 h0 = __floats2half2_rn(a.x, a.y);
    __half2 h1 = __floats2half2_rn(a.z, a.w);
    __half2 h2 = __floats2half2_rn(b.x, b.y);
    __half2 h3 = __floats2half2_rn(b.z, b.w);
    uint4 u;
    u.x = *(uint32_t*)&h0; u.y = *(uint32_t*)&h1;
    u.z = *(uint32_t*)&h2; u.w = *(uint32_t*)&h3;
    ((uint4*)dst)[i] = u;
}

// ============================================================================
// Kernel 0c: zero g_vt tail (k in [192,256)). Runs BEFORE qkv.
// ============================================================================
__global__ __launch_bounds__(256) void vt_pad_kernel()
{
    const int i = blockIdx.x * 256 + threadIdx.x;
    if (i >= B * H * HD * 16) return;
    const int row = i >> 4, j = i & 15;
    ((uint2*)(g_vt + (size_t)row * VT_PITCH + 192))[j] = make_uint2(0u, 0u);
}

// ============================================================================
// Kernel 1: QKV projection (R8 core, + m-block offset for batch-split).
// ============================================================================
#define HPITCH 72
#define A_HALVES (128 * HPITCH)
#define B_HALVES (256 * HPITCH)
#define STAGE_HALVES (A_HALVES + B_HALVES)
#define STAGE_BYTES (STAGE_HALVES * 2)          // 55296
#define SMEM_QKV_BYTES (3 * STAGE_BYTES)        // 165888
#define NCHUNK 12

__global__ __launch_bounds__(512, 1) void qkv_mma_kernel(
    const float* __restrict__ bq, const float* __restrict__ bv, int mblk0)
{
    extern __shared__ __half smh[];
    const uint32_t sbase = smem_u32(smh);

    const int tid  = threadIdx.x;
    const int lane = tid & 31;
    const int wid  = tid >> 5;
    const int g    = lane >> 2;
    const int t    = lane & 3;
    const int wm   = wid & 1;
    const int wn   = wid >> 1;

    const int m0  = (mblk0 + blockIdx.x) * 128;
    const int n0g = blockIdx.y * 256;
    const int proj = n0g / 768;
    const int n0   = n0g - proj * 768;

    const float* bias = (proj == 0) ? bq : ((proj == 2) ? bv : nullptr);

    const int lrow = tid >> 3;
    const int lcg  = tid & 7;

    auto issue = [&](int c, int s) {
        const int k0 = c * 64;
        const uint32_t smA = sbase + s * STAGE_BYTES;
        const uint32_t smB = smA + A_HALVES * 2;
#pragma unroll
        for (int i = 0; i < 2; ++i) {
            const int row = lrow + i * 64;
            const int m = m0 + row;
            const bool pa = m < M_TOT;
            const __half* srcA = g_xh + (size_t)(pa ? m : 0) * 768 + k0 + lcg * 8;
            cp16(smA + (row * HPITCH + lcg * 8) * 2, srcA, pa);
        }
#pragma unroll
        for (int i = 0; i < 4; ++i) {
            const int row = lrow + i * 64;
            const __half* srcB = g_wh + (size_t)(n0g + row) * 768 + k0 + lcg * 8;
            cp16(smB + (row * HPITCH + lcg * 8) * 2, srcB, true);
        }
        CP_COMMIT();
    };

    issue(0, 0);
    issue(1, 1);

    const int a_row_l = (lane & 7) + ((lane >> 3) & 1) * 8;
    const int a_col_l = ((lane >> 4) & 1) * 8;
    const int b_row_l = (lane & 7) + ((lane >> 4) & 1) * 8;
    const int b_col_l = ((lane >> 3) & 1) * 8;

    float acc[4][4][4];
#pragma unroll
    for (int mt = 0; mt < 4; ++mt)
#pragma unroll
        for (int nt = 0; nt < 4; ++nt)
#pragma unroll
            for (int e = 0; e < 4; ++e) acc[mt][nt][e] = 0.f;

    for (int c = 0; c < NCHUNK; ++c) {
        CP_WAIT1();
        __syncthreads();
        if (c + 2 < NCHUNK) issue(c + 2, (c + 2) % 3);

        const uint32_t stA = sbase + (c % 3) * STAGE_BYTES;
        const uint32_t stB = stA + A_HALVES * 2;
#pragma unroll
        for (int ks = 0; ks < 4; ++ks) {
            uint32_t af[4][4], bf[4][2];
#pragma unroll
            for (int mt = 0; mt < 4; ++mt) {
                const uint32_t addr = stA +
                    ((wm * 64 + mt * 16 + a_row_l) * HPITCH + ks * 16 + a_col_l) * 2;
                ldsm_x4(af[mt][0], af[mt][1], af[mt][2], af[mt][3], addr);
            }
#pragma unroll
            for (int ntp = 0; ntp < 2; ++ntp) {
                const uint32_t addr = stB +
                    ((wn * 32 + ntp * 16 + b_row_l) * HPITCH + ks * 16 + b_col_l) * 2;
                ldsm_x4(bf[2 * ntp][0], bf[2 * ntp][1],
                        bf[2 * ntp + 1][0], bf[2 * ntp + 1][1], addr);
            }
#pragma unroll
            for (int mt = 0; mt < 4; ++mt)
#pragma unroll
                for (int nt = 0; nt < 4; ++nt)
                    mma_f16(acc[mt][nt], af[mt], bf[nt]);
        }
    }

    const float scale = (proj == 0) ? 0.125f : 1.0f;
#pragma unroll
    for (int mt = 0; mt < 4; ++mt) {
        const int r0 = m0 + wm * 64 + mt * 16 + g;
#pragma unroll
        for (int nt = 0; nt < 4; ++nt) {
            const int n = n0 + wn * 32 + nt * 8 + t * 2;
            const int hh = n >> 6;
            const int hd = n & 63;
            float bx = 0.f, by = 0.f;
            if (bias) { bx = bias[n]; by = bias[n + 1]; }
#pragma unroll
            for (int half_i = 0; half_i < 2; ++half_i) {
                const int m = r0 + half_i * 8;
                if (m >= M_TOT) continue;
                const int bb = m / S;
                const int ss = m - bb * S;
                const int bh = bb * H + hh;
                const float vx = (acc[mt][nt][half_i * 2 + 0] + bx) * scale;
                const float vy = (acc[mt][nt][half_i * 2 + 1] + by) * scale;
                if (proj == 2) {
                    g_vt[((size_t)bh * HD + hd) * VT_PITCH + ss]     = __float2half_rn(vx);
                    g_vt[((size_t)bh * HD + hd + 1) * VT_PITCH + ss] = __float2half_rn(vy);
                } else {
                    __half2 hv = __floats2half2_rn(vx, vy);
                    __half* dst = (proj == 0) ? g_qh : g_kh;
                    *(__half2*)(dst + ((size_t)bh * S + ss) * HD + hd) = hv;
                }
            }
        }
    }
}

// ============================================================================
// Kernel 2: expand relative-position bias to fp16 g_bias[h][q][BP].
// ============================================================================
__global__ __launch_bounds__(256) void bias_expand_kernel(
    const float* __restrict__ bias_table, const int* __restrict__ rel_index)
{
    const int i = blockIdx.x * 256 + threadIdx.x;
    if (i >= S * S) return;
    const int q = i / S, k = i - q * S;
    const int r = rel_index[i];
#pragma unroll
    for (int h = 0; h < H; ++h)
        g_bias[((size_t)h * S + q) * BP + k] = __float2half_rn(bias_table[r * H + h]);
}

// ============================================================================
// Kernel 3: flash attention (R9 core + bh offset + fp16 bias loads).
// ============================================================================
#define FK_PITCH 72
#define FP_PITCH 136
#define K_HALVES (128 * FK_PITCH)
#define V_HALVES (72 * FP_PITCH)
#define FV_BASE (2 * K_HALVES)
#define FP_BASE (2 * K_HALVES + 2 * V_HALVES)
#define SMEM_FLASH_BYTES ((FP_BASE + 128 * FP_PITCH) * 2)   // 110848

__global__ __launch_bounds__(256, 2) void flash_kernel(float* __restrict__ out, int bh0)
{
    extern __shared__ __half smh[];
    const uint32_t sbase = smem_u32(smh);

    const int tid  = threadIdx.x;
    const int lane = tid & 31;
    const int wid  = tid >> 5;
    const int g    = lane >> 2;
    const int t    = lane & 3;

    const int qt = blockIdx.x;
    const int bh = bh0 + blockIdx.y;
    const int b  = bh / H;
    const int h  = bh - b * H;
    const int qbase = qt * 128;
    const int wrow  = wid * 16;

    const __half* Qg = g_qh + (size_t)bh * S * HD;
    const __half* Kg = g_kh + (size_t)bh * S * HD;
    const __half* Vt = g_vt + (size_t)bh * HD * VT_PITCH;

#pragma unroll
    for (int kt = 0; kt < 2; ++kt) {
        const int kb = kt * 128;
        const uint32_t smK = sbase + kt * K_HALVES * 2;
        const uint32_t smV = sbase + (FV_BASE + kt * V_HALVES) * 2;
#pragma unroll
        for (int it = 0; it < 4; ++it) {
            const int f = tid + it * 256;
            const int row = f >> 3, cg = f & 7;
            const int kk = kb + row;
            const bool p = kk < S;
            cp16(smK + (row * FK_PITCH + cg * 8) * 2,
                 Kg + (size_t)(p ? kk : 0) * HD + cg * 8, p);
        }
#pragma unroll
        for (int it = 0; it < 4; ++it) {
            const int f = tid + it * 256;
            const int row = f >> 4, cg = f & 15;
            cp16(smV + (row * FP_PITCH + cg * 8) * 2,
                 Vt + (size_t)row * VT_PITCH + kb + cg * 8, true);
        }
        CP_COMMIT();
    }

    // static sV rows 64-71 (ones / zeros), both buffers
    {
        const __half one  = __float2half(1.f);
        const __half zero = __float2half(0.f);
        for (int i = tid; i < 2 * 8 * FP_PITCH; i += 256) {
            const int buf = i / (8 * FP_PITCH);
            const int rem = i - buf * 8 * FP_PITCH;
            const int r   = rem / FP_PITCH;
            const int cc  = rem - r * FP_PITCH;
            smh[FV_BASE + buf * V_HALVES + (64 + r) * FP_PITCH + cc] = (r == 0) ? one : zero;
        }
    }

    // stage Q into P region
    {
        __half* sQ = smh + FP_BASE;
#pragma unroll
        for (int it = 0; it < 4; ++it) {
            const int f = tid + it * 256;
            const int row = f >> 3, cg = f & 7;
            const int m = qbase + row;
            uint4 u = make_uint4(0u, 0u, 0u, 0u);
            if (m < S) u = *(const uint4*)(Qg + (size_t)m * HD + cg * 8);
            *(uint4*)(sQ + row * FK_PITCH + cg * 8) = u;
        }
    }
    __syncthreads();

    uint32_t qf[4][4];
    {
        const __half* sQ = smh + FP_BASE;
#pragma unroll
        for (int ks = 0; ks < 4; ++ks) {
            qf[ks][0] = *(const uint32_t*)(sQ + (wrow + g) * FK_PITCH + ks * 16 + 2 * t);
            qf[ks][1] = *(const uint32_t*)(sQ + (wrow + g + 8) * FK_PITCH + ks * 16 + 2 * t);
            qf[ks][2] = *(const uint32_t*)(sQ + (wrow + g) * FK_PITCH + ks * 16 + 8 + 2 * t);
            qf[ks][3] = *(const uint32_t*)(sQ + (wrow + g + 8) * FK_PITCH + ks * 16 + 8 + 2 * t);
        }
    }
    __syncthreads();

    const int qr0 = qbase + wrow + g;
    const int qr1 = qr0 + 8;
    const __half* brow0 = g_bias + ((size_t)h * S + min(qr0, S - 1)) * BP;
    const __half* brow1 = g_bias + ((size_t)h * S + min(qr1, S - 1)) * BP;

    float m0r = -1e30f, m1r = -1e30f;
    float o[9][4];
#pragma unroll
    for (int j = 0; j < 9; ++j)
#pragma unroll
        for (int e = 0; e < 4; ++e) o[j][e] = 0.f;

#pragma unroll
    for (int kt = 0; kt < 2; ++kt) {
        const int kb = kt * 128;
        if (kt == 0) { CP_WAIT1(); } else { CP_WAIT0(); }
        __syncthreads();

        const __half* sK = smh + kt * K_HALVES;
        const __half* sV = smh + FV_BASE + kt * V_HALVES;

        float sacc[16][4];
#pragma unroll
        for (int j = 0; j < 16; ++j)
#pragma unroll
            for (int e = 0; e < 4; ++e) sacc[j][e] = 0.f;

#pragma unroll
        for (int ks = 0; ks < 4; ++ks) {
#pragma unroll
            for (int j = 0; j < 16; ++j) {
                uint32_t bf[2];
                bf[0] = *(const uint32_t*)(sK + (j * 8 + g) * FK_PITCH + ks * 16 + 2 * t);
                bf[1] = *(const uint32_t*)(sK + (j * 8 + g) * FK_PITCH + ks * 16 + 8 + 2 * t);
                mma_f16(sacc[j], qf[ks], bf);
            }
        }

        // bias add (fp16 half2 loads; row elem 197 is zero-padded) + mask
#pragma unroll
        for (int j = 0; j < 16; ++j) {
            const int kc = kb + j * 8 + 2 * t;
            if (kc < S) {
                const float2 b0 = __half22float2(*(const __half2*)(brow0 + kc));
                const float2 b1 = __half22float2(*(const __half2*)(brow1 + kc));
                sacc[j][0] += b0.x;
                sacc[j][1] = (kc + 1 < S) ? sacc[j][1] + b0.y : -1e30f;
                sacc[j][2] += b1.x;
                sacc[j][3] = (kc + 1 < S) ? sacc[j][3] + b1.y : -1e30f;
            } else {
                sacc[j][0] = -1e30f; sacc[j][1] = -1e30f;
                sacc[j][2] = -1e30f; sacc[j][3] = -1e30f;
            }
        }

        float mx0 = -1e30f, mx1 = -1e30f;
#pragma unroll
        for (int j = 0; j < 16; ++j) {
            mx0 = fmaxf(mx0, fmaxf(sacc[j][0], sacc[j][1]));
            mx1 = fmaxf(mx1, fmaxf(sacc[j][2], sacc[j][3]));
        }
        mx0 = fmaxf(mx0, __shfl_xor_sync(0xffffffffu, mx0, 1));
        mx0 = fmaxf(mx0, __shfl_xor_sync(0xffffffffu, mx0, 2));
        mx1 = fmaxf(mx1, __shfl_xor_sync(0xffffffffu, mx1, 1));
        mx1 = fmaxf(mx1, __shfl_xor_sync(0xffffffffu, mx1, 2));

        const float nm0 = fmaxf(m0r, mx0);
        const float nm1 = fmaxf(m1r, mx1);
        const float sc0 = __expf(m0r - nm0);
        const float sc1 = __expf(m1r - nm1);
        m0r = nm0; m1r = nm1;

        const float c0 = -nm0 * LOG2E;
        const float c1 = -nm1 * LOG2E;
        __half* sP = smh + FP_BASE;
#pragma unroll
        for (int j = 0; j < 16; ++j) {
            const int col = j * 8 + 2 * t;
            __half2 a0 = __floats2half2_rn(fmaf(sacc[j][0], LOG2E, c0),
                                           fmaf(sacc[j][1], LOG2E, c0));
            __half2 a1 = __floats2half2_rn(fmaf(sacc[j][2], LOG2E, c1),
                                           fmaf(sacc[j][3], LOG2E, c1));
            *(uint32_t*)(sP + (wrow + g) * FP_PITCH + col)     = ex2_f16x2(a0);
            *(uint32_t*)(sP + (wrow + g + 8) * FP_PITCH + col) = ex2_f16x2(a1);
        }

#pragma unroll
        for (int j = 0; j < 9; ++j) {
            o[j][0] *= sc0; o[j][1] *= sc0;
            o[j][2] *= sc1; o[j][3] *= sc1;
        }
        __syncwarp();

#pragma unroll
        for (int ks = 0; ks < 8; ++ks) {
            uint32_t af[4];
            af[0] = *(const uint32_t*)(sP + (wrow + g) * FP_PITCH + ks * 16 + 2 * t);
            af[1] = *(const uint32_t*)(sP + (wrow + g + 8) * FP_PITCH + ks * 16 + 2 * t);
            af[2] = *(const uint32_t*)(sP + (wrow + g) * FP_PITCH + ks * 16 + 8 + 2 * t);
            af[3] = *(const uint32_t*)(sP + (wrow + g + 8) * FP_PITCH + ks * 16 + 8 + 2 * t);
#pragma unroll
            for (int j = 0; j < 9; ++j) {
                uint32_t bf[2];
                bf[0] = *(const uint32_t*)(sV + (j * 8 + g) * FP_PITCH + ks * 16 + 2 * t);
                bf[1] = *(const uint32_t*)(sV + (j * 8 + g) * FP_PITCH + ks * 16 + 8 + 2 * t);
                mma_f16(o[j], af, bf);
            }
        }
        __syncwarp();
    }

    const float l0 = __shfl_sync(0xffffffffu, o[8][0], lane & ~3);
    const float l1 = __shfl_sync(0xffffffffu, o[8][2], lane & ~3);
    const float inv0 = 1.f / l0;
    const float inv1 = 1.f / l1;
#pragma unroll
    for (int j = 0; j < 8; ++j) {
        const int col = h * HD + j * 8 + 2 * t;
        if (qr0 < S) {
            float2 v; v.x = o[j][0] * inv0; v.y = o[j][1] * inv0;
            *(float2*)(out + ((size_t)b * S + qr0) * D + col) = v;
        }
        if (qr1 < S) {
            float2 v; v.x = o[j][2] * inv1; v.y = o[j][3] * inv1;
            *(float2*)(out + ((size_t)b * S + qr1) * D + col) = v;
        }
    }
}

// ============================================================================
// Launch: batch-split pipeline.
//   stream0: cvt_xA | wait prep | qkvA | rec evA | wait evXB | qkvB | flashB | wait evF
//   s1:      wait fork | cvt_w, vt_pad, bias_expand | rec evP | cvt_xB | rec evXB
//            | wait evA | flashA | rec evF
// ============================================================================
extern "C" void kernel_launch(void* const* d_in, const int* in_sizes, int n_in,
                              void* d_out, int out_size)
{
    const float* X  = (const float*)d_in[0];
    const float* wq = (const float*)d_in[1];
    const float* bq = (const float*)d_in[2];
    const float* wk = (const float*)d_in[3];
    const float* wv = (const float*)d_in[4];
    const float* bv = (const float*)d_in[5];
    const float* bt = (const float*)d_in[6];
    const int*   ri = (const int*)d_in[7];
    float* out = (float*)d_out;

    (void)in_sizes; (void)n_in; (void)out_size;

    static __half* xh_ptr = nullptr;
    static __half* wh_ptr = nullptr;
    static cudaStream_t s1 = nullptr;
    static cudaEvent_t ev_fork, ev_prep, ev_xb, ev_a, ev_f;
    if (!xh_ptr) {
        cudaGetSymbolAddress((void**)&xh_ptr, g_xh);
        cudaGetSymbolAddress((void**)&wh_ptr, g_wh);
        cudaFuncSetAttribute(qkv_mma_kernel, cudaFuncAttributeMaxDynamicSharedMemorySize, SMEM_QKV_BYTES);
        cudaFuncSetAttribute(flash_kernel, cudaFuncAttributeMaxDynamicSharedMemorySize, SMEM_FLASH_BYTES);
        cudaStreamCreateWithFlags(&s1, cudaStreamNonBlocking);
        cudaEventCreateWithFlags(&ev_fork, cudaEventDisableTiming);
        cudaEventCreateWithFlags(&ev_prep, cudaEventDisableTiming);
        cudaEventCreateWithFlags(&ev_xb,   cudaEventDisableTiming);
        cudaEventCreateWithFlags(&ev_a,    cudaEventDisableTiming);
        cudaEventCreateWithFlags(&ev_f,    cudaEventDisableTiming);
    }

    const int nx8a = ROWS_A * D / 8;                    // rows 0..6399
    const int nx8b = (M_TOT - ROWS_A) * D / 8;
    const int nw8  = 3 * D * D / 8;

    cudaEventRecord(ev_fork, 0);
    cudaStreamWaitEvent(s1, ev_fork, 0);

    // stream0: X part A (needed by qkvA)
    cvt_x_kernel<<<(nx8a + 255) / 256, 256>>>(X, xh_ptr, nx8a);

    // s1: weights + pads + bias, then X part B (concurrent with qkvA)
    cvt_w_kernel<<<(nw8 + 255) / 256, 256, 0, s1>>>(wq, wk, wv, wh_ptr);
    vt_pad_kernel<<<(B * H * HD * 16 + 255) / 256, 256, 0, s1>>>();
    bias_expand_kernel<<<(S * S + 255) / 256, 256, 0, s1>>>(bt, ri);
    cudaEventRecord(ev_prep, s1);
    cvt_x_kernel<<<(nx8b + 255) / 256, 256, 0, s1>>>(
        X + (size_t)ROWS_A * D, xh_ptr + (size_t)ROWS_A * D, nx8b);
    cudaEventRecord(ev_xb, s1);

    // qkvA after prep (weights, vt_pad)
    cudaStreamWaitEvent(0, ev_prep, 0);
    qkv_mma_kernel<<<dim3(MBLK_A, 9), 512, SMEM_QKV_BYTES>>>(bq, bv, 0);
    cudaEventRecord(ev_a, 0);

    // qkvB needs X part B
    cudaStreamWaitEvent(0, ev_xb, 0);
    qkv_mma_kernel<<<dim3(MBLK_B, 9), 512, SMEM_QKV_BYTES>>>(bq, bv, MBLK_A);

    // flashA (batches 0..31) on s1, concurrent with qkvB
    cudaStreamWaitEvent(s1, ev_a, 0);
    flash_kernel<<<dim3(2, 32 * H), 256, SMEM_FLASH_BYTES, s1>>>(out, 0);
    cudaEventRecord(ev_f, s1);

    // flashB (batches 32..63) on stream0 after qkvB
    flash_kernel<<<dim3(2, 32 * H), 256, SMEM_FLASH_BYTES>>>(out, 32 * H);

    cudaStreamWaitEvent(0, ev_f, 0);
}

// round 11
// speedup vs baseline: 7.1297x; 1.0191x over previous
#include <cuda_runtime.h>
#include <cuda_fp16.h>
#include <math.h>
#include <cstdint>

#define B 64
#define S 197
#define D 768
#define H 12
#define HD 64
#define M_TOT (B * S)          // 12608
#define NUM_REL 732
#define VT_PITCH 256
#define BP 198                 // bias pitch (even -> aligned half2)
#define LOG2E 1.44269504f

#define MBLK_A 50
#define MBLK_B 49
#define ROWS_A 6400

// -------- device scratch --------
__device__ __half g_xh[(size_t)M_TOT * D];
__device__ __half g_wh[(size_t)3 * D * D];
__device__ __half g_qh[(size_t)B * H * S * HD];
__device__ __half g_kh[(size_t)B * H * S * HD];
__device__ __half g_vt[(size_t)B * H * HD * VT_PITCH];
__device__ __half g_bias[(size_t)H * S * BP];

__device__ __forceinline__ void mma_f16(float* d, const uint32_t* a, const uint32_t* b) {
    asm volatile(
        "mma.sync.aligned.m16n8k16.row.col.f32.f16.f16.f32 "
        "{%0,%1,%2,%3}, {%4,%5,%6,%7}, {%8,%9}, {%0,%1,%2,%3};"
        : "+f"(d[0]), "+f"(d[1]), "+f"(d[2]), "+f"(d[3])
        : "r"(a[0]), "r"(a[1]), "r"(a[2]), "r"(a[3]), "r"(b[0]), "r"(b[1]));
}

__device__ __forceinline__ void ldsm_x4(uint32_t& r0, uint32_t& r1, uint32_t& r2, uint32_t& r3,
                                        uint32_t addr) {
    asm volatile("ldmatrix.sync.aligned.m8n8.x4.shared.b16 {%0,%1,%2,%3}, [%4];"
                 : "=r"(r0), "=r"(r1), "=r"(r2), "=r"(r3) : "r"(addr));
}
__device__ __forceinline__ void ldsm_x2(uint32_t& r0, uint32_t& r1, uint32_t addr) {
    asm volatile("ldmatrix.sync.aligned.m8n8.x2.shared.b16 {%0,%1}, [%2];"
                 : "=r"(r0), "=r"(r1) : "r"(addr));
}

__device__ __forceinline__ uint32_t smem_u32(const void* p) {
    uint32_t a;
    asm("{ .reg .u64 t; cvta.to.shared.u64 t, %1; cvt.u32.u64 %0, t; }" : "=r"(a) : "l"(p));
    return a;
}

__device__ __forceinline__ void cp16(uint32_t dst, const void* src, bool pred) {
    const int sz = pred ? 16 : 0;
    asm volatile("cp.async.cg.shared.global [%0], [%1], 16, %2;"
                 :: "r"(dst), "l"(src), "r"(sz) : "memory");
}
#define CP_COMMIT() asm volatile("cp.async.commit_group;" ::: "memory")
#define CP_WAIT1()  asm volatile("cp.async.wait_group 1;" ::: "memory")
#define CP_WAIT0()  asm volatile("cp.async.wait_group 0;" ::: "memory")

__device__ __forceinline__ uint32_t ex2_f16x2(__half2 x) {
    uint32_t r;
    asm("ex2.approx.f16x2 %0, %1;" : "=r"(r) : "r"(*(uint32_t*)&x));
    return r;
}

// ============================================================================
// Kernel 0a: fp32 -> fp16 convert.
// ============================================================================
__global__ __launch_bounds__(256) void cvt_x_kernel(
    const float* __restrict__ src, __half* __restrict__ dst, int n8)
{
    const int i = blockIdx.x * 256 + threadIdx.x;
    if (i >= n8) return;
    const float4 a = ((const float4*)src)[2 * i];
    const float4 b = ((const float4*)src)[2 * i + 1];
    __half2 h0 = __floats2half2_rn(a.x, a.y);
    __half2 h1 = __floats2half2_rn(a.z, a.w);
    __half2 h2 = __floats2half2_rn(b.x, b.y);
    __half2 h3 = __floats2half2_rn(b.z, b.w);
    uint4 u;
    u.x = *(uint32_t*)&h0; u.y = *(uint32_t*)&h1;
    u.z = *(uint32_t*)&h2; u.w = *(uint32_t*)&h3;
    ((uint4*)dst)[i] = u;
}

// ============================================================================
// Kernel 0b: fused weight convert.
// ============================================================================
__global__ __launch_bounds__(256) void cvt_w_kernel(
    const float* __restrict__ wq, const float* __restrict__ wk,
    const float* __restrict__ wv, __half* __restrict__ dst)
{
    const int nw8 = D * D / 8;
    const int i = blockIdx.x * 256 + threadIdx.x;
    if (i >= 3 * nw8) return;
    const float* src;
    int j;
    if (i < nw8)          { src = wq; j = i; }
    else if (i < 2 * nw8) { src = wk; j = i - nw8; }
    else                  { src = wv; j = i - 2 * nw8; }
    const float4 a = ((const float4*)src)[2 * j];
    const float4 b = ((const float4*)src)[2 * j + 1];
    __half2 h0 = __floats2half2_rn(a.x, a.y);
    __half2 h1 = __floats2half2_rn(a.z, a.w);
    __half2 h2 = __floats2half2_rn(b.x, b.y);
    __half2 h3 = __floats2half2_rn(b.z, b.w);
    uint4 u;
    u.x = *(uint32_t*)&h0; u.y = *(uint32_t*)&h1;
    u.z = *(uint32_t*)&h2; u.w = *(uint32_t*)&h3;
    ((uint4*)dst)[i] = u;
}

// ============================================================================
// Kernel 0c: zero g_vt tail.
// ============================================================================
__global__ __launch_bounds__(256) void vt_pad_kernel()
{
    const int i = blockIdx.x * 256 + threadIdx.x;
    if (i >= B * H * HD * 16) return;
    const int row = i >> 4, j = i & 15;
    ((uint2*)(g_vt + (size_t)row * VT_PITCH + 192))[j] = make_uint2(0u, 0u);
}

// ============================================================================
// Kernel 1: QKV projection (unchanged, proven).
// ============================================================================
#define HPITCH 72
#define A_HALVES (128 * HPITCH)
#define B_HALVES (256 * HPITCH)
#define STAGE_HALVES (A_HALVES + B_HALVES)
#define STAGE_BYTES (STAGE_HALVES * 2)
#define SMEM_QKV_BYTES (3 * STAGE_BYTES)        // 165888
#define NCHUNK 12

__global__ __launch_bounds__(512, 1) void qkv_mma_kernel(
    const float* __restrict__ bq, const float* __restrict__ bv, int mblk0)
{
    extern __shared__ __half smh[];
    const uint32_t sbase = smem_u32(smh);

    const int tid  = threadIdx.x;
    const int lane = tid & 31;
    const int wid  = tid >> 5;
    const int g    = lane >> 2;
    const int t    = lane & 3;
    const int wm   = wid & 1;
    const int wn   = wid >> 1;

    const int m0  = (mblk0 + blockIdx.x) * 128;
    const int n0g = blockIdx.y * 256;
    const int proj = n0g / 768;
    const int n0   = n0g - proj * 768;

    const float* bias = (proj == 0) ? bq : ((proj == 2) ? bv : nullptr);

    const int lrow = tid >> 3;
    const int lcg  = tid & 7;

    auto issue = [&](int c, int s) {
        const int k0 = c * 64;
        const uint32_t smA = sbase + s * STAGE_BYTES;
        const uint32_t smB = smA + A_HALVES * 2;
#pragma unroll
        for (int i = 0; i < 2; ++i) {
            const int row = lrow + i * 64;
            const int m = m0 + row;
            const bool pa = m < M_TOT;
            const __half* srcA = g_xh + (size_t)(pa ? m : 0) * 768 + k0 + lcg * 8;
            cp16(smA + (row * HPITCH + lcg * 8) * 2, srcA, pa);
        }
#pragma unroll
        for (int i = 0; i < 4; ++i) {
            const int row = lrow + i * 64;
            const __half* srcB = g_wh + (size_t)(n0g + row) * 768 + k0 + lcg * 8;
            cp16(smB + (row * HPITCH + lcg * 8) * 2, srcB, true);
        }
        CP_COMMIT();
    };

    issue(0, 0);
    issue(1, 1);

    const int a_row_l = (lane & 7) + ((lane >> 3) & 1) * 8;
    const int a_col_l = ((lane >> 4) & 1) * 8;
    const int b_row_l = (lane & 7) + ((lane >> 4) & 1) * 8;
    const int b_col_l = ((lane >> 3) & 1) * 8;

    float acc[4][4][4];
#pragma unroll
    for (int mt = 0; mt < 4; ++mt)
#pragma unroll
        for (int nt = 0; nt < 4; ++nt)
#pragma unroll
            for (int e = 0; e < 4; ++e) acc[mt][nt][e] = 0.f;

    for (int c = 0; c < NCHUNK; ++c) {
        CP_WAIT1();
        __syncthreads();
        if (c + 2 < NCHUNK) issue(c + 2, (c + 2) % 3);

        const uint32_t stA = sbase + (c % 3) * STAGE_BYTES;
        const uint32_t stB = stA + A_HALVES * 2;
#pragma unroll
        for (int ks = 0; ks < 4; ++ks) {
            uint32_t af[4][4], bf[4][2];
#pragma unroll
            for (int mt = 0; mt < 4; ++mt) {
                const uint32_t addr = stA +
                    ((wm * 64 + mt * 16 + a_row_l) * HPITCH + ks * 16 + a_col_l) * 2;
                ldsm_x4(af[mt][0], af[mt][1], af[mt][2], af[mt][3], addr);
            }
#pragma unroll
            for (int ntp = 0; ntp < 2; ++ntp) {
                const uint32_t addr = stB +
                    ((wn * 32 + ntp * 16 + b_row_l) * HPITCH + ks * 16 + b_col_l) * 2;
                ldsm_x4(bf[2 * ntp][0], bf[2 * ntp][1],
                        bf[2 * ntp + 1][0], bf[2 * ntp + 1][1], addr);
            }
#pragma unroll
            for (int mt = 0; mt < 4; ++mt)
#pragma unroll
                for (int nt = 0; nt < 4; ++nt)
                    mma_f16(acc[mt][nt], af[mt], bf[nt]);
        }
    }

    const float scale = (proj == 0) ? 0.125f : 1.0f;
#pragma unroll
    for (int mt = 0; mt < 4; ++mt) {
        const int r0 = m0 + wm * 64 + mt * 16 + g;
#pragma unroll
        for (int nt = 0; nt < 4; ++nt) {
            const int n = n0 + wn * 32 + nt * 8 + t * 2;
            const int hh = n >> 6;
            const int hd = n & 63;
            float bx = 0.f, by = 0.f;
            if (bias) { bx = bias[n]; by = bias[n + 1]; }
#pragma unroll
            for (int half_i = 0; half_i < 2; ++half_i) {
                const int m = r0 + half_i * 8;
                if (m >= M_TOT) continue;
                const int bb = m / S;
                const int ss = m - bb * S;
                const int bh = bb * H + hh;
                const float vx = (acc[mt][nt][half_i * 2 + 0] + bx) * scale;
                const float vy = (acc[mt][nt][half_i * 2 + 1] + by) * scale;
                if (proj == 2) {
                    g_vt[((size_t)bh * HD + hd) * VT_PITCH + ss]     = __float2half_rn(vx);
                    g_vt[((size_t)bh * HD + hd + 1) * VT_PITCH + ss] = __float2half_rn(vy);
                } else {
                    __half2 hv = __floats2half2_rn(vx, vy);
                    __half* dst = (proj == 0) ? g_qh : g_kh;
                    *(__half2*)(dst + ((size_t)bh * S + ss) * HD + hd) = hv;
                }
            }
        }
    }
}

// ============================================================================
// Kernel 2: bias expand (fp16, pitch 198).
// ============================================================================
__global__ __launch_bounds__(256) void bias_expand_kernel(
    const float* __restrict__ bias_table, const int* __restrict__ rel_index)
{
    const int i = blockIdx.x * 256 + threadIdx.x;
    if (i >= S * S) return;
    const int q = i / S, k = i - q * S;
    const int r = rel_index[i];
#pragma unroll
    for (int h = 0; h < H; ++h)
        g_bias[((size_t)h * S + q) * BP + k] = __float2half_rn(bias_table[r * H + h]);
}

// ============================================================================
// Kernel 3: flash attention — ALL fragment loads via ldmatrix.
// ============================================================================
#define FK_PITCH 72
#define FP_PITCH 136
#define K_HALVES (128 * FK_PITCH)
#define V_HALVES (72 * FP_PITCH)
#define FV_BASE (2 * K_HALVES)
#define FP_BASE (2 * K_HALVES + 2 * V_HALVES)
#define SMEM_FLASH_BYTES ((FP_BASE + 128 * FP_PITCH) * 2)   // 110848

__global__ __launch_bounds__(256, 2) void flash_kernel(float* __restrict__ out, int bh0)
{
    extern __shared__ __half smh[];
    const uint32_t sbase = smem_u32(smh);

    const int tid  = threadIdx.x;
    const int lane = tid & 31;
    const int wid  = tid >> 5;
    const int g    = lane >> 2;
    const int t    = lane & 3;

    const int qt = blockIdx.x;
    const int bh = bh0 + blockIdx.y;
    const int b  = bh / H;
    const int h  = bh - b * H;
    const int qbase = qt * 128;
    const int wrow  = wid * 16;

    // ldmatrix lane decode (same as qkv, proven)
    const int a_row_l = (lane & 7) + ((lane >> 3) & 1) * 8;
    const int a_col_l = ((lane >> 4) & 1) * 8;
    const int b_row_l = (lane & 7) + ((lane >> 4) & 1) * 8;
    const int b_col_l = ((lane >> 3) & 1) * 8;

    const __half* Qg = g_qh + (size_t)bh * S * HD;
    const __half* Kg = g_kh + (size_t)bh * S * HD;
    const __half* Vt = g_vt + (size_t)bh * HD * VT_PITCH;

#pragma unroll
    for (int kt = 0; kt < 2; ++kt) {
        const int kb = kt * 128;
        const uint32_t smK = sbase + kt * K_HALVES * 2;
        const uint32_t smV = sbase + (FV_BASE + kt * V_HALVES) * 2;
#pragma unroll
        for (int it = 0; it < 4; ++it) {
            const int f = tid + it * 256;
            const int row = f >> 3, cg = f & 7;
            const int kk = kb + row;
            const bool p = kk < S;
            cp16(smK + (row * FK_PITCH + cg * 8) * 2,
                 Kg + (size_t)(p ? kk : 0) * HD + cg * 8, p);
        }
#pragma unroll
        for (int it = 0; it < 4; ++it) {
            const int f = tid + it * 256;
            const int row = f >> 4, cg = f & 15;
            cp16(smV + (row * FP_PITCH + cg * 8) * 2,
                 Vt + (size_t)row * VT_PITCH + kb + cg * 8, true);
        }
        CP_COMMIT();
    }

    // static sV rows 64-71 (ones / zeros), both buffers
    {
        const __half one  = __float2half(1.f);
        const __half zero = __float2half(0.f);
        for (int i = tid; i < 2 * 8 * FP_PITCH; i += 256) {
            const int buf = i / (8 * FP_PITCH);
            const int rem = i - buf * 8 * FP_PITCH;
            const int r   = rem / FP_PITCH;
            const int cc  = rem - r * FP_PITCH;
            smh[FV_BASE + buf * V_HALVES + (64 + r) * FP_PITCH + cc] = (r == 0) ? one : zero;
        }
    }

    // stage Q into P region
    {
        __half* sQ = smh + FP_BASE;
#pragma unroll
        for (int it = 0; it < 4; ++it) {
            const int f = tid + it * 256;
            const int row = f >> 3, cg = f & 7;
            const int m = qbase + row;
            uint4 u = make_uint4(0u, 0u, 0u, 0u);
            if (m < S) u = *(const uint4*)(Qg + (size_t)m * HD + cg * 8);
            *(uint4*)(sQ + row * FK_PITCH + cg * 8) = u;
        }
    }
    __syncthreads();

    // Q fragments via ldmatrix (A-operand layout), pitch 144B -> conflict-free
    uint32_t qf[4][4];
    {
        const uint32_t sQ = sbase + FP_BASE * 2;
#pragma unroll
        for (int ks = 0; ks < 4; ++ks) {
            const uint32_t addr = sQ + ((wrow + a_row_l) * FK_PITCH + ks * 16 + a_col_l) * 2;
            ldsm_x4(qf[ks][0], qf[ks][1], qf[ks][2], qf[ks][3], addr);
        }
    }
    __syncthreads();

    const int qr0 = qbase + wrow + g;
    const int qr1 = qr0 + 8;
    const __half* brow0 = g_bias + ((size_t)h * S + min(qr0, S - 1)) * BP;
    const __half* brow1 = g_bias + ((size_t)h * S + min(qr1, S - 1)) * BP;

    float m0r = -1e30f, m1r = -1e30f;
    float o[9][4];
#pragma unroll
    for (int j = 0; j < 9; ++j)
#pragma unroll
        for (int e = 0; e < 4; ++e) o[j][e] = 0.f;

#pragma unroll
    for (int kt = 0; kt < 2; ++kt) {
        const int kb = kt * 128;
        if (kt == 0) { CP_WAIT1(); } else { CP_WAIT0(); }
        __syncthreads();

        const uint32_t sK = sbase + kt * K_HALVES * 2;
        const uint32_t sV = sbase + (FV_BASE + kt * V_HALVES) * 2;

        float sacc[16][4];
#pragma unroll
        for (int j = 0; j < 16; ++j)
#pragma unroll
            for (int e = 0; e < 4; ++e) sacc[j][e] = 0.f;

        // ---- S = Q K^T, K-fragments via ldmatrix ----
#pragma unroll
        for (int ks = 0; ks < 4; ++ks) {
            uint32_t bf[16][2];
#pragma unroll
            for (int jp = 0; jp < 8; ++jp) {
                const uint32_t addr = sK +
                    ((jp * 16 + b_row_l) * FK_PITCH + ks * 16 + b_col_l) * 2;
                ldsm_x4(bf[2 * jp][0], bf[2 * jp][1],
                        bf[2 * jp + 1][0], bf[2 * jp + 1][1], addr);
            }
#pragma unroll
            for (int j = 0; j < 16; ++j)
                mma_f16(sacc[j], qf[ks], bf[j]);
        }

        // ---- bias add + mask ----
#pragma unroll
        for (int j = 0; j < 16; ++j) {
            const int kc = kb + j * 8 + 2 * t;
            if (kc < S) {
                const float2 b0 = __half22float2(*(const __half2*)(brow0 + kc));
                const float2 b1 = __half22float2(*(const __half2*)(brow1 + kc));
                sacc[j][0] += b0.x;
                sacc[j][1] = (kc + 1 < S) ? sacc[j][1] + b0.y : -1e30f;
                sacc[j][2] += b1.x;
                sacc[j][3] = (kc + 1 < S) ? sacc[j][3] + b1.y : -1e30f;
            } else {
                sacc[j][0] = -1e30f; sacc[j][1] = -1e30f;
                sacc[j][2] = -1e30f; sacc[j][3] = -1e30f;
            }
        }

        // ---- online max ----
        float mx0 = -1e30f, mx1 = -1e30f;
#pragma unroll
        for (int j = 0; j < 16; ++j) {
            mx0 = fmaxf(mx0, fmaxf(sacc[j][0], sacc[j][1]));
            mx1 = fmaxf(mx1, fmaxf(sacc[j][2], sacc[j][3]));
        }
        mx0 = fmaxf(mx0, __shfl_xor_sync(0xffffffffu, mx0, 1));
        mx0 = fmaxf(mx0, __shfl_xor_sync(0xffffffffu, mx0, 2));
        mx1 = fmaxf(mx1, __shfl_xor_sync(0xffffffffu, mx1, 1));
        mx1 = fmaxf(mx1, __shfl_xor_sync(0xffffffffu, mx1, 2));

        const float nm0 = fmaxf(m0r, mx0);
        const float nm1 = fmaxf(m1r, mx1);
        const float sc0 = __expf(m0r - nm0);
        const float sc1 = __expf(m1r - nm1);
        m0r = nm0; m1r = nm1;

        // ---- P = ex2.f16x2, stored to sP ----
        const float c0 = -nm0 * LOG2E;
        const float c1 = -nm1 * LOG2E;
        __half* sPp = smh + FP_BASE;
#pragma unroll
        for (int j = 0; j < 16; ++j) {
            const int col = j * 8 + 2 * t;
            __half2 a0 = __floats2half2_rn(fmaf(sacc[j][0], LOG2E, c0),
                                           fmaf(sacc[j][1], LOG2E, c0));
            __half2 a1 = __floats2half2_rn(fmaf(sacc[j][2], LOG2E, c1),
                                           fmaf(sacc[j][3], LOG2E, c1));
            *(uint32_t*)(sPp + (wrow + g) * FP_PITCH + col)     = ex2_f16x2(a0);
            *(uint32_t*)(sPp + (wrow + g + 8) * FP_PITCH + col) = ex2_f16x2(a1);
        }

#pragma unroll
        for (int j = 0; j < 9; ++j) {
            o[j][0] *= sc0; o[j][1] *= sc0;
            o[j][2] *= sc1; o[j][3] *= sc1;
        }
        __syncwarp();

        // ---- O += P V, all fragments via ldmatrix ----
        const uint32_t sP = sbase + FP_BASE * 2;
#pragma unroll
        for (int ks = 0; ks < 8; ++ks) {
            uint32_t af[4];
            {
                const uint32_t addr = sP +
                    ((wrow + a_row_l) * FP_PITCH + ks * 16 + a_col_l) * 2;
                ldsm_x4(af[0], af[1], af[2], af[3], addr);
            }
            uint32_t bf[9][2];
#pragma unroll
            for (int jp = 0; jp < 4; ++jp) {
                const uint32_t addr = sV +
                    ((jp * 16 + b_row_l) * FP_PITCH + ks * 16 + b_col_l) * 2;
                ldsm_x4(bf[2 * jp][0], bf[2 * jp][1],
                        bf[2 * jp + 1][0], bf[2 * jp + 1][1], addr);
            }
            {   // ones-column tile (rows 64-71): x2 uses lanes 0-15 addresses
                const uint32_t addr = sV +
                    ((64 + (b_row_l & 7)) * FP_PITCH + ks * 16 + b_col_l) * 2;
                ldsm_x2(bf[8][0], bf[8][1], addr);
            }
#pragma unroll
            for (int j = 0; j < 9; ++j)
                mma_f16(o[j], af, bf[j]);
        }
        __syncwarp();
    }

    const float l0 = __shfl_sync(0xffffffffu, o[8][0], lane & ~3);
    const float l1 = __shfl_sync(0xffffffffu, o[8][2], lane & ~3);
    const float inv0 = 1.f / l0;
    const float inv1 = 1.f / l1;
#pragma unroll
    for (int j = 0; j < 8; ++j) {
        const int col = h * HD + j * 8 + 2 * t;
        if (qr0 < S) {
            float2 v; v.x = o[j][0] * inv0; v.y = o[j][1] * inv0;
            *(float2*)(out + ((size_t)b * S + qr0) * D + col) = v;
        }
        if (qr1 < S) {
            float2 v; v.x = o[j][2] * inv1; v.y = o[j][3] * inv1;
            *(float2*)(out + ((size_t)b * S + qr1) * D + col) = v;
        }
    }
}

// ============================================================================
// Launch: batch-split pipeline (unchanged from R10).
// ============================================================================
extern "C" void kernel_launch(void* const* d_in, const int* in_sizes, int n_in,
                              void* d_out, int out_size)
{
    const float* X  = (const float*)d_in[0];
    const float* wq = (const float*)d_in[1];
    const float* bq = (const float*)d_in[2];
    const float* wk = (const float*)d_in[3];
    const float* wv = (const float*)d_in[4];
    const float* bv = (const float*)d_in[5];
    const float* bt = (const float*)d_in[6];
    const int*   ri = (const int*)d_in[7];
    float* out = (float*)d_out;

    (void)in_sizes; (void)n_in; (void)out_size;

    static __half* xh_ptr = nullptr;
    static __half* wh_ptr = nullptr;
    static cudaStream_t s1 = nullptr;
    static cudaEvent_t ev_fork, ev_prep, ev_xb, ev_a, ev_f;
    if (!xh_ptr) {
        cudaGetSymbolAddress((void**)&xh_ptr, g_xh);
        cudaGetSymbolAddress((void**)&wh_ptr, g_wh);
        cudaFuncSetAttribute(qkv_mma_kernel, cudaFuncAttributeMaxDynamicSharedMemorySize, SMEM_QKV_BYTES);
        cudaFuncSetAttribute(flash_kernel, cudaFuncAttributeMaxDynamicSharedMemorySize, SMEM_FLASH_BYTES);
        cudaStreamCreateWithFlags(&s1, cudaStreamNonBlocking);
        cudaEventCreateWithFlags(&ev_fork, cudaEventDisableTiming);
        cudaEventCreateWithFlags(&ev_prep, cudaEventDisableTiming);
        cudaEventCreateWithFlags(&ev_xb,   cudaEventDisableTiming);
        cudaEventCreateWithFlags(&ev_a,    cudaEventDisableTiming);
        cudaEventCreateWithFlags(&ev_f,    cudaEventDisableTiming);
    }

    const int nx8a = ROWS_A * D / 8;
    const int nx8b = (M_TOT - ROWS_A) * D / 8;
    const int nw8  = 3 * D * D / 8;

    cudaEventRecord(ev_fork, 0);
    cudaStreamWaitEvent(s1, ev_fork, 0);

    cvt_x_kernel<<<(nx8a + 255) / 256, 256>>>(X, xh_ptr, nx8a);

    cvt_w_kernel<<<(nw8 + 255) / 256, 256, 0, s1>>>(wq, wk, wv, wh_ptr);
    vt_pad_kernel<<<(B * H * HD * 16 + 255) / 256, 256, 0, s1>>>();
    bias_expand_kernel<<<(S * S + 255) / 256, 256, 0, s1>>>(bt, ri);
    cudaEventRecord(ev_prep, s1);
    cvt_x_kernel<<<(nx8b + 255) / 256, 256, 0, s1>>>(
        X + (size_t)ROWS_A * D, xh_ptr + (size_t)ROWS_A * D, nx8b);
    cudaEventRecord(ev_xb, s1);

    cudaStreamWaitEvent(0, ev_prep, 0);
    qkv_mma_kernel<<<dim3(MBLK_A, 9), 512, SMEM_QKV_BYTES>>>(bq, bv, 0);
    cudaEventRecord(ev_a, 0);

    cudaStreamWaitEvent(0, ev_xb, 0);
    qkv_mma_kernel<<<dim3(MBLK_B, 9), 512, SMEM_QKV_BYTES>>>(bq, bv, MBLK_A);

    cudaStreamWaitEvent(s1, ev_a, 0);
    flash_kernel<<<dim3(2, 32 * H), 256, SMEM_FLASH_BYTES, s1>>>(out, 0);
    cudaEventRecord(ev_f, s1);

    flash_kernel<<<dim3(2, 32 * H), 256, SMEM_FLASH_BYTES>>>(out, 32 * H);

    cudaStreamWaitEvent(0, ev_f, 0);
}